// round 7
// baseline (speedup 1.0000x reference)
#include <cuda_runtime.h>
#include <math.h>
#include <stdint.h>

#define E_ 172
#define KROW 192          // padded K bytes (6 k32 steps)
#define KSTEP 6
#define NSEG 192          // padded N per weight segment
#define KNB 20
#define HH 2
#define HD_ 86
#define NNODES 100000
#define BMAX 12000
#define BPAD 12032        // 94*128
#define NPADN 100096      // 782*128
#define NSLOT 240000      // 1875*128

// pack row offsets within the packed weight buffer
#define P1_OFF 0      // tqkv: q,kE,vE (+biases)   N=576
#define P2_OFF 576    // node/upd kv: kE,vE        N=384
#define P3_OFF 960    // edge kv: kD,vD            N=384
#define P4_OFF 1344   // q proj                    N=192
#define P5_OFF 1536   // out proj (+bias)          N=192
#define PTOT 1728

// ---------------- scratch ----------------
__device__ int8_t g_A1[(size_t)NSLOT * KROW];
__device__ int8_t g_A2[(size_t)NSLOT * KROW];
__device__ float  g_sA[NSLOT];
__device__ int8_t g_W1[(size_t)PTOT * KROW];
__device__ int8_t g_W2[(size_t)PTOT * KROW];
__device__ float  g_sW[PTOT];
__device__ float  g_Wb[PTOT];

__device__ float g_tqkv[BMAX * 576];
__device__ float g_node_kv[(size_t)NNODES * 384];
__device__ float g_edge_kv[(size_t)NSLOT * 384];
__device__ float g_upd_kv[BMAX * 384];
__device__ float g_qh[BMAX * KROW];
__device__ float g_h1f[BPAD * KROW];
__device__ int8_t g_H1q1[BPAD * KROW];
__device__ int8_t g_H1q2[BPAD * KROW];
__device__ float  g_sh1[BPAD];
__device__ int g_owner[NNODES];

// ---------------- asm helpers ----------------
__device__ __forceinline__ void cpa16(uint32_t dst, const void* src) {
  asm volatile("cp.async.cg.shared.global [%0], [%1], 16;" :: "r"(dst), "l"(src));
}
__device__ __forceinline__ void cpa_commit() { asm volatile("cp.async.commit_group;" ::: "memory"); }
template <int N>
__device__ __forceinline__ void cpa_wait() { asm volatile("cp.async.wait_group %0;" :: "n"(N) : "memory"); }

__device__ __forceinline__ void ldsm4(uint32_t* r, uint32_t addr) {
  asm volatile("ldmatrix.sync.aligned.m8n8.x4.shared.b16 {%0,%1,%2,%3}, [%4];"
               : "=r"(r[0]), "=r"(r[1]), "=r"(r[2]), "=r"(r[3]) : "r"(addr));
}
__device__ __forceinline__ void ldsm2(uint32_t* r, uint32_t addr) {
  asm volatile("ldmatrix.sync.aligned.m8n8.x2.shared.b16 {%0,%1}, [%2];"
               : "=r"(r[0]), "=r"(r[1]) : "r"(addr));
}
__device__ __forceinline__ void imma(int* d, const uint32_t* a, const uint32_t* b) {
  asm volatile(
      "mma.sync.aligned.m16n8k32.row.col.s32.s8.s8.s32 "
      "{%0,%1,%2,%3},{%4,%5,%6,%7},{%8,%9},{%0,%1,%2,%3};"
      : "+r"(d[0]), "+r"(d[1]), "+r"(d[2]), "+r"(d[3])
      : "r"(a[0]), "r"(a[1]), "r"(a[2]), "r"(a[3]), "r"(b[0]), "r"(b[1]));
}

// ---------------- small kernels ----------------
__global__ void init_owner_kernel() {
  int i = blockIdx.x * blockDim.x + threadIdx.x;
  if (i < NNODES) g_owner[i] = -1;
}
__global__ void build_owner_kernel(const int* __restrict__ nodes, int B) {
  int i = blockIdx.x * blockDim.x + threadIdx.x;
  if (i < B) atomicMax(&g_owner[nodes[i]], i);
}

// ---------------- row quantization (warp per row) ----------------
__device__ __forceinline__ void quant_store8(const float* x, float inv,
                                             int8_t* Q1, int8_t* Q2, size_t off) {
  uint32_t p1a = 0, p1b = 0, p2a = 0, p2b = 0;
#pragma unroll
  for (int i = 0; i < 8; i++) {
    float xs = x[i] * inv;
    int q1 = __float2int_rn(xs);
    int q2 = __float2int_rn((xs - (float)q1) * 128.f);
    uint32_t b1 = (uint32_t)(q1 & 255), b2 = (uint32_t)(q2 & 255);
    if (i < 4) { p1a |= b1 << (8 * i); p2a |= b2 << (8 * i); }
    else       { p1b |= b1 << (8 * (i - 4)); p2b |= b2 << (8 * (i - 4)); }
  }
  *(uint2*)(Q1 + off) = make_uint2(p1a, p1b);
  *(uint2*)(Q2 + off) = make_uint2(p2a, p2b);
}

// gmode: 0 src=r ; 1 src=g1[r]
__global__ void quant_rows_kernel(const float* __restrict__ X, int ldx,
                                  const int* __restrict__ g1, int gmode,
                                  int M, int Mpad, int ncols,
                                  int8_t* __restrict__ Q1, int8_t* __restrict__ Q2,
                                  float* __restrict__ sc) {
  int wid = (blockIdx.x * blockDim.x + threadIdx.x) >> 5;
  int lane = threadIdx.x & 31;
  if (wid >= Mpad) return;
  bool valid = wid < M;
  const float* src = X;
  if (valid) {
    int s = wid;
    if (gmode >= 1) s = g1[wid];
    src = X + (size_t)s * ldx;
  }
  int c0 = lane * 8;
  float x[8];
  float amax = 0.f;
#pragma unroll
  for (int i = 0; i < 8; i++) {
    int c = c0 + i;
    float v = (valid && c < ncols) ? src[c] : 0.f;
    x[i] = v;
    amax = fmaxf(amax, fabsf(v));
  }
#pragma unroll
  for (int o = 16; o; o >>= 1) amax = fmaxf(amax, __shfl_xor_sync(~0u, amax, o));
  float inv = amax > 0.f ? 127.f / amax : 0.f;
  if (lane == 0) sc[wid] = amax * (1.f / 127.f);
  if (c0 >= KROW) return;
  quant_store8(x, inv, Q1, Q2, (size_t)wid * KROW + c0);
}

__global__ void timequant_kernel(const float* __restrict__ ts,
                                 const float* __restrict__ tw,
                                 const float* __restrict__ tb, int B, int Mpad) {
  int wid = (blockIdx.x * blockDim.x + threadIdx.x) >> 5;
  int lane = threadIdx.x & 31;
  if (wid >= Mpad) return;
  bool valid = wid < B;
  float tval = valid ? ts[wid] : 0.f;
  int c0 = lane * 8;
  float x[8];
  float amax = 0.f;
#pragma unroll
  for (int i = 0; i < 8; i++) {
    int c = c0 + i;
    float v = 0.f;
    if (valid && c < E_) {
      float arg = __fadd_rn(__fmul_rn(tval, tw[c]), tb[c]);
      v = (float)cos((double)arg);
    }
    x[i] = v;
    amax = fmaxf(amax, fabsf(v));
  }
#pragma unroll
  for (int o = 16; o; o >>= 1) amax = fmaxf(amax, __shfl_xor_sync(~0u, amax, o));
  float inv = amax > 0.f ? 127.f / amax : 0.f;
  if (lane == 0) g_sA[wid] = amax * (1.f / 127.f);
  if (c0 >= KROW) return;
  quant_store8(x, inv, g_A1, g_A2, (size_t)wid * KROW + c0);
}

// ---------------- weight quantization ----------------
struct PArgs {
  const float* w[3];
  int ld[3];
  int coff[3];
  const float* bias[3];
};
__global__ void quant_w_kernel(PArgs a, int nseg, int8_t* Q1, int8_t* Q2,
                               float* sc, float* pbias) {
  int wid = (blockIdx.x * blockDim.x + threadIdx.x) >> 5;
  int lane = threadIdx.x & 31;
  if (wid >= nseg * NSEG) return;
  int seg = wid / NSEG, nr = wid - seg * NSEG;
  bool valid = nr < E_;
  const float* src = valid ? a.w[seg] + (size_t)nr * a.ld[seg] + a.coff[seg] : nullptr;
  int c0 = lane * 8;
  float x[8];
  float amax = 0.f;
#pragma unroll
  for (int i = 0; i < 8; i++) {
    int c = c0 + i;
    float v = (valid && c < E_) ? src[c] : 0.f;
    x[i] = v;
    amax = fmaxf(amax, fabsf(v));
  }
#pragma unroll
  for (int o = 16; o; o >>= 1) amax = fmaxf(amax, __shfl_xor_sync(~0u, amax, o));
  float inv = amax > 0.f ? 127.f / amax : 0.f;
  if (lane == 0) {
    sc[wid] = amax * (1.f / 127.f);
    pbias[wid] = (valid && a.bias[seg]) ? a.bias[seg][nr] : 0.f;
  }
  if (c0 >= KROW) return;
  quant_store8(x, inv, Q1, Q2, (size_t)wid * KROW + c0);
}

// gather quantized h1 rows into A buffers for layer-1 q
__global__ void gather_h1_kernel(const int* __restrict__ nodes, int B, int Mpad) {
  int i = blockIdx.x * blockDim.x + threadIdx.x;
  if (i >= Mpad * (KROW / 4)) return;
  int r = i / (KROW / 4), w = i - r * (KROW / 4);
  int v1 = 0, v2 = 0;
  if (r < B) {
    int src = g_owner[nodes[r]];
    v1 = *(const int*)(g_H1q1 + (size_t)src * KROW + w * 4);
    v2 = *(const int*)(g_H1q2 + (size_t)src * KROW + w * 4);
    if (w == 0) g_sA[r] = g_sh1[src];
  } else if (w == 0) {
    g_sA[r] = 0.f;
  }
  *(int*)(g_A1 + (size_t)r * KROW + w * 4) = v1;
  *(int*)(g_A2 + (size_t)r * KROW + w * 4) = v2;
}

// ---------------- int8 two-limb GEMM ----------------
#define BM 128
#define BN 48
#define APITCH 48
#define STAGE_A (BM * APITCH)   // 6144
#define STAGE_B (BN * APITCH)   // 2304
#define SM_A1 0
#define SM_A2 (SM_A1 + 4 * STAGE_A)
#define SM_B1 (SM_A2 + 4 * STAGE_A)
#define SM_B2 (SM_B1 + 4 * STAGE_B)
#define SMEM_G (SM_B2 + 4 * STAGE_B)  // 67584

__global__ __launch_bounds__(256, 2) void imma_gemm_kernel(
    const int8_t* __restrict__ A1, const int8_t* __restrict__ A2,
    const int8_t* __restrict__ W1, const int8_t* __restrict__ W2,
    const float* __restrict__ sA, const float* __restrict__ sW,
    const float* __restrict__ bias, float* __restrict__ out,
    int M, int ldout, int segstride, int nwrite) {
  extern __shared__ __align__(128) char smraw[];
  const uint32_t sm = (uint32_t)__cvta_generic_to_shared(smraw);
  const int tid = threadIdx.x;
  const int warp = tid >> 5, lane = tid & 31;
  const int m0 = blockIdx.y * BM, n0 = blockIdx.x * BN;
  const int wm0 = (warp >> 1) * 32;  // 4 m-warps
  const int wn0 = (warp & 1) * 24;   // 2 n-warps

  int acc1[2][3][4], accX[2][3][4];
#pragma unroll
  for (int i = 0; i < 2; i++)
#pragma unroll
    for (int j = 0; j < 3; j++)
#pragma unroll
      for (int k = 0; k < 4; k++) { acc1[i][j][k] = 0; accX[i][j][k] = 0; }

  const int lr = tid >> 1, lch = tid & 1;
  const size_t srcA = (size_t)(m0 + lr) * KROW + lch * 16;
  const size_t srcB = (size_t)(n0 + lr) * KROW + lch * 16;
  const uint32_t dstO = (uint32_t)(lr * APITCH + lch * 16);

#define LOAD_STAGE(buf, ks)                                              \
  do {                                                                   \
    cpa16(sm + SM_A1 + (buf) * STAGE_A + dstO, A1 + srcA + (ks) * 32);   \
    cpa16(sm + SM_A2 + (buf) * STAGE_A + dstO, A2 + srcA + (ks) * 32);   \
    if (tid < 2 * BN) {                                                  \
      cpa16(sm + SM_B1 + (buf) * STAGE_B + dstO, W1 + srcB + (ks) * 32); \
      cpa16(sm + SM_B2 + (buf) * STAGE_B + dstO, W2 + srcB + (ks) * 32); \
    }                                                                    \
  } while (0)

  LOAD_STAGE(0, 0); cpa_commit();
  LOAD_STAGE(1, 1); cpa_commit();
  LOAD_STAGE(2, 2); cpa_commit();

  // ldmatrix lane offsets
  const uint32_t aOff = (uint32_t)((lane & 15) * APITCH + (lane >> 4) * 16);
  const uint32_t b4Off = (uint32_t)((wn0 + (lane & 15)) * APITCH + (lane >> 4) * 16);
  const uint32_t b2Off = (uint32_t)((wn0 + 16 + (lane & 7)) * APITCH + ((lane >> 3) & 1) * 16);

  for (int ks = 0; ks < KSTEP; ks++) {
    const int buf = ks & 3;
    cpa_wait<2>();
    __syncthreads();
    if (ks + 3 < KSTEP) LOAD_STAGE((ks + 3) & 3, ks + 3);
    cpa_commit();

    const uint32_t a1B = sm + SM_A1 + buf * STAGE_A;
    const uint32_t a2B = sm + SM_A2 + buf * STAGE_A;
    const uint32_t b1B = sm + SM_B1 + buf * STAGE_B;
    const uint32_t b2B = sm + SM_B2 + buf * STAGE_B;

    uint32_t a1f[2][4], a2f[2][4], b1f[3][2], b2f[3][2];
#pragma unroll
    for (int ti = 0; ti < 2; ti++) {
      uint32_t ro = (uint32_t)((wm0 + ti * 16) * APITCH) + aOff;
      ldsm4(a1f[ti], a1B + ro);
      ldsm4(a2f[ti], a2B + ro);
    }
    {
      uint32_t t[4];
      ldsm4(t, b1B + b4Off);
      b1f[0][0] = t[0]; b1f[0][1] = t[2];
      b1f[1][0] = t[1]; b1f[1][1] = t[3];
      ldsm2(b1f[2], b1B + b2Off);
      ldsm4(t, b2B + b4Off);
      b2f[0][0] = t[0]; b2f[0][1] = t[2];
      b2f[1][0] = t[1]; b2f[1][1] = t[3];
      ldsm2(b2f[2], b2B + b2Off);
    }
#pragma unroll
    for (int ti = 0; ti < 2; ti++)
#pragma unroll
      for (int nj = 0; nj < 3; nj++) {
        imma(acc1[ti][nj], a1f[ti], b1f[nj]);
        imma(accX[ti][nj], a1f[ti], b2f[nj]);
        imma(accX[ti][nj], a2f[ti], b1f[nj]);
      }
  }
#undef LOAD_STAGE

  // epilogue: out = sA*sW*(acc1 + accX/128) + bias
  const int g = lane >> 2, tq = lane & 3;
#pragma unroll
  for (int nj = 0; nj < 3; nj++) {
    int n = n0 + wn0 + nj * 8 + tq * 2;
    int seg = n / NSEG, nr = n - seg * NSEG;
    if (nr >= nwrite) continue;
    int col = seg * segstride + nr;
    float sw0 = sW[n], sw1 = sW[n + 1];
    float b0 = bias[n], b1 = bias[n + 1];
#pragma unroll
    for (int ti = 0; ti < 2; ti++) {
      int m = m0 + wm0 + ti * 16 + g;
#pragma unroll
      for (int half = 0; half < 2; half++) {
        int mm = m + half * 8;
        if (mm >= M) continue;
        float sa = sA[mm];
        float f0 = (float)acc1[ti][nj][2 * half] + (float)accX[ti][nj][2 * half] * 0.0078125f;
        float f1 = (float)acc1[ti][nj][2 * half + 1] + (float)accX[ti][nj][2 * half + 1] * 0.0078125f;
        *(float2*)(out + (size_t)mm * ldout + col) =
            make_float2(sa * sw0 * f0 + b0, sa * sw1 * f1 + b1);
      }
    }
  }
}

// ---------------- attention (per sample), quantized output ----------------
template <int LAYER>
__global__ __launch_bounds__(256) void attn_kernel(const int* __restrict__ neighbors, int B) {
  __shared__ float q[E_];
  __shared__ float kk[KNB][E_];
  __shared__ float sc[HH][KNB];
  __shared__ float at[HH][KNB];
  __shared__ float red[256];
  __shared__ const float* akp[KNB];
  __shared__ const float* bkp[KNB];
  __shared__ int pad[KNB];

  const int b = blockIdx.x;
  const int tid = threadIdx.x;
  const float* trow = g_tqkv + (size_t)b * 576;

  if (tid < KNB) {
    int nb = neighbors[b * KNB + tid];
    pad[tid] = (nb == 0) ? 1 : 0;
    const float* ap = g_node_kv + (size_t)nb * 384;
    if (LAYER == 1) {
      int ow = g_owner[nb];
      if (ow >= 0) ap = g_upd_kv + (size_t)ow * 384;
    }
    akp[tid] = ap;
    bkp[tid] = g_edge_kv + ((size_t)b * KNB + tid) * 384;
  }
  if (tid < E_) q[tid] = g_qh[(size_t)b * KROW + tid] + trow[tid];
  __syncthreads();

  const float* tk = trow + NSEG;
  for (int idx = tid; idx < KNB * E_; idx += 256) {
    int j = idx / E_, e = idx - j * E_;
    kk[j][e] = akp[j][e] + bkp[j][e] + tk[e];
  }
  if (tid == 0) {
    int all = 1;
#pragma unroll
    for (int j = 0; j < KNB; j++) all &= pad[j];
    if (all) pad[0] = 0;
  }
  __syncthreads();

  if (tid < HH * KNB) {
    int h = tid / KNB, j = tid - h * KNB;
    const float* qp = q + h * HD_;
    const float* kp = &kk[j][h * HD_];
    float sum = 0.f;
#pragma unroll
    for (int d = 0; d < HD_; d++) sum += qp[d] * kp[d];
    sum *= 0.10783277320343841f;
    if (pad[j]) sum = -1e9f;
    sc[h][j] = sum;
  }
  __syncthreads();

  if (tid < HH) {
    float m = -INFINITY;
#pragma unroll
    for (int j = 0; j < KNB; j++) m = fmaxf(m, sc[tid][j]);
    float ex[KNB], ssum = 0.f;
#pragma unroll
    for (int j = 0; j < KNB; j++) { ex[j] = expf(sc[tid][j] - m); ssum += ex[j]; }
    float inv = 1.f / ssum;
#pragma unroll
    for (int j = 0; j < KNB; j++) at[tid][j] = ex[j] * inv;
  }
  __syncthreads();

  float o = 0.f;
  if (tid < E_) {
    int h = tid / HD_;
    o = trow[2 * NSEG + tid];  // t_v (includes bv); sum(attn)==1
#pragma unroll
    for (int j = 0; j < KNB; j++)
      o += at[h][j] * (akp[j][NSEG + tid] + bkp[j][NSEG + tid]);
  }
  // quantize the row into A buffers
  red[tid] = (tid < E_) ? fabsf(o) : 0.f;
  __syncthreads();
#pragma unroll
  for (int s = 128; s; s >>= 1) {
    if (tid < s) red[tid] = fmaxf(red[tid], red[tid + s]);
    __syncthreads();
  }
  float amax = red[0];
  float inv = amax > 0.f ? 127.f / amax : 0.f;
  if (tid == 0) g_sA[b] = amax * (1.f / 127.f);
  if (tid < KROW) {
    int q1 = 0, q2 = 0;
    if (tid < E_) {
      float xs = o * inv;
      q1 = __float2int_rn(xs);
      q2 = __float2int_rn((xs - (float)q1) * 128.f);
    }
    g_A1[(size_t)b * KROW + tid] = (int8_t)q1;
    g_A2[(size_t)b * KROW + tid] = (int8_t)q2;
  }
}

// ---------------- launch ----------------
static inline int cdiv(int a, int b) { return (a + b - 1) / b; }

extern "C" void kernel_launch(void* const* d_in, const int* in_sizes, int n_in,
                              void* d_out, int out_size) {
  const int* nodes     = (const int*)d_in[0];
  const float* ts      = (const float*)d_in[1];
  const int* neighbors = (const int*)d_in[2];
  const int* eidx      = (const int*)d_in[3];
  const float* nf      = (const float*)d_in[4];
  const float* ef      = (const float*)d_in[5];
  const float* time_w  = (const float*)d_in[6];
  const float* time_b  = (const float*)d_in[7];
  const float* q_w     = (const float*)d_in[8];
  const float* k_w     = (const float*)d_in[9];
  const float* v_w     = (const float*)d_in[10];
  const float* bq      = (const float*)d_in[11];
  const float* bk      = (const float*)d_in[12];
  const float* bv      = (const float*)d_in[13];
  const float* out_w   = (const float*)d_in[14];
  const float* out_b   = (const float*)d_in[15];
  float* out = (float*)d_out;
  const int B = in_sizes[0];

  int8_t *pA1, *pA2, *pW1, *pW2, *pH1q1, *pH1q2;
  float *psA, *psW, *pWb, *ptqkv, *pnodekv, *pedgekv, *pupdkv, *pqh, *ph1f, *psh1;
  cudaGetSymbolAddress((void**)&pA1, g_A1);
  cudaGetSymbolAddress((void**)&pA2, g_A2);
  cudaGetSymbolAddress((void**)&psA, g_sA);
  cudaGetSymbolAddress((void**)&pW1, g_W1);
  cudaGetSymbolAddress((void**)&pW2, g_W2);
  cudaGetSymbolAddress((void**)&psW, g_sW);
  cudaGetSymbolAddress((void**)&pWb, g_Wb);
  cudaGetSymbolAddress((void**)&ptqkv, g_tqkv);
  cudaGetSymbolAddress((void**)&pnodekv, g_node_kv);
  cudaGetSymbolAddress((void**)&pedgekv, g_edge_kv);
  cudaGetSymbolAddress((void**)&pupdkv, g_upd_kv);
  cudaGetSymbolAddress((void**)&pqh, g_qh);
  cudaGetSymbolAddress((void**)&ph1f, g_h1f);
  cudaGetSymbolAddress((void**)&pH1q1, g_H1q1);
  cudaGetSymbolAddress((void**)&pH1q2, g_H1q2);
  cudaGetSymbolAddress((void**)&psh1, g_sh1);

  cudaFuncSetAttribute(imma_gemm_kernel, cudaFuncAttributeMaxDynamicSharedMemorySize, SMEM_G);

  PArgs p;

#define QW(poff, nseg)                                                           \
  quant_w_kernel<<<cdiv((nseg) * NSEG * 32, 256), 256>>>(                        \
      p, (nseg), pW1 + (size_t)(poff) * KROW, pW2 + (size_t)(poff) * KROW,       \
      psW + (poff), pWb + (poff))
#define GEMM(Mpad, Npad, poff, sAp, Ap1, Ap2, outp, M, ldo, segs, nw)            \
  imma_gemm_kernel<<<dim3((Npad) / BN, (Mpad) / BM), 256, SMEM_G>>>(             \
      Ap1, Ap2, pW1 + (size_t)(poff) * KROW, pW2 + (size_t)(poff) * KROW,        \
      sAp, psW + (poff), pWb + (poff), outp, M, ldo, segs, nw)

  // 0: edge weights (P3)
  p.w[0] = k_w; p.ld[0] = 2 * E_; p.coff[0] = E_; p.bias[0] = nullptr;
  p.w[1] = v_w; p.ld[1] = 2 * E_; p.coff[1] = E_; p.bias[1] = nullptr;
  p.w[2] = nullptr; p.ld[2] = 0; p.coff[2] = 0; p.bias[2] = nullptr;
  QW(P3_OFF, 2);
  // 1: edge features quantize (gather eidx)
  quant_rows_kernel<<<cdiv(NSLOT * 32, 256), 256>>>(ef, E_, eidx, 1, B * KNB, NSLOT, E_, pA1, pA2, psA);
  // 2: init owner
  init_owner_kernel<<<cdiv(NNODES, 256), 256>>>();
  // 3: edge GEMM  <-- ncu capture target
  GEMM(NSLOT, 384, P3_OFF, psA, pA1, pA2, pedgekv, B * KNB, 384, NSEG, NSEG);

  // 4: P1 (tqkv + biases)
  p.w[0] = q_w; p.ld[0] = E_;     p.coff[0] = 0; p.bias[0] = bq;
  p.w[1] = k_w; p.ld[1] = 2 * E_; p.coff[1] = 0; p.bias[1] = bk;
  p.w[2] = v_w; p.ld[2] = 2 * E_; p.coff[2] = 0; p.bias[2] = bv;
  QW(P1_OFF, 3);
  // 5: P2 (node/upd kv)
  p.w[0] = k_w; p.ld[0] = 2 * E_; p.coff[0] = 0; p.bias[0] = nullptr;
  p.w[1] = v_w; p.ld[1] = 2 * E_; p.coff[1] = 0; p.bias[1] = nullptr;
  p.w[2] = nullptr;
  QW(P2_OFF, 2);
  // 6: time encoding quantize
  timequant_kernel<<<cdiv(BPAD * 32, 256), 256>>>(ts, time_w, time_b, B, BPAD);
  // 7: tqkv GEMM
  GEMM(BPAD, 576, P1_OFF, psA, pA1, pA2, ptqkv, B, 576, NSEG, NSEG);
  // 8: node features quantize
  quant_rows_kernel<<<cdiv(NPADN * 32, 256), 256>>>(nf, E_, nullptr, 0, NNODES, NPADN, E_, pA1, pA2, psA);
  // 9: node GEMM
  GEMM(NPADN, 384, P2_OFF, psA, pA1, pA2, pnodekv, NNODES, 384, NSEG, NSEG);
  // 10: P4 (q proj)
  p.w[0] = q_w; p.ld[0] = E_; p.coff[0] = 0; p.bias[0] = nullptr;
  p.w[1] = nullptr; p.w[2] = nullptr;
  QW(P4_OFF, 1);
  // 11: P5 (out proj + bias)
  p.w[0] = out_w; p.bias[0] = out_b;
  QW(P5_OFF, 1);

  // ---- layer 0 ----
  quant_rows_kernel<<<cdiv(BPAD * 32, 256), 256>>>(nf, E_, nodes, 1, B, BPAD, E_, pA1, pA2, psA);
  GEMM(BPAD, NSEG, P4_OFF, psA, pA1, pA2, pqh, B, KROW, 0, KROW);
  attn_kernel<0><<<B, 256>>>(neighbors, B);  // writes quantized rows to A buffers
  GEMM(BPAD, NSEG, P5_OFF, psA, pA1, pA2, ph1f, B, KROW, 0, KROW);
  build_owner_kernel<<<cdiv(B, 256), 256>>>(nodes, B);

  // ---- layer 1 ----
  quant_rows_kernel<<<cdiv(BPAD * 32, 256), 256>>>(ph1f, KROW, nullptr, 0, B, BPAD, E_, pH1q1, pH1q2, psh1);
  GEMM(BPAD, 384, P2_OFF, psh1, pH1q1, pH1q2, pupdkv, B, 384, NSEG, NSEG);
  gather_h1_kernel<<<cdiv(BPAD * (KROW / 4), 256), 256>>>(nodes, B, BPAD);
  GEMM(BPAD, NSEG, P4_OFF, psA, pA1, pA2, pqh, B, KROW, 0, KROW);
  attn_kernel<1><<<B, 256>>>(neighbors, B);
  GEMM(BPAD, NSEG, P5_OFF, psA, pA1, pA2, out, B, E_, 0, E_);
#undef GEMM
#undef QW
}

// round 8
// speedup vs baseline: 1.4575x; 1.4575x over previous
#include <cuda_runtime.h>
#include <cuda_bf16.h>
#include <math.h>
#include <stdint.h>

#define E_ 172
#define KP 176            // padded K (11 k16 steps)
#define KSTEPS 11
#define NSEG 192          // padded N per weight segment
#define KNB 20
#define HH 2
#define HD_ 86
#define NNODES 100000
#define BMAX 12000
#define BPAD 12032        // 94*128
#define NPADN 100096      // 782*128
#define NSLOT 240000      // 1875*128
#define HTSZ (1 << 19)

// pack row offsets within the packed weight buffer (rows of KP cols)
#define P1_OFF 0      // tqkv: 3 segs (q,kE,vE) + biases        N=576
#define P2_OFF 576    // node/upd kv: (kE, vE)                  N=384
#define P3_OFF 960    // edge kv: (kD, vD)                      N=384
#define P4_OFF 1344   // q proj                                 N=192
#define P5_OFF 1536   // out proj + bias                        N=192
#define PTOT 1728

// ---------------- scratch ----------------
__device__ __nv_bfloat16 g_Ahi[(size_t)NSLOT * KP];
__device__ __nv_bfloat16 g_Alo[(size_t)NSLOT * KP];
__device__ __nv_bfloat16 g_Whi[(size_t)PTOT * KP];
__device__ __nv_bfloat16 g_Wlo[(size_t)PTOT * KP];
__device__ float g_Wb[PTOT];

__device__ float g_tqkv[BMAX * 576];
__device__ float g_node_kv[(size_t)NNODES * 384];
__device__ float g_edge_kv[(size_t)NSLOT * 384];  // rows indexed by unique-edge uid
__device__ float g_upd_kv[BMAX * 384];
__device__ float g_qh[BMAX * KP];
__device__ __nv_bfloat16 g_H1hi[BPAD * KP];   // layer-0 output, bf16 split
__device__ __nv_bfloat16 g_H1lo[BPAD * KP];
__device__ int g_owner[NNODES];

// edge dedup
__device__ int g_ht[HTSZ];
__device__ int g_uidtab[HTSZ];
__device__ int g_uelist[NSLOT];
__device__ int g_map[NSLOT];
__device__ int g_cnt;

// ---------------- helpers ----------------
__device__ __forceinline__ void cpa16(uint32_t dst, const void* src) {
  asm volatile("cp.async.cg.shared.global [%0], [%1], 16;" :: "r"(dst), "l"(src));
}
__device__ __forceinline__ void cpa_commit() { asm volatile("cp.async.commit_group;" ::: "memory"); }
template <int N>
__device__ __forceinline__ void cpa_wait() { asm volatile("cp.async.wait_group %0;" :: "n"(N) : "memory"); }

__device__ __forceinline__ void ldsm4(uint32_t* r, uint32_t addr) {
  asm volatile("ldmatrix.sync.aligned.m8n8.x4.shared.b16 {%0,%1,%2,%3}, [%4];"
               : "=r"(r[0]), "=r"(r[1]), "=r"(r[2]), "=r"(r[3]) : "r"(addr));
}
__device__ __forceinline__ void mma_bf16(float* d, const uint32_t* a, const uint32_t* b) {
  asm volatile(
      "mma.sync.aligned.m16n8k16.row.col.f32.bf16.bf16.f32 "
      "{%0,%1,%2,%3},{%4,%5,%6,%7},{%8,%9},{%0,%1,%2,%3};"
      : "+f"(d[0]), "+f"(d[1]), "+f"(d[2]), "+f"(d[3])
      : "r"(a[0]), "r"(a[1]), "r"(a[2]), "r"(a[3]), "r"(b[0]), "r"(b[1]));
}

__device__ __forceinline__ void bf16split(float v, __nv_bfloat16& h, __nv_bfloat16& l) {
  h = __float2bfloat16(v);
  l = __float2bfloat16(v - __bfloat162float(h));
}

__device__ __forceinline__ uint32_t ehash(int e) {
  return (((uint32_t)e * 2654435761u) >> 13) & (HTSZ - 1);
}

// ---------------- small kernels ----------------
__global__ void init_owner_kernel() {
  int i = blockIdx.x * blockDim.x + threadIdx.x;
  if (i < NNODES) g_owner[i] = -1;
}
__global__ void build_owner_kernel(const int* __restrict__ nodes, int B) {
  int i = blockIdx.x * blockDim.x + threadIdx.x;
  if (i < B) atomicMax(&g_owner[nodes[i]], i);
}

// ---------------- edge dedup (3 race-free phases) ----------------
__global__ void dedup1_kernel(const int* __restrict__ eidx, int n) {
  int i = blockIdx.x * blockDim.x + threadIdx.x;
  if (i >= n) return;
  int e = eidx[i];
  uint32_t h = ehash(e);
  while (true) {
    int prev = atomicCAS(&g_ht[h], -1, e);
    if (prev == -1 || prev == e) break;
    h = (h + 1) & (HTSZ - 1);
  }
}
__global__ void dedup2_kernel() {
  int i = blockIdx.x * blockDim.x + threadIdx.x;
  if (i >= HTSZ) return;
  int e = g_ht[i];
  if (e != -1) {
    int uid = atomicAdd(&g_cnt, 1);
    g_uidtab[i] = uid;
    g_uelist[uid] = e;
  }
}
__global__ void dedup3_kernel(const int* __restrict__ eidx, int n) {
  int i = blockIdx.x * blockDim.x + threadIdx.x;
  if (i >= n) return;
  int e = eidx[i];
  uint32_t h = ehash(e);
  while (g_ht[h] != e) h = (h + 1) & (HTSZ - 1);
  g_map[i] = g_uidtab[h];
}

// ---------------- weight packing ----------------
struct PArgs {
  const float* w[3];
  int ld[3];
  int coff[3];
  const float* bias[3];
};
__global__ void pack_w_kernel(PArgs a, int nseg, __nv_bfloat16* whi,
                              __nv_bfloat16* wlo, float* pbias) {
  int i = blockIdx.x * blockDim.x + threadIdx.x;
  int tot = nseg * NSEG * KP;
  if (i >= tot) return;
  int n = i / KP, c = i - n * KP;
  int seg = n / NSEG, nr = n - seg * NSEG;
  float v = 0.f;
  if (nr < E_ && c < E_) v = a.w[seg][(size_t)nr * a.ld[seg] + a.coff[seg] + c];
  __nv_bfloat16 h, l;
  bf16split(v, h, l);
  whi[i] = h; wlo[i] = l;
  if (c == 0) pbias[n] = (nr < E_ && a.bias[seg]) ? a.bias[seg][nr] : 0.f;
}

// ---------------- input conversion ----------------
__global__ void convert_kernel(const float* __restrict__ X, int ldx,
                               const int* __restrict__ g1, int gmode,
                               int M, int Mpad) {
  int i = blockIdx.x * blockDim.x + threadIdx.x;
  if (i >= Mpad * KP) return;
  int r = i / KP, c = i - r * KP;
  float v = 0.f;
  if (r < M && c < E_) {
    int src = r;
    if (gmode >= 1) src = g1[r];
    v = X[(size_t)src * ldx + c];
  }
  __nv_bfloat16 h, l;
  bf16split(v, h, l);
  g_Ahi[i] = h; g_Alo[i] = l;
}

__global__ void convert_uedges_kernel(const float* __restrict__ ef) {
  int i = blockIdx.x * blockDim.x + threadIdx.x;
  if (i >= NSLOT * KP) return;
  int r = i / KP, c = i - r * KP;
  if (r >= g_cnt) return;
  float v = (c < E_) ? ef[(size_t)g_uelist[r] * E_ + c] : 0.f;
  __nv_bfloat16 h, l;
  bf16split(v, h, l);
  g_Ahi[i] = h; g_Alo[i] = l;
}

__global__ void timeconv_kernel(const float* __restrict__ ts,
                                const float* __restrict__ tw,
                                const float* __restrict__ tb, int B, int Mpad) {
  int i = blockIdx.x * blockDim.x + threadIdx.x;
  if (i >= Mpad * KP) return;
  int r = i / KP, c = i - r * KP;
  float v = 0.f;
  if (r < B && c < E_) {
    float arg = __fadd_rn(__fmul_rn(ts[r], tw[c]), tb[c]);
    v = (float)cos((double)arg);
  }
  __nv_bfloat16 h, l;
  bf16split(v, h, l);
  g_Ahi[i] = h; g_Alo[i] = l;
}

// gather h1 rows (bf16 split) for layer-1 q
__global__ void gather_h1_kernel(const int* __restrict__ nodes, int B, int Mpad) {
  int i = blockIdx.x * blockDim.x + threadIdx.x;
  if (i >= Mpad * KP) return;
  int r = i / KP, c = i - r * KP;
  __nv_bfloat16 h = __float2bfloat16(0.f), l = h;
  if (r < B) {
    int src = g_owner[nodes[r]];
    h = g_H1hi[(size_t)src * KP + c];
    l = g_H1lo[(size_t)src * KP + c];
  }
  g_Ahi[i] = h; g_Alo[i] = l;
}

// ---------------- pipelined bf16 HMMA GEMM ----------------
#define BM 128
#define BN 96
#define ST 24
#define STAGE_A_B (BM * ST * 2)
#define STAGE_B_B (BN * ST * 2)
#define SM_AH 0
#define SM_AL (SM_AH + 4 * STAGE_A_B)
#define SM_BH (SM_AL + 4 * STAGE_A_B)
#define SM_BL (SM_BH + 4 * STAGE_B_B)
#define SMEM_G (SM_BL + 4 * STAGE_B_B)

__global__ __launch_bounds__(256, 2) void mma_gemm_kernel(
    const __nv_bfloat16* __restrict__ Ahi, const __nv_bfloat16* __restrict__ Alo,
    const __nv_bfloat16* __restrict__ Whi, const __nv_bfloat16* __restrict__ Wlo,
    const float* __restrict__ bias, float* __restrict__ out,
    __nv_bfloat16* __restrict__ ohi, __nv_bfloat16* __restrict__ olo,
    int M, int ldout, int segstride, int nwrite, const int* __restrict__ Mptr) {
  if (Mptr) {
    M = *Mptr;
    if ((int)(blockIdx.y * BM) >= M) return;
  }
  extern __shared__ __align__(128) char smraw[];
  const uint32_t sm = (uint32_t)__cvta_generic_to_shared(smraw);
  const int tid = threadIdx.x;
  const int warp = tid >> 5, lane = tid & 31;
  const int m0 = blockIdx.y * BM;
  const int n0 = blockIdx.x * BN;
  const int wm0 = (warp >> 1) * 32;
  const int wn0 = (warp & 1) * 48;

  float acc[2][6][4];
#pragma unroll
  for (int i = 0; i < 2; i++)
#pragma unroll
    for (int j = 0; j < 6; j++)
#pragma unroll
      for (int k = 0; k < 4; k++) acc[i][j][k] = 0.f;

  const int lr = tid >> 1, lch = tid & 1;
  const size_t srcA = (size_t)(m0 + lr) * KP + lch * 8;
  const size_t srcB = (size_t)(n0 + lr) * KP + lch * 8;
  const uint32_t dstAoff = (uint32_t)((lr * ST + lch * 8) * 2);
  const uint32_t dstBoff = dstAoff;

#define LOAD_STAGE(buf, ki)                                                   \
  do {                                                                        \
    cpa16(sm + SM_AH + (buf) * STAGE_A_B + dstAoff, Ahi + srcA + (ki) * 16);  \
    cpa16(sm + SM_AL + (buf) * STAGE_A_B + dstAoff, Alo + srcA + (ki) * 16);  \
    if (tid < 2 * BN) {                                                       \
      cpa16(sm + SM_BH + (buf) * STAGE_B_B + dstBoff, Whi + srcB + (ki) * 16);\
      cpa16(sm + SM_BL + (buf) * STAGE_B_B + dstBoff, Wlo + srcB + (ki) * 16);\
    }                                                                         \
  } while (0)

  LOAD_STAGE(0, 0); cpa_commit();
  LOAD_STAGE(1, 1); cpa_commit();
  LOAD_STAGE(2, 2); cpa_commit();

  const int aRow = (lane & 7) + ((lane >> 3) & 1) * 8;
  const int aCol = ((lane >> 4) & 1) * 8;
  const int bRow = (lane & 7) + ((lane >> 4) & 1) * 8;
  const int bCol = ((lane >> 3) & 1) * 8;

  for (int ki = 0; ki < KSTEPS; ki++) {
    const int buf = ki & 3;
    cpa_wait<2>();
    __syncthreads();
    if (ki + 3 < KSTEPS) LOAD_STAGE((ki + 3) & 3, ki + 3);
    cpa_commit();

    const uint32_t aB = sm + SM_AH + buf * STAGE_A_B;
    const uint32_t alB = sm + SM_AL + buf * STAGE_A_B;
    const uint32_t bB = sm + SM_BH + buf * STAGE_B_B;
    const uint32_t blB = sm + SM_BL + buf * STAGE_B_B;

    uint32_t ah[2][4], al[2][4], bh[6][2], bl[6][2];
#pragma unroll
    for (int ti = 0; ti < 2; ti++) {
      uint32_t off = (uint32_t)(((wm0 + ti * 16 + aRow) * ST + aCol) * 2);
      ldsm4(ah[ti], aB + off);
      ldsm4(al[ti], alB + off);
    }
#pragma unroll
    for (int p = 0; p < 3; p++) {
      uint32_t off = (uint32_t)(((wn0 + p * 16 + bRow) * ST + bCol) * 2);
      uint32_t t[4];
      ldsm4(t, bB + off);
      bh[2 * p][0] = t[0]; bh[2 * p][1] = t[1];
      bh[2 * p + 1][0] = t[2]; bh[2 * p + 1][1] = t[3];
      ldsm4(t, blB + off);
      bl[2 * p][0] = t[0]; bl[2 * p][1] = t[1];
      bl[2 * p + 1][0] = t[2]; bl[2 * p + 1][1] = t[3];
    }
#pragma unroll
    for (int ti = 0; ti < 2; ti++)
#pragma unroll
      for (int nj = 0; nj < 6; nj++) {
        mma_bf16(acc[ti][nj], ah[ti], bh[nj]);
        mma_bf16(acc[ti][nj], ah[ti], bl[nj]);
        mma_bf16(acc[ti][nj], al[ti], bh[nj]);
      }
  }
#undef LOAD_STAGE

  // epilogue
  const int g = lane >> 2, tq = lane & 3;
#pragma unroll
  for (int ti = 0; ti < 2; ti++) {
    int m = m0 + wm0 + ti * 16 + g;
#pragma unroll
    for (int nj = 0; nj < 6; nj++) {
      int n = n0 + wn0 + nj * 8 + tq * 2;
      int seg = n / NSEG, nr = n - seg * NSEG;
      if (nr >= nwrite) continue;
      int col = seg * segstride + nr;
      float b0 = bias[n], b1 = bias[n + 1];
#pragma unroll
      for (int half = 0; half < 2; half++) {
        int mm = m + half * 8;
        if (mm >= M) continue;
        float v0 = acc[ti][nj][2 * half] + b0;
        float v1 = acc[ti][nj][2 * half + 1] + b1;
        if (out) {
          *(float2*)(out + (size_t)mm * ldout + col) = make_float2(v0, v1);
        } else {
          __nv_bfloat16 h0, l0, h1, l1;
          bf16split(v0, h0, l0);
          bf16split(v1, h1, l1);
          *(__nv_bfloat162*)(ohi + (size_t)mm * KP + col) = __nv_bfloat162(h0, h1);
          *(__nv_bfloat162*)(olo + (size_t)mm * KP + col) = __nv_bfloat162(l0, l1);
        }
      }
    }
  }
}

// ---------------- attention (per sample), writes bf16-split output ----------------
template <int LAYER>
__global__ __launch_bounds__(256) void attn_kernel(const int* __restrict__ neighbors, int B) {
  __shared__ float q[E_];
  __shared__ float kk[KNB][E_];
  __shared__ float sc[HH][KNB];
  __shared__ float at[HH][KNB];
  __shared__ const float* akp[KNB];
  __shared__ const float* bkp[KNB];
  __shared__ int pad[KNB];

  const int b = blockIdx.x;
  const int tid = threadIdx.x;
  const float* trow = g_tqkv + (size_t)b * 576;

  if (tid < KNB) {
    int nb = neighbors[b * KNB + tid];
    pad[tid] = (nb == 0) ? 1 : 0;
    const float* ap = g_node_kv + (size_t)nb * 384;
    if (LAYER == 1) {
      int ow = g_owner[nb];
      if (ow >= 0) ap = g_upd_kv + (size_t)ow * 384;
    }
    akp[tid] = ap;
    bkp[tid] = g_edge_kv + (size_t)g_map[b * KNB + tid] * 384;
  }
  if (tid < E_) q[tid] = g_qh[(size_t)b * KP + tid] + trow[tid];
  __syncthreads();

  const float* tk = trow + NSEG;
  for (int idx = tid; idx < KNB * E_; idx += 256) {
    int j = idx / E_, e = idx - j * E_;
    kk[j][e] = akp[j][e] + bkp[j][e] + tk[e];
  }
  if (tid == 0) {
    int all = 1;
#pragma unroll
    for (int j = 0; j < KNB; j++) all &= pad[j];
    if (all) pad[0] = 0;
  }
  __syncthreads();

  if (tid < HH * KNB) {
    int h = tid / KNB, j = tid - h * KNB;
    const float* qp = q + h * HD_;
    const float* kp = &kk[j][h * HD_];
    float sum = 0.f;
#pragma unroll
    for (int d = 0; d < HD_; d++) sum += qp[d] * kp[d];
    sum *= 0.10783277320343841f;
    if (pad[j]) sum = -1e9f;
    sc[h][j] = sum;
  }
  __syncthreads();

  if (tid < HH) {
    float m = -INFINITY;
#pragma unroll
    for (int j = 0; j < KNB; j++) m = fmaxf(m, sc[tid][j]);
    float ex[KNB], ssum = 0.f;
#pragma unroll
    for (int j = 0; j < KNB; j++) { ex[j] = expf(sc[tid][j] - m); ssum += ex[j]; }
    float inv = 1.f / ssum;
#pragma unroll
    for (int j = 0; j < KNB; j++) at[tid][j] = ex[j] * inv;
  }
  __syncthreads();

  if (tid < E_) {
    int h = tid / HD_;
    float o = trow[2 * NSEG + tid];  // t_v (includes bv); sum(attn)==1
#pragma unroll
    for (int j = 0; j < KNB; j++)
      o += at[h][j] * (akp[j][NSEG + tid] + bkp[j][NSEG + tid]);
    __nv_bfloat16 hh, ll;
    bf16split(o, hh, ll);
    g_Ahi[(size_t)b * KP + tid] = hh;
    g_Alo[(size_t)b * KP + tid] = ll;
  }
}

// ---------------- launch ----------------
static inline int cdiv(int a, int b) { return (a + b - 1) / b; }

extern "C" void kernel_launch(void* const* d_in, const int* in_sizes, int n_in,
                              void* d_out, int out_size) {
  const int* nodes     = (const int*)d_in[0];
  const float* ts      = (const float*)d_in[1];
  const int* neighbors = (const int*)d_in[2];
  const int* eidx      = (const int*)d_in[3];
  const float* nf      = (const float*)d_in[4];
  const float* ef      = (const float*)d_in[5];
  const float* time_w  = (const float*)d_in[6];
  const float* time_b  = (const float*)d_in[7];
  const float* q_w     = (const float*)d_in[8];
  const float* k_w     = (const float*)d_in[9];
  const float* v_w     = (const float*)d_in[10];
  const float* bq      = (const float*)d_in[11];
  const float* bk      = (const float*)d_in[12];
  const float* bv      = (const float*)d_in[13];
  const float* out_w   = (const float*)d_in[14];
  const float* out_b   = (const float*)d_in[15];
  float* out = (float*)d_out;
  const int B = in_sizes[0];

  __nv_bfloat16 *pWhi, *pWlo, *pAhi, *pAlo, *pH1hi, *pH1lo;
  float *pWb, *ptqkv, *pnodekv, *pedgekv, *pupdkv, *pqh;
  int *pht, *pcnt;
  cudaGetSymbolAddress((void**)&pWhi, g_Whi);
  cudaGetSymbolAddress((void**)&pWlo, g_Wlo);
  cudaGetSymbolAddress((void**)&pWb, g_Wb);
  cudaGetSymbolAddress((void**)&pAhi, g_Ahi);
  cudaGetSymbolAddress((void**)&pAlo, g_Alo);
  cudaGetSymbolAddress((void**)&pH1hi, g_H1hi);
  cudaGetSymbolAddress((void**)&pH1lo, g_H1lo);
  cudaGetSymbolAddress((void**)&ptqkv, g_tqkv);
  cudaGetSymbolAddress((void**)&pnodekv, g_node_kv);
  cudaGetSymbolAddress((void**)&pedgekv, g_edge_kv);
  cudaGetSymbolAddress((void**)&pupdkv, g_upd_kv);
  cudaGetSymbolAddress((void**)&pqh, g_qh);
  cudaGetSymbolAddress((void**)&pht, g_ht);
  cudaGetSymbolAddress((void**)&pcnt, g_cnt);

  cudaFuncSetAttribute(mma_gemm_kernel, cudaFuncAttributeMaxDynamicSharedMemorySize, SMEM_G);

  PArgs p;

#define GEMMF(Mpad, Npad, poff, outp, M, ldo, segs, nw, Mptr)                 \
  mma_gemm_kernel<<<dim3((Npad) / BN, (Mpad) / BM), 256, SMEM_G>>>(           \
      pAhi, pAlo, pWhi + (size_t)(poff) * KP, pWlo + (size_t)(poff) * KP,     \
      pWb + (poff), outp, nullptr, nullptr, M, ldo, segs, nw, Mptr)
#define GEMMB(Mpad, Npad, poff, M)                                            \
  mma_gemm_kernel<<<dim3((Npad) / BN, (Mpad) / BM), 256, SMEM_G>>>(           \
      pAhi, pAlo, pWhi + (size_t)(poff) * KP, pWlo + (size_t)(poff) * KP,     \
      pWb + (poff), nullptr, pH1hi, pH1lo, M, KP, 0, KP, nullptr)

  // ---- edge dedup ----
  cudaMemsetAsync(pht, 0xFF, (size_t)HTSZ * sizeof(int));
  cudaMemsetAsync(pcnt, 0, sizeof(int));
  dedup1_kernel<<<cdiv(B * KNB, 256), 256>>>(eidx, B * KNB);
  dedup2_kernel<<<cdiv(HTSZ, 256), 256>>>();

  // pack edge weights (P3), convert unique edges, edge GEMM
  p.w[0] = k_w; p.ld[0] = 2 * E_; p.coff[0] = E_; p.bias[0] = nullptr;
  p.w[1] = v_w; p.ld[1] = 2 * E_; p.coff[1] = E_; p.bias[1] = nullptr;
  p.w[2] = nullptr; p.ld[2] = 0; p.coff[2] = 0; p.bias[2] = nullptr;
  pack_w_kernel<<<cdiv(2 * NSEG * KP, 256), 256>>>(p, 2, pWhi + (size_t)P3_OFF * KP, pWlo + (size_t)P3_OFF * KP, pWb + P3_OFF);
  convert_uedges_kernel<<<cdiv(NSLOT * KP, 256), 256>>>(ef);
  GEMMF(NSLOT, 384, P3_OFF, pedgekv, B * KNB, 384, NSEG, NSEG, pcnt);
  dedup3_kernel<<<cdiv(B * KNB, 256), 256>>>(eidx, B * KNB);

  init_owner_kernel<<<cdiv(NNODES, 256), 256>>>();

  // pack P1 (tqkv + biases), P2 (node/upd kv)
  p.w[0] = q_w; p.ld[0] = E_;     p.coff[0] = 0; p.bias[0] = bq;
  p.w[1] = k_w; p.ld[1] = 2 * E_; p.coff[1] = 0; p.bias[1] = bk;
  p.w[2] = v_w; p.ld[2] = 2 * E_; p.coff[2] = 0; p.bias[2] = bv;
  pack_w_kernel<<<cdiv(3 * NSEG * KP, 256), 256>>>(p, 3, pWhi + (size_t)P1_OFF * KP, pWlo + (size_t)P1_OFF * KP, pWb + P1_OFF);
  p.w[0] = k_w; p.ld[0] = 2 * E_; p.coff[0] = 0; p.bias[0] = nullptr;
  p.w[1] = v_w; p.ld[1] = 2 * E_; p.coff[1] = 0; p.bias[1] = nullptr;
  p.w[2] = nullptr;
  pack_w_kernel<<<cdiv(2 * NSEG * KP, 256), 256>>>(p, 2, pWhi + (size_t)P2_OFF * KP, pWlo + (size_t)P2_OFF * KP, pWb + P2_OFF);

  // tqkv
  timeconv_kernel<<<cdiv(BPAD * KP, 256), 256>>>(ts, time_w, time_b, B, BPAD);
  GEMMF(BPAD, 576, P1_OFF, ptqkv, B, 576, NSEG, NSEG, nullptr);
  // node kv
  convert_kernel<<<cdiv(NPADN * KP, 256), 256>>>(nf, E_, nullptr, 0, NNODES, NPADN);
  GEMMF(NPADN, 384, P2_OFF, pnodekv, NNODES, 384, NSEG, NSEG, nullptr);
  // pack P4 (q), P5 (out + bias)
  p.w[0] = q_w; p.ld[0] = E_; p.coff[0] = 0; p.bias[0] = nullptr;
  p.w[1] = nullptr; p.w[2] = nullptr;
  pack_w_kernel<<<cdiv(NSEG * KP, 256), 256>>>(p, 1, pWhi + (size_t)P4_OFF * KP, pWlo + (size_t)P4_OFF * KP, pWb + P4_OFF);
  p.w[0] = out_w; p.bias[0] = out_b;
  pack_w_kernel<<<cdiv(NSEG * KP, 256), 256>>>(p, 1, pWhi + (size_t)P5_OFF * KP, pWlo + (size_t)P5_OFF * KP, pWb + P5_OFF);

  // ---- layer 0 ----
  convert_kernel<<<cdiv(BPAD * KP, 256), 256>>>(nf, E_, nodes, 1, B, BPAD);
  GEMMF(BPAD, NSEG, P4_OFF, pqh, B, KP, 0, KP, nullptr);
  attn_kernel<0><<<B, 256>>>(neighbors, B);          // writes bf16 into g_Ahi/g_Alo
  GEMMB(BPAD, NSEG, P5_OFF, B);                      // h1 -> bf16 split buffers
  build_owner_kernel<<<cdiv(B, 256), 256>>>(nodes, B);

  // ---- layer 1 ----
  mma_gemm_kernel<<<dim3(384 / BN, BPAD / BM), 256, SMEM_G>>>(
      pH1hi, pH1lo, pWhi + (size_t)P2_OFF * KP, pWlo + (size_t)P2_OFF * KP,
      pWb + P2_OFF, pupdkv, nullptr, nullptr, B, 384, NSEG, NSEG, nullptr);
  gather_h1_kernel<<<cdiv(BPAD * KP, 256), 256>>>(nodes, B, BPAD);
  GEMMF(BPAD, NSEG, P4_OFF, pqh, B, KP, 0, KP, nullptr);
  attn_kernel<1><<<B, 256>>>(neighbors, B);
  GEMMF(BPAD, NSEG, P5_OFF, out, B, E_, 0, E_, nullptr);
#undef GEMMF
#undef GEMMB
}

// round 9
// speedup vs baseline: 1.8065x; 1.2394x over previous
#include <cuda_runtime.h>
#include <cuda_bf16.h>
#include <math.h>
#include <stdint.h>

#define E_ 172
#define KP 176            // padded K (11 k16 steps)
#define KSTEPS 11
#define C4 (KP / 4)       // 44 float4 chunks per row (chunk 43 = zeros)
#define NSEG 192
#define KNB 20
#define HH 2
#define HD_ 86
#define NNODES 100000
#define BMAX 12000
#define BPAD 12032
#define NPADN 100096
#define NSLOT 240000
#define HTSZ (1 << 19)

#define P1_OFF 0
#define P2_OFF 576
#define P3_OFF 960
#define P4_OFF 1344
#define P5_OFF 1536
#define PTOT 1728

// ---------------- scratch ----------------
__device__ __nv_bfloat16 g_Ahi[(size_t)NSLOT * KP];
__device__ __nv_bfloat16 g_Alo[(size_t)NSLOT * KP];
__device__ __nv_bfloat16 g_Whi[(size_t)PTOT * KP];
__device__ __nv_bfloat16 g_Wlo[(size_t)PTOT * KP];
__device__ float g_Wb[PTOT];

__device__ float g_tqkv[BMAX * 576];
__device__ float g_node_kv[(size_t)NNODES * 384];
__device__ float g_edge_kv[(size_t)NSLOT * 384];
__device__ float g_upd_kv[BMAX * 384];
__device__ float g_qh[BMAX * KP];
__device__ __nv_bfloat16 g_H1hi[BPAD * KP];
__device__ __nv_bfloat16 g_H1lo[BPAD * KP];
__device__ int g_owner[NNODES];

__device__ int g_ht[HTSZ];
__device__ int g_uidtab[HTSZ];
__device__ int g_uelist[NSLOT];
__device__ int g_map[NSLOT];
__device__ int g_cnt;

// ---------------- helpers ----------------
__device__ __forceinline__ void cpa16(uint32_t dst, const void* src) {
  asm volatile("cp.async.cg.shared.global [%0], [%1], 16;" :: "r"(dst), "l"(src));
}
__device__ __forceinline__ void cpa_commit() { asm volatile("cp.async.commit_group;" ::: "memory"); }
template <int N>
__device__ __forceinline__ void cpa_wait() { asm volatile("cp.async.wait_group %0;" :: "n"(N) : "memory"); }

__device__ __forceinline__ void ldsm4(uint32_t* r, uint32_t addr) {
  asm volatile("ldmatrix.sync.aligned.m8n8.x4.shared.b16 {%0,%1,%2,%3}, [%4];"
               : "=r"(r[0]), "=r"(r[1]), "=r"(r[2]), "=r"(r[3]) : "r"(addr));
}
__device__ __forceinline__ void mma_bf16(float* d, const uint32_t* a, const uint32_t* b) {
  asm volatile(
      "mma.sync.aligned.m16n8k16.row.col.f32.bf16.bf16.f32 "
      "{%0,%1,%2,%3},{%4,%5,%6,%7},{%8,%9},{%0,%1,%2,%3};"
      : "+f"(d[0]), "+f"(d[1]), "+f"(d[2]), "+f"(d[3])
      : "r"(a[0]), "r"(a[1]), "r"(a[2]), "r"(a[3]), "r"(b[0]), "r"(b[1]));
}

__device__ __forceinline__ void bf16split(float v, __nv_bfloat16& h, __nv_bfloat16& l) {
  h = __float2bfloat16(v);
  l = __float2bfloat16(v - __bfloat162float(h));
}

// split a float4 into hi/lo bfloat162 pairs and store 4+4 bytes each
__device__ __forceinline__ void split_store4(float4 v, __nv_bfloat16* hi,
                                             __nv_bfloat16* lo, size_t off) {
  __nv_bfloat16 h0, l0, h1, l1, h2, l2, h3, l3;
  bf16split(v.x, h0, l0); bf16split(v.y, h1, l1);
  bf16split(v.z, h2, l2); bf16split(v.w, h3, l3);
  __nv_bfloat162 hA(h0, h1), hB(h2, h3), lA(l0, l1), lB(l2, l3);
  *(uint2*)(hi + off) = *(uint2*)&hA;  // hA,hB contiguous? store separately:
  ((__nv_bfloat162*)(hi + off))[0] = hA;
  ((__nv_bfloat162*)(hi + off))[1] = hB;
  ((__nv_bfloat162*)(lo + off))[0] = lA;
  ((__nv_bfloat162*)(lo + off))[1] = lB;
}

__device__ __forceinline__ uint32_t ehash(int e) {
  return (((uint32_t)e * 2654435761u) >> 13) & (HTSZ - 1);
}

// ---------------- small kernels ----------------
__global__ void init_owner_kernel() {
  int i = blockIdx.x * blockDim.x + threadIdx.x;
  if (i < NNODES) g_owner[i] = -1;
}
__global__ void build_owner_kernel(const int* __restrict__ nodes, int B) {
  int i = blockIdx.x * blockDim.x + threadIdx.x;
  if (i < B) atomicMax(&g_owner[nodes[i]], i);
}

// ---------------- edge dedup ----------------
__global__ void dedup1_kernel(const int* __restrict__ eidx, int n) {
  int i = blockIdx.x * blockDim.x + threadIdx.x;
  if (i >= n) return;
  int e = eidx[i];
  uint32_t h = ehash(e);
  while (true) {
    int prev = atomicCAS(&g_ht[h], -1, e);
    if (prev == -1 || prev == e) break;
    h = (h + 1) & (HTSZ - 1);
  }
}
__global__ void dedup2_kernel() {
  int i = blockIdx.x * blockDim.x + threadIdx.x;
  if (i >= HTSZ) return;
  int e = g_ht[i];
  if (e != -1) {
    int uid = atomicAdd(&g_cnt, 1);
    g_uidtab[i] = uid;
    g_uelist[uid] = e;
  }
}
__global__ void dedup3_kernel(const int* __restrict__ eidx, int n) {
  int i = blockIdx.x * blockDim.x + threadIdx.x;
  if (i >= n) return;
  int e = eidx[i];
  uint32_t h = ehash(e);
  while (g_ht[h] != e) h = (h + 1) & (HTSZ - 1);
  g_map[i] = g_uidtab[h];
}

// ---------------- weight packing ----------------
struct PArgs {
  const float* w[3];
  int ld[3];
  int coff[3];
  const float* bias[3];
};
__global__ void pack_w_kernel(PArgs a, int nseg, __nv_bfloat16* whi,
                              __nv_bfloat16* wlo, float* pbias) {
  int i = blockIdx.x * blockDim.x + threadIdx.x;
  int tot = nseg * NSEG * KP;
  if (i >= tot) return;
  int n = i / KP, c = i - n * KP;
  int seg = n / NSEG, nr = n - seg * NSEG;
  float v = 0.f;
  if (nr < E_ && c < E_) v = a.w[seg][(size_t)nr * a.ld[seg] + a.coff[seg] + c];
  __nv_bfloat16 h, l;
  bf16split(v, h, l);
  whi[i] = h; wlo[i] = l;
  if (c == 0) pbias[n] = (nr < E_ && a.bias[seg]) ? a.bias[seg][nr] : 0.f;
}

// ---------------- vectorized converts (1 float4 per thread) ----------------
__global__ void convert_kernel(const float* __restrict__ X, int ldx,
                               const int* __restrict__ g1, int gmode,
                               int M, int Mpad) {
  int i = blockIdx.x * blockDim.x + threadIdx.x;
  if (i >= Mpad * C4) return;
  int r = i / C4, c4 = i - r * C4;
  float4 v = make_float4(0.f, 0.f, 0.f, 0.f);
  if (r < M && c4 < 43) {
    int src = (gmode >= 1) ? g1[r] : r;
    v = *(const float4*)(X + (size_t)src * ldx + c4 * 4);
  }
  split_store4(v, g_Ahi, g_Alo, (size_t)r * KP + c4 * 4);
}

__global__ void convert_uedges_kernel(const float* __restrict__ ef) {
  int i = blockIdx.x * blockDim.x + threadIdx.x;
  if (i >= NSLOT * C4) return;
  int r = i / C4, c4 = i - r * C4;
  if (r >= g_cnt) return;
  float4 v = make_float4(0.f, 0.f, 0.f, 0.f);
  if (c4 < 43) v = *(const float4*)(ef + (size_t)g_uelist[r] * E_ + c4 * 4);
  split_store4(v, g_Ahi, g_Alo, (size_t)r * KP + c4 * 4);
}

__global__ void timeconv_kernel(const float* __restrict__ ts,
                                const float* __restrict__ tw,
                                const float* __restrict__ tb, int B, int Mpad) {
  int i = blockIdx.x * blockDim.x + threadIdx.x;
  if (i >= Mpad * C4) return;
  int r = i / C4, c4 = i - r * C4;
  float4 v = make_float4(0.f, 0.f, 0.f, 0.f);
  if (r < B && c4 < 43) {
    float tval = ts[r];
    float4 w = *(const float4*)(tw + c4 * 4);
    float4 b = *(const float4*)(tb + c4 * 4);
    v.x = (float)cos((double)__fadd_rn(__fmul_rn(tval, w.x), b.x));
    v.y = (float)cos((double)__fadd_rn(__fmul_rn(tval, w.y), b.y));
    v.z = (float)cos((double)__fadd_rn(__fmul_rn(tval, w.z), b.z));
    v.w = (float)cos((double)__fadd_rn(__fmul_rn(tval, w.w), b.w));
  }
  split_store4(v, g_Ahi, g_Alo, (size_t)r * KP + c4 * 4);
}

// gather h1 rows (bf16 split, int4 copy: 22 chunks of 16B per row)
__global__ void gather_h1_kernel(const int* __restrict__ nodes, int B, int Mpad) {
  int i = blockIdx.x * blockDim.x + threadIdx.x;
  const int CH = KP * 2 / 16;  // 22
  if (i >= Mpad * CH) return;
  int r = i / CH, w = i - r * CH;
  int4 v1 = make_int4(0, 0, 0, 0), v2 = v1;
  if (r < B) {
    int src = g_owner[nodes[r]];
    v1 = *(const int4*)((const char*)(g_H1hi + (size_t)src * KP) + w * 16);
    v2 = *(const int4*)((const char*)(g_H1lo + (size_t)src * KP) + w * 16);
  }
  *(int4*)((char*)(g_Ahi + (size_t)r * KP) + w * 16) = v1;
  *(int4*)((char*)(g_Alo + (size_t)r * KP) + w * 16) = v2;
}

// ---------------- pipelined bf16 HMMA GEMM ----------------
#define BM 128
#define BN 96
#define ST 24
#define STAGE_A_B (BM * ST * 2)
#define STAGE_B_B (BN * ST * 2)
#define SM_AH 0
#define SM_AL (SM_AH + 4 * STAGE_A_B)
#define SM_BH (SM_AL + 4 * STAGE_A_B)
#define SM_BL (SM_BH + 4 * STAGE_B_B)
#define SMEM_G (SM_BL + 4 * STAGE_B_B)

__global__ __launch_bounds__(256, 2) void mma_gemm_kernel(
    const __nv_bfloat16* __restrict__ Ahi, const __nv_bfloat16* __restrict__ Alo,
    const __nv_bfloat16* __restrict__ Whi, const __nv_bfloat16* __restrict__ Wlo,
    const float* __restrict__ bias, float* __restrict__ out,
    __nv_bfloat16* __restrict__ ohi, __nv_bfloat16* __restrict__ olo,
    int M, int ldout, int segstride, int nwrite, const int* __restrict__ Mptr) {
  if (Mptr) {
    M = *Mptr;
    if ((int)(blockIdx.y * BM) >= M) return;
  }
  extern __shared__ __align__(128) char smraw[];
  const uint32_t sm = (uint32_t)__cvta_generic_to_shared(smraw);
  const int tid = threadIdx.x;
  const int warp = tid >> 5, lane = tid & 31;
  const int m0 = blockIdx.y * BM;
  const int n0 = blockIdx.x * BN;
  const int wm0 = (warp >> 1) * 32;
  const int wn0 = (warp & 1) * 48;

  float acc[2][6][4];
#pragma unroll
  for (int i = 0; i < 2; i++)
#pragma unroll
    for (int j = 0; j < 6; j++)
#pragma unroll
      for (int k = 0; k < 4; k++) acc[i][j][k] = 0.f;

  const int lr = tid >> 1, lch = tid & 1;
  const size_t srcA = (size_t)(m0 + lr) * KP + lch * 8;
  const size_t srcB = (size_t)(n0 + lr) * KP + lch * 8;
  const uint32_t dstAoff = (uint32_t)((lr * ST + lch * 8) * 2);
  const uint32_t dstBoff = dstAoff;

#define LOAD_STAGE(buf, ki)                                                   \
  do {                                                                        \
    cpa16(sm + SM_AH + (buf) * STAGE_A_B + dstAoff, Ahi + srcA + (ki) * 16);  \
    cpa16(sm + SM_AL + (buf) * STAGE_A_B + dstAoff, Alo + srcA + (ki) * 16);  \
    if (tid < 2 * BN) {                                                       \
      cpa16(sm + SM_BH + (buf) * STAGE_B_B + dstBoff, Whi + srcB + (ki) * 16);\
      cpa16(sm + SM_BL + (buf) * STAGE_B_B + dstBoff, Wlo + srcB + (ki) * 16);\
    }                                                                         \
  } while (0)

  LOAD_STAGE(0, 0); cpa_commit();
  LOAD_STAGE(1, 1); cpa_commit();
  LOAD_STAGE(2, 2); cpa_commit();

  const int aRow = (lane & 7) + ((lane >> 3) & 1) * 8;
  const int aCol = ((lane >> 4) & 1) * 8;
  const int bRow = (lane & 7) + ((lane >> 4) & 1) * 8;
  const int bCol = ((lane >> 3) & 1) * 8;

  for (int ki = 0; ki < KSTEPS; ki++) {
    const int buf = ki & 3;
    cpa_wait<2>();
    __syncthreads();
    if (ki + 3 < KSTEPS) LOAD_STAGE((ki + 3) & 3, ki + 3);
    cpa_commit();

    const uint32_t aB = sm + SM_AH + buf * STAGE_A_B;
    const uint32_t alB = sm + SM_AL + buf * STAGE_A_B;
    const uint32_t bB = sm + SM_BH + buf * STAGE_B_B;
    const uint32_t blB = sm + SM_BL + buf * STAGE_B_B;

    uint32_t ah[2][4], al[2][4], bh[6][2], bl[6][2];
#pragma unroll
    for (int ti = 0; ti < 2; ti++) {
      uint32_t off = (uint32_t)(((wm0 + ti * 16 + aRow) * ST + aCol) * 2);
      ldsm4(ah[ti], aB + off);
      ldsm4(al[ti], alB + off);
    }
#pragma unroll
    for (int p = 0; p < 3; p++) {
      uint32_t off = (uint32_t)(((wn0 + p * 16 + bRow) * ST + bCol) * 2);
      uint32_t t[4];
      ldsm4(t, bB + off);
      bh[2 * p][0] = t[0]; bh[2 * p][1] = t[1];
      bh[2 * p + 1][0] = t[2]; bh[2 * p + 1][1] = t[3];
      ldsm4(t, blB + off);
      bl[2 * p][0] = t[0]; bl[2 * p][1] = t[1];
      bl[2 * p + 1][0] = t[2]; bl[2 * p + 1][1] = t[3];
    }
#pragma unroll
    for (int ti = 0; ti < 2; ti++)
#pragma unroll
      for (int nj = 0; nj < 6; nj++) {
        mma_bf16(acc[ti][nj], ah[ti], bh[nj]);
        mma_bf16(acc[ti][nj], ah[ti], bl[nj]);
        mma_bf16(acc[ti][nj], al[ti], bh[nj]);
      }
  }
#undef LOAD_STAGE

  const int g = lane >> 2, tq = lane & 3;
#pragma unroll
  for (int ti = 0; ti < 2; ti++) {
    int m = m0 + wm0 + ti * 16 + g;
#pragma unroll
    for (int nj = 0; nj < 6; nj++) {
      int n = n0 + wn0 + nj * 8 + tq * 2;
      int seg = n / NSEG, nr = n - seg * NSEG;
      if (nr >= nwrite) continue;
      int col = seg * segstride + nr;
      float b0 = bias[n], b1 = bias[n + 1];
#pragma unroll
      for (int half = 0; half < 2; half++) {
        int mm = m + half * 8;
        if (mm >= M) continue;
        float v0 = acc[ti][nj][2 * half] + b0;
        float v1 = acc[ti][nj][2 * half + 1] + b1;
        if (out) {
          *(float2*)(out + (size_t)mm * ldout + col) = make_float2(v0, v1);
        } else {
          __nv_bfloat16 h0, l0, h1, l1;
          bf16split(v0, h0, l0);
          bf16split(v1, h1, l1);
          *(__nv_bfloat162*)(ohi + (size_t)mm * KP + col) = __nv_bfloat162(h0, h1);
          *(__nv_bfloat162*)(olo + (size_t)mm * KP + col) = __nv_bfloat162(l0, l1);
        }
      }
    }
  }
}

// ---------------- attention (per sample) ----------------
template <int LAYER>
__global__ __launch_bounds__(256) void attn_kernel(const int* __restrict__ neighbors, int B) {
  __shared__ float q[E_];
  __shared__ __align__(16) float kk[KNB][E_];
  __shared__ float sc[HH][KNB];
  __shared__ float at[HH][KNB];
  __shared__ const float* akp[KNB];
  __shared__ const float* bkp[KNB];
  __shared__ int pad[KNB];

  const int b = blockIdx.x;
  const int tid = threadIdx.x;
  const float* trow = g_tqkv + (size_t)b * 576;

  if (tid < KNB) {
    int nb = neighbors[b * KNB + tid];
    pad[tid] = (nb == 0) ? 1 : 0;
    const float* ap = g_node_kv + (size_t)nb * 384;
    if (LAYER == 1) {
      int ow = g_owner[nb];
      if (ow >= 0) ap = g_upd_kv + (size_t)ow * 384;
    }
    akp[tid] = ap;
    bkp[tid] = g_edge_kv + (size_t)g_map[b * KNB + tid] * 384;
  }
  if (tid < E_) q[tid] = g_qh[(size_t)b * KP + tid] + trow[tid];
  __syncthreads();

  // compose k = node_k + edge_k + t_k  (float4 vectorized: 20*43 chunks)
  const float* tk = trow + NSEG;
  for (int idx = tid; idx < KNB * 43; idx += 256) {
    int j = idx / 43, c4 = idx - j * 43;
    float4 a = *(const float4*)(akp[j] + c4 * 4);
    float4 e = *(const float4*)(bkp[j] + c4 * 4);
    float4 t = *(const float4*)(tk + c4 * 4);
    *(float4*)(&kk[j][c4 * 4]) =
        make_float4(a.x + e.x + t.x, a.y + e.y + t.y, a.z + e.z + t.z, a.w + e.w + t.w);
  }
  if (tid == 0) {
    int all = 1;
#pragma unroll
    for (int j = 0; j < KNB; j++) all &= pad[j];
    if (all) pad[0] = 0;
  }
  __syncthreads();

  if (tid < HH * KNB) {
    int h = tid / KNB, j = tid - h * KNB;
    const float* qp = q + h * HD_;
    const float* kp = &kk[j][h * HD_];
    float sum = 0.f;
#pragma unroll
    for (int d = 0; d < HD_; d++) sum += qp[d] * kp[d];
    sum *= 0.10783277320343841f;
    if (pad[j]) sum = -1e9f;
    sc[h][j] = sum;
  }
  __syncthreads();

  if (tid < HH) {
    float m = -INFINITY;
#pragma unroll
    for (int j = 0; j < KNB; j++) m = fmaxf(m, sc[tid][j]);
    float ex[KNB], ssum = 0.f;
#pragma unroll
    for (int j = 0; j < KNB; j++) { ex[j] = expf(sc[tid][j] - m); ssum += ex[j]; }
    float inv = 1.f / ssum;
#pragma unroll
    for (int j = 0; j < KNB; j++) at[tid][j] = ex[j] * inv;
  }
  __syncthreads();

  if (tid < E_) {
    int h = tid / HD_;
    float o = trow[2 * NSEG + tid];
#pragma unroll
    for (int j = 0; j < KNB; j++)
      o += at[h][j] * (akp[j][NSEG + tid] + bkp[j][NSEG + tid]);
    __nv_bfloat16 hh, ll;
    bf16split(o, hh, ll);
    g_Ahi[(size_t)b * KP + tid] = hh;
    g_Alo[(size_t)b * KP + tid] = ll;
  }
}

// ---------------- launch ----------------
static inline int cdiv(int a, int b) { return (a + b - 1) / b; }

extern "C" void kernel_launch(void* const* d_in, const int* in_sizes, int n_in,
                              void* d_out, int out_size) {
  const int* nodes     = (const int*)d_in[0];
  const float* ts      = (const float*)d_in[1];
  const int* neighbors = (const int*)d_in[2];
  const int* eidx      = (const int*)d_in[3];
  const float* nf      = (const float*)d_in[4];
  const float* ef      = (const float*)d_in[5];
  const float* time_w  = (const float*)d_in[6];
  const float* time_b  = (const float*)d_in[7];
  const float* q_w     = (const float*)d_in[8];
  const float* k_w     = (const float*)d_in[9];
  const float* v_w     = (const float*)d_in[10];
  const float* bq      = (const float*)d_in[11];
  const float* bk      = (const float*)d_in[12];
  const float* bv      = (const float*)d_in[13];
  const float* out_w   = (const float*)d_in[14];
  const float* out_b   = (const float*)d_in[15];
  float* out = (float*)d_out;
  const int B = in_sizes[0];

  __nv_bfloat16 *pWhi, *pWlo, *pAhi, *pAlo, *pH1hi, *pH1lo;
  float *pWb, *ptqkv, *pnodekv, *pedgekv, *pupdkv, *pqh;
  int *pht, *pcnt;
  cudaGetSymbolAddress((void**)&pWhi, g_Whi);
  cudaGetSymbolAddress((void**)&pWlo, g_Wlo);
  cudaGetSymbolAddress((void**)&pWb, g_Wb);
  cudaGetSymbolAddress((void**)&pAhi, g_Ahi);
  cudaGetSymbolAddress((void**)&pAlo, g_Alo);
  cudaGetSymbolAddress((void**)&pH1hi, g_H1hi);
  cudaGetSymbolAddress((void**)&pH1lo, g_H1lo);
  cudaGetSymbolAddress((void**)&ptqkv, g_tqkv);
  cudaGetSymbolAddress((void**)&pnodekv, g_node_kv);
  cudaGetSymbolAddress((void**)&pedgekv, g_edge_kv);
  cudaGetSymbolAddress((void**)&pupdkv, g_upd_kv);
  cudaGetSymbolAddress((void**)&pqh, g_qh);
  cudaGetSymbolAddress((void**)&pht, g_ht);
  cudaGetSymbolAddress((void**)&pcnt, g_cnt);

  cudaFuncSetAttribute(mma_gemm_kernel, cudaFuncAttributeMaxDynamicSharedMemorySize, SMEM_G);

  PArgs p;

#define GEMMF(Mpad, Npad, poff, outp, M, ldo, segs, nw, Mptr)                 \
  mma_gemm_kernel<<<dim3((Npad) / BN, (Mpad) / BM), 256, SMEM_G>>>(           \
      pAhi, pAlo, pWhi + (size_t)(poff) * KP, pWlo + (size_t)(poff) * KP,     \
      pWb + (poff), outp, nullptr, nullptr, M, ldo, segs, nw, Mptr)
#define GEMMB(Mpad, Npad, poff, M)                                            \
  mma_gemm_kernel<<<dim3((Npad) / BN, (Mpad) / BM), 256, SMEM_G>>>(           \
      pAhi, pAlo, pWhi + (size_t)(poff) * KP, pWlo + (size_t)(poff) * KP,     \
      pWb + (poff), nullptr, pH1hi, pH1lo, M, KP, 0, KP, nullptr)

  // ---- edge dedup ----
  cudaMemsetAsync(pht, 0xFF, (size_t)HTSZ * sizeof(int));
  cudaMemsetAsync(pcnt, 0, sizeof(int));
  dedup1_kernel<<<cdiv(B * KNB, 256), 256>>>(eidx, B * KNB);
  dedup2_kernel<<<cdiv(HTSZ, 256), 256>>>();

  // pack edge weights (P3), convert unique edges, edge GEMM
  p.w[0] = k_w; p.ld[0] = 2 * E_; p.coff[0] = E_; p.bias[0] = nullptr;
  p.w[1] = v_w; p.ld[1] = 2 * E_; p.coff[1] = E_; p.bias[1] = nullptr;
  p.w[2] = nullptr; p.ld[2] = 0; p.coff[2] = 0; p.bias[2] = nullptr;
  pack_w_kernel<<<cdiv(2 * NSEG * KP, 256), 256>>>(p, 2, pWhi + (size_t)P3_OFF * KP, pWlo + (size_t)P3_OFF * KP, pWb + P3_OFF);
  convert_uedges_kernel<<<cdiv(NSLOT * C4, 256), 256>>>(ef);
  GEMMF(NSLOT, 384, P3_OFF, pedgekv, B * KNB, 384, NSEG, NSEG, pcnt);
  dedup3_kernel<<<cdiv(B * KNB, 256), 256>>>(eidx, B * KNB);

  init_owner_kernel<<<cdiv(NNODES, 256), 256>>>();

  // pack P1, P2
  p.w[0] = q_w; p.ld[0] = E_;     p.coff[0] = 0; p.bias[0] = bq;
  p.w[1] = k_w; p.ld[1] = 2 * E_; p.coff[1] = 0; p.bias[1] = bk;
  p.w[2] = v_w; p.ld[2] = 2 * E_; p.coff[2] = 0; p.bias[2] = bv;
  pack_w_kernel<<<cdiv(3 * NSEG * KP, 256), 256>>>(p, 3, pWhi + (size_t)P1_OFF * KP, pWlo + (size_t)P1_OFF * KP, pWb + P1_OFF);
  p.w[0] = k_w; p.ld[0] = 2 * E_; p.coff[0] = 0; p.bias[0] = nullptr;
  p.w[1] = v_w; p.ld[1] = 2 * E_; p.coff[1] = 0; p.bias[1] = nullptr;
  p.w[2] = nullptr;
  pack_w_kernel<<<cdiv(2 * NSEG * KP, 256), 256>>>(p, 2, pWhi + (size_t)P2_OFF * KP, pWlo + (size_t)P2_OFF * KP, pWb + P2_OFF);

  // tqkv
  timeconv_kernel<<<cdiv(BPAD * C4, 256), 256>>>(ts, time_w, time_b, B, BPAD);
  GEMMF(BPAD, 576, P1_OFF, ptqkv, B, 576, NSEG, NSEG, nullptr);
  // node kv
  convert_kernel<<<cdiv(NPADN * C4, 256), 256>>>(nf, E_, nullptr, 0, NNODES, NPADN);
  GEMMF(NPADN, 384, P2_OFF, pnodekv, NNODES, 384, NSEG, NSEG, nullptr);
  // pack P4, P5
  p.w[0] = q_w; p.ld[0] = E_; p.coff[0] = 0; p.bias[0] = nullptr;
  p.w[1] = nullptr; p.w[2] = nullptr;
  pack_w_kernel<<<cdiv(NSEG * KP, 256), 256>>>(p, 1, pWhi + (size_t)P4_OFF * KP, pWlo + (size_t)P4_OFF * KP, pWb + P4_OFF);
  p.w[0] = out_w; p.bias[0] = out_b;
  pack_w_kernel<<<cdiv(NSEG * KP, 256), 256>>>(p, 1, pWhi + (size_t)P5_OFF * KP, pWlo + (size_t)P5_OFF * KP, pWb + P5_OFF);

  // ---- layer 0 ----
  convert_kernel<<<cdiv(BPAD * C4, 256), 256>>>(nf, E_, nodes, 1, B, BPAD);
  GEMMF(BPAD, NSEG, P4_OFF, pqh, B, KP, 0, KP, nullptr);
  attn_kernel<0><<<B, 256>>>(neighbors, B);
  GEMMB(BPAD, NSEG, P5_OFF, B);
  build_owner_kernel<<<cdiv(B, 256), 256>>>(nodes, B);

  // ---- layer 1 ----
  mma_gemm_kernel<<<dim3(384 / BN, BPAD / BM), 256, SMEM_G>>>(
      pH1hi, pH1lo, pWhi + (size_t)P2_OFF * KP, pWlo + (size_t)P2_OFF * KP,
      pWb + P2_OFF, pupdkv, nullptr, nullptr, B, 384, NSEG, NSEG, nullptr);
  gather_h1_kernel<<<cdiv(BPAD * (KP * 2 / 16), 256), 256>>>(nodes, B, BPAD);
  GEMMF(BPAD, NSEG, P4_OFF, pqh, B, KP, 0, KP, nullptr);
  attn_kernel<1><<<B, 256>>>(neighbors, B);
  GEMMF(BPAD, NSEG, P5_OFF, out, B, E_, 0, E_, nullptr);
#undef GEMMF
#undef GEMMB
}

// round 10
// speedup vs baseline: 1.8424x; 1.0199x over previous
#include <cuda_runtime.h>
#include <cuda_bf16.h>
#include <math.h>
#include <stdint.h>

#define E_ 172
#define KP 176            // padded K (11 k16 steps)
#define KSTEPS 11
#define C4 (KP / 4)       // 44 float4 chunks per row (chunk 43 = zeros)
#define NSEG 192
#define KNB 20
#define HH 2
#define HD_ 86
#define NNODES 100000
#define BMAX 12000
#define BPAD 12032
#define NPADN 100096
#define NSLOT 240000
#define HTSZ (1 << 19)

// disjoint A-buffer row regions (for cross-stream overlap)
#define R_EDGE 0
#define R_TIME 240000
#define R_NODE 252032                 // R_TIME + BPAD
#define R_Q0   352128                 // R_NODE + NPADN
#define R_O    364160                 // R_Q0 + BPAD
#define AROWS  376192                 // R_O + BPAD

#define P1_OFF 0
#define P2_OFF 576
#define P3_OFF 960
#define P4_OFF 1344
#define P5_OFF 1536
#define PTOT 1728

// ---------------- scratch ----------------
__device__ __nv_bfloat16 g_Ahi[(size_t)AROWS * KP];
__device__ __nv_bfloat16 g_Alo[(size_t)AROWS * KP];
__device__ __nv_bfloat16 g_Whi[(size_t)PTOT * KP];
__device__ __nv_bfloat16 g_Wlo[(size_t)PTOT * KP];
__device__ float g_Wb[PTOT];

__device__ float g_tqkv[BMAX * 576];
__device__ float g_node_kv[(size_t)NNODES * 384];
__device__ float g_edge_kv[(size_t)NSLOT * 384];
__device__ float g_upd_kv[BMAX * 384];
__device__ float g_qh[BMAX * KP];
__device__ __nv_bfloat16 g_H1hi[BPAD * KP];
__device__ __nv_bfloat16 g_H1lo[BPAD * KP];
__device__ int g_owner[NNODES];

__device__ int g_ht[HTSZ];
__device__ int g_uidtab[HTSZ];
__device__ int g_uelist[NSLOT];
__device__ int g_map[NSLOT];
__device__ int g_cnt;

// ---------------- helpers ----------------
__device__ __forceinline__ void cpa16(uint32_t dst, const void* src) {
  asm volatile("cp.async.cg.shared.global [%0], [%1], 16;" :: "r"(dst), "l"(src));
}
__device__ __forceinline__ void cpa_commit() { asm volatile("cp.async.commit_group;" ::: "memory"); }
template <int N>
__device__ __forceinline__ void cpa_wait() { asm volatile("cp.async.wait_group %0;" :: "n"(N) : "memory"); }

__device__ __forceinline__ void ldsm4(uint32_t* r, uint32_t addr) {
  asm volatile("ldmatrix.sync.aligned.m8n8.x4.shared.b16 {%0,%1,%2,%3}, [%4];"
               : "=r"(r[0]), "=r"(r[1]), "=r"(r[2]), "=r"(r[3]) : "r"(addr));
}
__device__ __forceinline__ void mma_bf16(float* d, const uint32_t* a, const uint32_t* b) {
  asm volatile(
      "mma.sync.aligned.m16n8k16.row.col.f32.bf16.bf16.f32 "
      "{%0,%1,%2,%3},{%4,%5,%6,%7},{%8,%9},{%0,%1,%2,%3};"
      : "+f"(d[0]), "+f"(d[1]), "+f"(d[2]), "+f"(d[3])
      : "r"(a[0]), "r"(a[1]), "r"(a[2]), "r"(a[3]), "r"(b[0]), "r"(b[1]));
}

__device__ __forceinline__ void bf16split(float v, __nv_bfloat16& h, __nv_bfloat16& l) {
  h = __float2bfloat16(v);
  l = __float2bfloat16(v - __bfloat162float(h));
}

__device__ __forceinline__ void split_store4(float4 v, __nv_bfloat16* hi,
                                             __nv_bfloat16* lo, size_t off) {
  __nv_bfloat16 h0, l0, h1, l1, h2, l2, h3, l3;
  bf16split(v.x, h0, l0); bf16split(v.y, h1, l1);
  bf16split(v.z, h2, l2); bf16split(v.w, h3, l3);
  __nv_bfloat162 hA(h0, h1), hB(h2, h3), lA(l0, l1), lB(l2, l3);
  ((__nv_bfloat162*)(hi + off))[0] = hA;
  ((__nv_bfloat162*)(hi + off))[1] = hB;
  ((__nv_bfloat162*)(lo + off))[0] = lA;
  ((__nv_bfloat162*)(lo + off))[1] = lB;
}

__device__ __forceinline__ uint32_t ehash(int e) {
  return (((uint32_t)e * 2654435761u) >> 13) & (HTSZ - 1);
}

// ---------------- small kernels ----------------
__global__ void init_owner_kernel() {
  int i = blockIdx.x * blockDim.x + threadIdx.x;
  if (i < NNODES) g_owner[i] = -1;
}
__global__ void build_owner_kernel(const int* __restrict__ nodes, int B) {
  int i = blockIdx.x * blockDim.x + threadIdx.x;
  if (i < B) atomicMax(&g_owner[nodes[i]], i);
}

// ---------------- edge dedup ----------------
__global__ void dedup1_kernel(const int* __restrict__ eidx, int n) {
  int i = blockIdx.x * blockDim.x + threadIdx.x;
  if (i >= n) return;
  int e = eidx[i];
  uint32_t h = ehash(e);
  while (true) {
    int prev = atomicCAS(&g_ht[h], -1, e);
    if (prev == -1 || prev == e) break;
    h = (h + 1) & (HTSZ - 1);
  }
}
__global__ void dedup2_kernel() {
  int i = blockIdx.x * blockDim.x + threadIdx.x;
  if (i >= HTSZ) return;
  int e = g_ht[i];
  if (e != -1) {
    int uid = atomicAdd(&g_cnt, 1);
    g_uidtab[i] = uid;
    g_uelist[uid] = e;
  }
}
__global__ void dedup3_kernel(const int* __restrict__ eidx, int n) {
  int i = blockIdx.x * blockDim.x + threadIdx.x;
  if (i >= n) return;
  int e = eidx[i];
  uint32_t h = ehash(e);
  while (g_ht[h] != e) h = (h + 1) & (HTSZ - 1);
  g_map[i] = g_uidtab[h];
}

// ---------------- weight packing ----------------
struct PArgs {
  const float* w[3];
  int ld[3];
  int coff[3];
  const float* bias[3];
};
__global__ void pack_w_kernel(PArgs a, int nseg, __nv_bfloat16* whi,
                              __nv_bfloat16* wlo, float* pbias) {
  int i = blockIdx.x * blockDim.x + threadIdx.x;
  int tot = nseg * NSEG * KP;
  if (i >= tot) return;
  int n = i / KP, c = i - n * KP;
  int seg = n / NSEG, nr = n - seg * NSEG;
  float v = 0.f;
  if (nr < E_ && c < E_) v = a.w[seg][(size_t)nr * a.ld[seg] + a.coff[seg] + c];
  __nv_bfloat16 h, l;
  bf16split(v, h, l);
  whi[i] = h; wlo[i] = l;
  if (c == 0) pbias[n] = (nr < E_ && a.bias[seg]) ? a.bias[seg][nr] : 0.f;
}

// ---------------- vectorized converts (1 float4 per thread) ----------------
__global__ void convert_kernel(const float* __restrict__ X, int ldx,
                               const int* __restrict__ g1, int gmode,
                               int M, int Mpad, int rowoff) {
  int i = blockIdx.x * blockDim.x + threadIdx.x;
  if (i >= Mpad * C4) return;
  int r = i / C4, c4 = i - r * C4;
  float4 v = make_float4(0.f, 0.f, 0.f, 0.f);
  if (r < M && c4 < 43) {
    int src = (gmode >= 1) ? g1[r] : r;
    v = *(const float4*)(X + (size_t)src * ldx + c4 * 4);
  }
  split_store4(v, g_Ahi, g_Alo, (size_t)(rowoff + r) * KP + c4 * 4);
}

__global__ void convert_uedges_kernel(const float* __restrict__ ef) {
  int i = blockIdx.x * blockDim.x + threadIdx.x;
  if (i >= NSLOT * C4) return;
  int r = i / C4, c4 = i - r * C4;
  if (r >= g_cnt) return;
  float4 v = make_float4(0.f, 0.f, 0.f, 0.f);
  if (c4 < 43) v = *(const float4*)(ef + (size_t)g_uelist[r] * E_ + c4 * 4);
  split_store4(v, g_Ahi, g_Alo, (size_t)(R_EDGE + r) * KP + c4 * 4);
}

__global__ void timeconv_kernel(const float* __restrict__ ts,
                                const float* __restrict__ tw,
                                const float* __restrict__ tb, int B, int Mpad) {
  int i = blockIdx.x * blockDim.x + threadIdx.x;
  if (i >= Mpad * C4) return;
  int r = i / C4, c4 = i - r * C4;
  float4 v = make_float4(0.f, 0.f, 0.f, 0.f);
  if (r < B && c4 < 43) {
    float tval = ts[r];
    float4 w = *(const float4*)(tw + c4 * 4);
    float4 b = *(const float4*)(tb + c4 * 4);
    v.x = (float)cos((double)__fadd_rn(__fmul_rn(tval, w.x), b.x));
    v.y = (float)cos((double)__fadd_rn(__fmul_rn(tval, w.y), b.y));
    v.z = (float)cos((double)__fadd_rn(__fmul_rn(tval, w.z), b.z));
    v.w = (float)cos((double)__fadd_rn(__fmul_rn(tval, w.w), b.w));
  }
  split_store4(v, g_Ahi, g_Alo, (size_t)(R_TIME + r) * KP + c4 * 4);
}

// gather h1 rows (bf16 split, int4 copy) into R_Q0
__global__ void gather_h1_kernel(const int* __restrict__ nodes, int B, int Mpad) {
  int i = blockIdx.x * blockDim.x + threadIdx.x;
  const int CH = KP * 2 / 16;  // 22
  if (i >= Mpad * CH) return;
  int r = i / CH, w = i - r * CH;
  int4 v1 = make_int4(0, 0, 0, 0), v2 = v1;
  if (r < B) {
    int src = g_owner[nodes[r]];
    v1 = *(const int4*)((const char*)(g_H1hi + (size_t)src * KP) + w * 16);
    v2 = *(const int4*)((const char*)(g_H1lo + (size_t)src * KP) + w * 16);
  }
  *(int4*)((char*)(g_Ahi + (size_t)(R_Q0 + r) * KP) + w * 16) = v1;
  *(int4*)((char*)(g_Alo + (size_t)(R_Q0 + r) * KP) + w * 16) = v2;
}

// ---------------- pipelined bf16 HMMA GEMM ----------------
#define BM 128
#define BN 96
#define ST 24
#define STAGE_A_B (BM * ST * 2)
#define STAGE_B_B (BN * ST * 2)
#define SM_AH 0
#define SM_AL (SM_AH + 4 * STAGE_A_B)
#define SM_BH (SM_AL + 4 * STAGE_A_B)
#define SM_BL (SM_BH + 4 * STAGE_B_B)
#define SMEM_G (SM_BL + 4 * STAGE_B_B)

__global__ __launch_bounds__(256, 2) void mma_gemm_kernel(
    const __nv_bfloat16* __restrict__ Ahi, const __nv_bfloat16* __restrict__ Alo,
    const __nv_bfloat16* __restrict__ Whi, const __nv_bfloat16* __restrict__ Wlo,
    const float* __restrict__ bias, float* __restrict__ out,
    __nv_bfloat16* __restrict__ ohi, __nv_bfloat16* __restrict__ olo,
    int M, int ldout, int segstride, int nwrite, const int* __restrict__ Mptr) {
  if (Mptr) {
    M = *Mptr;
    if ((int)(blockIdx.y * BM) >= M) return;
  }
  extern __shared__ __align__(128) char smraw[];
  const uint32_t sm = (uint32_t)__cvta_generic_to_shared(smraw);
  const int tid = threadIdx.x;
  const int warp = tid >> 5, lane = tid & 31;
  const int m0 = blockIdx.y * BM;
  const int n0 = blockIdx.x * BN;
  const int wm0 = (warp >> 1) * 32;
  const int wn0 = (warp & 1) * 48;

  float acc[2][6][4];
#pragma unroll
  for (int i = 0; i < 2; i++)
#pragma unroll
    for (int j = 0; j < 6; j++)
#pragma unroll
      for (int k = 0; k < 4; k++) acc[i][j][k] = 0.f;

  const int lr = tid >> 1, lch = tid & 1;
  const size_t srcA = (size_t)(m0 + lr) * KP + lch * 8;
  const size_t srcB = (size_t)(n0 + lr) * KP + lch * 8;
  const uint32_t dstAoff = (uint32_t)((lr * ST + lch * 8) * 2);
  const uint32_t dstBoff = dstAoff;

#define LOAD_STAGE(buf, ki)                                                   \
  do {                                                                        \
    cpa16(sm + SM_AH + (buf) * STAGE_A_B + dstAoff, Ahi + srcA + (ki) * 16);  \
    cpa16(sm + SM_AL + (buf) * STAGE_A_B + dstAoff, Alo + srcA + (ki) * 16);  \
    if (tid < 2 * BN) {                                                       \
      cpa16(sm + SM_BH + (buf) * STAGE_B_B + dstBoff, Whi + srcB + (ki) * 16);\
      cpa16(sm + SM_BL + (buf) * STAGE_B_B + dstBoff, Wlo + srcB + (ki) * 16);\
    }                                                                         \
  } while (0)

  LOAD_STAGE(0, 0); cpa_commit();
  LOAD_STAGE(1, 1); cpa_commit();
  LOAD_STAGE(2, 2); cpa_commit();

  const int aRow = (lane & 7) + ((lane >> 3) & 1) * 8;
  const int aCol = ((lane >> 4) & 1) * 8;
  const int bRow = (lane & 7) + ((lane >> 4) & 1) * 8;
  const int bCol = ((lane >> 3) & 1) * 8;

  for (int ki = 0; ki < KSTEPS; ki++) {
    const int buf = ki & 3;
    cpa_wait<2>();
    __syncthreads();
    if (ki + 3 < KSTEPS) LOAD_STAGE((ki + 3) & 3, ki + 3);
    cpa_commit();

    const uint32_t aB = sm + SM_AH + buf * STAGE_A_B;
    const uint32_t alB = sm + SM_AL + buf * STAGE_A_B;
    const uint32_t bB = sm + SM_BH + buf * STAGE_B_B;
    const uint32_t blB = sm + SM_BL + buf * STAGE_B_B;

    uint32_t ah[2][4], al[2][4], bh[6][2], bl[6][2];
#pragma unroll
    for (int ti = 0; ti < 2; ti++) {
      uint32_t off = (uint32_t)(((wm0 + ti * 16 + aRow) * ST + aCol) * 2);
      ldsm4(ah[ti], aB + off);
      ldsm4(al[ti], alB + off);
    }
#pragma unroll
    for (int p = 0; p < 3; p++) {
      uint32_t off = (uint32_t)(((wn0 + p * 16 + bRow) * ST + bCol) * 2);
      uint32_t t[4];
      ldsm4(t, bB + off);
      bh[2 * p][0] = t[0]; bh[2 * p][1] = t[1];
      bh[2 * p + 1][0] = t[2]; bh[2 * p + 1][1] = t[3];
      ldsm4(t, blB + off);
      bl[2 * p][0] = t[0]; bl[2 * p][1] = t[1];
      bl[2 * p + 1][0] = t[2]; bl[2 * p + 1][1] = t[3];
    }
#pragma unroll
    for (int ti = 0; ti < 2; ti++)
#pragma unroll
      for (int nj = 0; nj < 6; nj++) {
        mma_bf16(acc[ti][nj], ah[ti], bh[nj]);
        mma_bf16(acc[ti][nj], ah[ti], bl[nj]);
        mma_bf16(acc[ti][nj], al[ti], bh[nj]);
      }
  }
#undef LOAD_STAGE

  const int g = lane >> 2, tq = lane & 3;
#pragma unroll
  for (int ti = 0; ti < 2; ti++) {
    int m = m0 + wm0 + ti * 16 + g;
#pragma unroll
    for (int nj = 0; nj < 6; nj++) {
      int n = n0 + wn0 + nj * 8 + tq * 2;
      int seg = n / NSEG, nr = n - seg * NSEG;
      if (nr >= nwrite) continue;
      int col = seg * segstride + nr;
      float b0 = bias[n], b1 = bias[n + 1];
#pragma unroll
      for (int half = 0; half < 2; half++) {
        int mm = m + half * 8;
        if (mm >= M) continue;
        float v0 = acc[ti][nj][2 * half] + b0;
        float v1 = acc[ti][nj][2 * half + 1] + b1;
        if (out) {
          *(float2*)(out + (size_t)mm * ldout + col) = make_float2(v0, v1);
        } else {
          __nv_bfloat16 h0, l0, h1, l1;
          bf16split(v0, h0, l0);
          bf16split(v1, h1, l1);
          *(__nv_bfloat162*)(ohi + (size_t)mm * KP + col) = __nv_bfloat162(h0, h1);
          *(__nv_bfloat162*)(olo + (size_t)mm * KP + col) = __nv_bfloat162(l0, l1);
        }
      }
    }
  }
}

// ---------------- attention (per sample), writes bf16 split to R_O ----------------
template <int LAYER>
__global__ __launch_bounds__(256) void attn_kernel(const int* __restrict__ neighbors, int B) {
  __shared__ float q[E_];
  __shared__ __align__(16) float kk[KNB][E_];
  __shared__ float sc[HH][KNB];
  __shared__ float at[HH][KNB];
  __shared__ const float* akp[KNB];
  __shared__ const float* bkp[KNB];
  __shared__ int pad[KNB];

  const int b = blockIdx.x;
  const int tid = threadIdx.x;
  const float* trow = g_tqkv + (size_t)b * 576;

  if (tid < KNB) {
    int nb = neighbors[b * KNB + tid];
    pad[tid] = (nb == 0) ? 1 : 0;
    const float* ap = g_node_kv + (size_t)nb * 384;
    if (LAYER == 1) {
      int ow = g_owner[nb];
      if (ow >= 0) ap = g_upd_kv + (size_t)ow * 384;
    }
    akp[tid] = ap;
    bkp[tid] = g_edge_kv + (size_t)g_map[b * KNB + tid] * 384;
  }
  if (tid < E_) q[tid] = g_qh[(size_t)b * KP + tid] + trow[tid];
  __syncthreads();

  const float* tk = trow + NSEG;
  for (int idx = tid; idx < KNB * 43; idx += 256) {
    int j = idx / 43, c4 = idx - j * 43;
    float4 a = *(const float4*)(akp[j] + c4 * 4);
    float4 e = *(const float4*)(bkp[j] + c4 * 4);
    float4 t = *(const float4*)(tk + c4 * 4);
    *(float4*)(&kk[j][c4 * 4]) =
        make_float4(a.x + e.x + t.x, a.y + e.y + t.y, a.z + e.z + t.z, a.w + e.w + t.w);
  }
  if (tid == 0) {
    int all = 1;
#pragma unroll
    for (int j = 0; j < KNB; j++) all &= pad[j];
    if (all) pad[0] = 0;
  }
  __syncthreads();

  if (tid < HH * KNB) {
    int h = tid / KNB, j = tid - h * KNB;
    const float* qp = q + h * HD_;
    const float* kp = &kk[j][h * HD_];
    float sum = 0.f;
#pragma unroll
    for (int d = 0; d < HD_; d++) sum += qp[d] * kp[d];
    sum *= 0.10783277320343841f;
    if (pad[j]) sum = -1e9f;
    sc[h][j] = sum;
  }
  __syncthreads();

  if (tid < HH) {
    float m = -INFINITY;
#pragma unroll
    for (int j = 0; j < KNB; j++) m = fmaxf(m, sc[tid][j]);
    float ex[KNB], ssum = 0.f;
#pragma unroll
    for (int j = 0; j < KNB; j++) { ex[j] = expf(sc[tid][j] - m); ssum += ex[j]; }
    float inv = 1.f / ssum;
#pragma unroll
    for (int j = 0; j < KNB; j++) at[tid][j] = ex[j] * inv;
  }
  __syncthreads();

  if (tid < E_) {
    int h = tid / HD_;
    float o = trow[2 * NSEG + tid];
#pragma unroll
    for (int j = 0; j < KNB; j++)
      o += at[h][j] * (akp[j][NSEG + tid] + bkp[j][NSEG + tid]);
    __nv_bfloat16 hh, ll;
    bf16split(o, hh, ll);
    g_Ahi[(size_t)(R_O + b) * KP + tid] = hh;
    g_Alo[(size_t)(R_O + b) * KP + tid] = ll;
  }
}

// ---------------- launch ----------------
static inline int cdiv(int a, int b) { return (a + b - 1) / b; }

extern "C" void kernel_launch(void* const* d_in, const int* in_sizes, int n_in,
                              void* d_out, int out_size) {
  const int* nodes     = (const int*)d_in[0];
  const float* ts      = (const float*)d_in[1];
  const int* neighbors = (const int*)d_in[2];
  const int* eidx      = (const int*)d_in[3];
  const float* nf      = (const float*)d_in[4];
  const float* ef      = (const float*)d_in[5];
  const float* time_w  = (const float*)d_in[6];
  const float* time_b  = (const float*)d_in[7];
  const float* q_w     = (const float*)d_in[8];
  const float* k_w     = (const float*)d_in[9];
  const float* v_w     = (const float*)d_in[10];
  const float* bq      = (const float*)d_in[11];
  const float* bk      = (const float*)d_in[12];
  const float* bv      = (const float*)d_in[13];
  const float* out_w   = (const float*)d_in[14];
  const float* out_b   = (const float*)d_in[15];
  float* out = (float*)d_out;
  const int B = in_sizes[0];

  __nv_bfloat16 *pWhi, *pWlo, *pAhi, *pAlo, *pH1hi, *pH1lo;
  float *pWb, *ptqkv, *pnodekv, *pedgekv, *pupdkv, *pqh;
  int *pht, *pcnt;
  cudaGetSymbolAddress((void**)&pWhi, g_Whi);
  cudaGetSymbolAddress((void**)&pWlo, g_Wlo);
  cudaGetSymbolAddress((void**)&pWb, g_Wb);
  cudaGetSymbolAddress((void**)&pAhi, g_Ahi);
  cudaGetSymbolAddress((void**)&pAlo, g_Alo);
  cudaGetSymbolAddress((void**)&pH1hi, g_H1hi);
  cudaGetSymbolAddress((void**)&pH1lo, g_H1lo);
  cudaGetSymbolAddress((void**)&ptqkv, g_tqkv);
  cudaGetSymbolAddress((void**)&pnodekv, g_node_kv);
  cudaGetSymbolAddress((void**)&pedgekv, g_edge_kv);
  cudaGetSymbolAddress((void**)&pupdkv, g_upd_kv);
  cudaGetSymbolAddress((void**)&pqh, g_qh);
  cudaGetSymbolAddress((void**)&pht, g_ht);
  cudaGetSymbolAddress((void**)&pcnt, g_cnt);

  cudaFuncSetAttribute(mma_gemm_kernel, cudaFuncAttributeMaxDynamicSharedMemorySize, SMEM_G);

  // persistent side-stream + capture-dependency events (host resources only;
  // identical GPU work is enqueued on every call)
  static cudaStream_t s1 = nullptr;
  static cudaEvent_t evF = nullptr, ev1, ev2, ev3, ev4;
  if (!s1) {
    cudaStreamCreateWithFlags(&s1, cudaStreamNonBlocking);
    cudaEventCreateWithFlags(&evF, cudaEventDisableTiming);
    cudaEventCreateWithFlags(&ev1, cudaEventDisableTiming);
    cudaEventCreateWithFlags(&ev2, cudaEventDisableTiming);
    cudaEventCreateWithFlags(&ev3, cudaEventDisableTiming);
    cudaEventCreateWithFlags(&ev4, cudaEventDisableTiming);
  }
  cudaStream_t s0 = 0;

  PArgs p;

#define GEMMF(Mpad, Npad, poff, Aoff, outp, M, ldo, segs, nw, Mptr)           \
  mma_gemm_kernel<<<dim3((Npad) / BN, (Mpad) / BM), 256, SMEM_G, s0>>>(       \
      pAhi + (size_t)(Aoff) * KP, pAlo + (size_t)(Aoff) * KP,                 \
      pWhi + (size_t)(poff) * KP, pWlo + (size_t)(poff) * KP,                 \
      pWb + (poff), outp, nullptr, nullptr, M, ldo, segs, nw, Mptr)
#define GEMMB(Mpad, Npad, poff, Aoff, M)                                      \
  mma_gemm_kernel<<<dim3((Npad) / BN, (Mpad) / BM), 256, SMEM_G, s0>>>(       \
      pAhi + (size_t)(Aoff) * KP, pAlo + (size_t)(Aoff) * KP,                 \
      pWhi + (size_t)(poff) * KP, pWlo + (size_t)(poff) * KP,                 \
      pWb + (poff), nullptr, pH1hi, pH1lo, M, KP, 0, KP, nullptr)

  // fork s1 from the capture stream
  cudaEventRecord(evF, s0);
  cudaStreamWaitEvent(s1, evF, 0);

  // ---- s1: all prep work ----
  // group 1: edge dedup + edge weights + edge convert
  cudaMemsetAsync(pht, 0xFF, (size_t)HTSZ * sizeof(int), s1);
  cudaMemsetAsync(pcnt, 0, sizeof(int), s1);
  dedup1_kernel<<<cdiv(B * KNB, 256), 256, 0, s1>>>(eidx, B * KNB);
  dedup2_kernel<<<cdiv(HTSZ, 256), 256, 0, s1>>>();
  p.w[0] = k_w; p.ld[0] = 2 * E_; p.coff[0] = E_; p.bias[0] = nullptr;
  p.w[1] = v_w; p.ld[1] = 2 * E_; p.coff[1] = E_; p.bias[1] = nullptr;
  p.w[2] = nullptr; p.ld[2] = 0; p.coff[2] = 0; p.bias[2] = nullptr;
  pack_w_kernel<<<cdiv(2 * NSEG * KP, 256), 256, 0, s1>>>(p, 2, pWhi + (size_t)P3_OFF * KP, pWlo + (size_t)P3_OFF * KP, pWb + P3_OFF);
  convert_uedges_kernel<<<cdiv(NSLOT * C4, 256), 256, 0, s1>>>(ef);
  cudaEventRecord(ev1, s1);
  // group 2: tqkv weights + time convert
  p.w[0] = q_w; p.ld[0] = E_;     p.coff[0] = 0; p.bias[0] = bq;
  p.w[1] = k_w; p.ld[1] = 2 * E_; p.coff[1] = 0; p.bias[1] = bk;
  p.w[2] = v_w; p.ld[2] = 2 * E_; p.coff[2] = 0; p.bias[2] = bv;
  pack_w_kernel<<<cdiv(3 * NSEG * KP, 256), 256, 0, s1>>>(p, 3, pWhi + (size_t)P1_OFF * KP, pWlo + (size_t)P1_OFF * KP, pWb + P1_OFF);
  timeconv_kernel<<<cdiv(BPAD * C4, 256), 256, 0, s1>>>(ts, time_w, time_b, B, BPAD);
  cudaEventRecord(ev2, s1);
  // group 3: node weights + node convert
  p.w[0] = k_w; p.ld[0] = 2 * E_; p.coff[0] = 0; p.bias[0] = nullptr;
  p.w[1] = v_w; p.ld[1] = 2 * E_; p.coff[1] = 0; p.bias[1] = nullptr;
  p.w[2] = nullptr;
  pack_w_kernel<<<cdiv(2 * NSEG * KP, 256), 256, 0, s1>>>(p, 2, pWhi + (size_t)P2_OFF * KP, pWlo + (size_t)P2_OFF * KP, pWb + P2_OFF);
  convert_kernel<<<cdiv(NPADN * C4, 256), 256, 0, s1>>>(nf, E_, nullptr, 0, NNODES, NPADN, R_NODE);
  cudaEventRecord(ev3, s1);
  // group 4: dedup3 map, owner init, q/out weights, L0 q convert
  dedup3_kernel<<<cdiv(B * KNB, 256), 256, 0, s1>>>(eidx, B * KNB);
  init_owner_kernel<<<cdiv(NNODES, 256), 256, 0, s1>>>();
  p.w[0] = q_w; p.ld[0] = E_; p.coff[0] = 0; p.bias[0] = nullptr;
  p.w[1] = nullptr; p.w[2] = nullptr;
  pack_w_kernel<<<cdiv(NSEG * KP, 256), 256, 0, s1>>>(p, 1, pWhi + (size_t)P4_OFF * KP, pWlo + (size_t)P4_OFF * KP, pWb + P4_OFF);
  p.w[0] = out_w; p.bias[0] = out_b;
  pack_w_kernel<<<cdiv(NSEG * KP, 256), 256, 0, s1>>>(p, 1, pWhi + (size_t)P5_OFF * KP, pWlo + (size_t)P5_OFF * KP, pWb + P5_OFF);
  convert_kernel<<<cdiv(BPAD * C4, 256), 256, 0, s1>>>(nf, E_, nodes, 1, B, BPAD, R_Q0);
  cudaEventRecord(ev4, s1);

  // ---- s0: GEMM chain + attention ----
  cudaStreamWaitEvent(s0, ev1, 0);
  GEMMF(NSLOT, 384, P3_OFF, R_EDGE, pedgekv, B * KNB, 384, NSEG, NSEG, pcnt);
  cudaStreamWaitEvent(s0, ev2, 0);
  GEMMF(BPAD, 576, P1_OFF, R_TIME, ptqkv, B, 576, NSEG, NSEG, nullptr);
  cudaStreamWaitEvent(s0, ev3, 0);
  GEMMF(NPADN, 384, P2_OFF, R_NODE, pnodekv, NNODES, 384, NSEG, NSEG, nullptr);
  cudaStreamWaitEvent(s0, ev4, 0);

  // layer 0
  GEMMF(BPAD, NSEG, P4_OFF, R_Q0, pqh, B, KP, 0, KP, nullptr);
  attn_kernel<0><<<B, 256, 0, s0>>>(neighbors, B);
  GEMMB(BPAD, NSEG, P5_OFF, R_O, B);
  build_owner_kernel<<<cdiv(B, 256), 256, 0, s0>>>(nodes, B);

  // layer 1
  mma_gemm_kernel<<<dim3(384 / BN, BPAD / BM), 256, SMEM_G, s0>>>(
      pH1hi, pH1lo, pWhi + (size_t)P2_OFF * KP, pWlo + (size_t)P2_OFF * KP,
      pWb + P2_OFF, pupdkv, nullptr, nullptr, B, 384, NSEG, NSEG, nullptr);
  gather_h1_kernel<<<cdiv(BPAD * (KP * 2 / 16), 256), 256, 0, s0>>>(nodes, B, BPAD);
  GEMMF(BPAD, NSEG, P4_OFF, R_Q0, pqh, B, KP, 0, KP, nullptr);
  attn_kernel<1><<<B, 256, 0, s0>>>(neighbors, B);
  GEMMF(BPAD, NSEG, P5_OFF, R_O, out, B, E_, 0, E_, nullptr);
#undef GEMMF
#undef GEMMB
}

// round 11
// speedup vs baseline: 1.8686x; 1.0143x over previous
#include <cuda_runtime.h>
#include <cuda_bf16.h>
#include <math.h>
#include <stdint.h>

#define E_ 172
#define KP 176            // padded K (11 k16 steps)
#define KSTEPS 11
#define C4 (KP / 4)       // 44 float4 chunks per row (chunk 43 = zeros)
#define NSEG 192
#define KNB 20
#define HH 2
#define HD_ 86
#define NNODES 100000
#define BMAX 12000
#define BPAD 12032
#define NPADN 100096
#define NSLOT 240000
#define HTSZ (1 << 19)

// disjoint A-buffer row regions (for cross-stream overlap)
#define R_EDGE 0
#define R_TIME 240000
#define R_NODE 252032                 // R_TIME + BPAD
#define R_Q0   352128                 // R_NODE + NPADN
#define R_O    364160                 // R_Q0 + BPAD
#define AROWS  376192                 // R_O + BPAD

#define P1_OFF 0
#define P2_OFF 576
#define P3_OFF 960
#define P4_OFF 1344
#define P5_OFF 1536
#define PTOT 1728

// ---------------- scratch ----------------
__device__ __nv_bfloat16 g_Ahi[(size_t)AROWS * KP];
__device__ __nv_bfloat16 g_Alo[(size_t)AROWS * KP];
__device__ __nv_bfloat16 g_Whi[(size_t)PTOT * KP];
__device__ __nv_bfloat16 g_Wlo[(size_t)PTOT * KP];
__device__ float g_Wb[PTOT];
__device__ float g_zbias[576];        // statically zero

__device__ float g_tqkv[BMAX * 576];
__device__ float g_node_kv[(size_t)NNODES * 384];
__device__ float g_edge_kv[(size_t)NSLOT * 384];
__device__ float g_l1out[BMAX * 576]; // layer-1 merged [q|k|v] of H1
__device__ float g_qh[BMAX * KP];
__device__ __nv_bfloat16 g_H1hi[BPAD * KP];
__device__ __nv_bfloat16 g_H1lo[BPAD * KP];
__device__ int g_owner[NNODES];

__device__ int g_ht[HTSZ];
__device__ int g_uidtab[HTSZ];
__device__ int g_uelist[NSLOT];
__device__ int g_map[NSLOT];
__device__ int g_cnt;

// ---------------- helpers ----------------
__device__ __forceinline__ void cpa16(uint32_t dst, const void* src) {
  asm volatile("cp.async.cg.shared.global [%0], [%1], 16;" :: "r"(dst), "l"(src));
}
__device__ __forceinline__ void cpa_commit() { asm volatile("cp.async.commit_group;" ::: "memory"); }
template <int N>
__device__ __forceinline__ void cpa_wait() { asm volatile("cp.async.wait_group %0;" :: "n"(N) : "memory"); }

__device__ __forceinline__ void ldsm4(uint32_t* r, uint32_t addr) {
  asm volatile("ldmatrix.sync.aligned.m8n8.x4.shared.b16 {%0,%1,%2,%3}, [%4];"
               : "=r"(r[0]), "=r"(r[1]), "=r"(r[2]), "=r"(r[3]) : "r"(addr));
}
__device__ __forceinline__ void mma_bf16(float* d, const uint32_t* a, const uint32_t* b) {
  asm volatile(
      "mma.sync.aligned.m16n8k16.row.col.f32.bf16.bf16.f32 "
      "{%0,%1,%2,%3},{%4,%5,%6,%7},{%8,%9},{%0,%1,%2,%3};"
      : "+f"(d[0]), "+f"(d[1]), "+f"(d[2]), "+f"(d[3])
      : "r"(a[0]), "r"(a[1]), "r"(a[2]), "r"(a[3]), "r"(b[0]), "r"(b[1]));
}

__device__ __forceinline__ void bf16split(float v, __nv_bfloat16& h, __nv_bfloat16& l) {
  h = __float2bfloat16(v);
  l = __float2bfloat16(v - __bfloat162float(h));
}

__device__ __forceinline__ void split_store4(float4 v, __nv_bfloat16* hi,
                                             __nv_bfloat16* lo, size_t off) {
  __nv_bfloat16 h0, l0, h1, l1, h2, l2, h3, l3;
  bf16split(v.x, h0, l0); bf16split(v.y, h1, l1);
  bf16split(v.z, h2, l2); bf16split(v.w, h3, l3);
  __nv_bfloat162 hA(h0, h1), hB(h2, h3), lA(l0, l1), lB(l2, l3);
  ((__nv_bfloat162*)(hi + off))[0] = hA;
  ((__nv_bfloat162*)(hi + off))[1] = hB;
  ((__nv_bfloat162*)(lo + off))[0] = lA;
  ((__nv_bfloat162*)(lo + off))[1] = lB;
}

__device__ __forceinline__ uint32_t ehash(int e) {
  return (((uint32_t)e * 2654435761u) >> 13) & (HTSZ - 1);
}

// ---------------- small kernels ----------------
__global__ void init_owner_kernel() {
  int i = blockIdx.x * blockDim.x + threadIdx.x;
  if (i < NNODES) g_owner[i] = -1;
}
__global__ void build_owner_kernel(const int* __restrict__ nodes, int B) {
  int i = blockIdx.x * blockDim.x + threadIdx.x;
  if (i < B) atomicMax(&g_owner[nodes[i]], i);
}

// ---------------- edge dedup ----------------
__global__ void dedup1_kernel(const int* __restrict__ eidx, int n) {
  int i = blockIdx.x * blockDim.x + threadIdx.x;
  if (i >= n) return;
  int e = eidx[i];
  uint32_t h = ehash(e);
  while (true) {
    int prev = atomicCAS(&g_ht[h], -1, e);
    if (prev == -1 || prev == e) break;
    h = (h + 1) & (HTSZ - 1);
  }
}
__global__ void dedup2_kernel() {
  int i = blockIdx.x * blockDim.x + threadIdx.x;
  if (i >= HTSZ) return;
  int e = g_ht[i];
  if (e != -1) {
    int uid = atomicAdd(&g_cnt, 1);
    g_uidtab[i] = uid;
    g_uelist[uid] = e;
  }
}
__global__ void dedup3_kernel(const int* __restrict__ eidx, int n) {
  int i = blockIdx.x * blockDim.x + threadIdx.x;
  if (i >= n) return;
  int e = eidx[i];
  uint32_t h = ehash(e);
  while (g_ht[h] != e) h = (h + 1) & (HTSZ - 1);
  g_map[i] = g_uidtab[h];
}

// ---------------- weight packing ----------------
struct PArgs {
  const float* w[3];
  int ld[3];
  int coff[3];
  const float* bias[3];
};
__global__ void pack_w_kernel(PArgs a, int nseg, __nv_bfloat16* whi,
                              __nv_bfloat16* wlo, float* pbias) {
  int i = blockIdx.x * blockDim.x + threadIdx.x;
  int tot = nseg * NSEG * KP;
  if (i >= tot) return;
  int n = i / KP, c = i - n * KP;
  int seg = n / NSEG, nr = n - seg * NSEG;
  float v = 0.f;
  if (nr < E_ && c < E_) v = a.w[seg][(size_t)nr * a.ld[seg] + a.coff[seg] + c];
  __nv_bfloat16 h, l;
  bf16split(v, h, l);
  whi[i] = h; wlo[i] = l;
  if (c == 0) pbias[n] = (nr < E_ && a.bias[seg]) ? a.bias[seg][nr] : 0.f;
}

// ---------------- vectorized converts (1 float4 per thread) ----------------
__global__ void convert_kernel(const float* __restrict__ X, int ldx,
                               const int* __restrict__ g1, int gmode,
                               int M, int Mpad, int rowoff) {
  int i = blockIdx.x * blockDim.x + threadIdx.x;
  if (i >= Mpad * C4) return;
  int r = i / C4, c4 = i - r * C4;
  float4 v = make_float4(0.f, 0.f, 0.f, 0.f);
  if (r < M && c4 < 43) {
    int src = (gmode >= 1) ? g1[r] : r;
    v = *(const float4*)(X + (size_t)src * ldx + c4 * 4);
  }
  split_store4(v, g_Ahi, g_Alo, (size_t)(rowoff + r) * KP + c4 * 4);
}

__global__ void convert_uedges_kernel(const float* __restrict__ ef) {
  int i = blockIdx.x * blockDim.x + threadIdx.x;
  if (i >= NSLOT * C4) return;
  int r = i / C4, c4 = i - r * C4;
  if (r >= g_cnt) return;
  float4 v = make_float4(0.f, 0.f, 0.f, 0.f);
  if (c4 < 43) v = *(const float4*)(ef + (size_t)g_uelist[r] * E_ + c4 * 4);
  split_store4(v, g_Ahi, g_Alo, (size_t)(R_EDGE + r) * KP + c4 * 4);
}

__global__ void timeconv_kernel(const float* __restrict__ ts,
                                const float* __restrict__ tw,
                                const float* __restrict__ tb, int B, int Mpad) {
  int i = blockIdx.x * blockDim.x + threadIdx.x;
  if (i >= Mpad * C4) return;
  int r = i / C4, c4 = i - r * C4;
  float4 v = make_float4(0.f, 0.f, 0.f, 0.f);
  if (r < B && c4 < 43) {
    float tval = ts[r];
    float4 w = *(const float4*)(tw + c4 * 4);
    float4 b = *(const float4*)(tb + c4 * 4);
    v.x = (float)cos((double)__fadd_rn(__fmul_rn(tval, w.x), b.x));
    v.y = (float)cos((double)__fadd_rn(__fmul_rn(tval, w.y), b.y));
    v.z = (float)cos((double)__fadd_rn(__fmul_rn(tval, w.z), b.z));
    v.w = (float)cos((double)__fadd_rn(__fmul_rn(tval, w.w), b.w));
  }
  split_store4(v, g_Ahi, g_Alo, (size_t)(R_TIME + r) * KP + c4 * 4);
}

// ---------------- pipelined bf16 HMMA GEMM ----------------
#define BM 128
#define BN 96
#define ST 24
#define STAGE_A_B (BM * ST * 2)
#define STAGE_B_B (BN * ST * 2)
#define SM_AH 0
#define SM_AL (SM_AH + 4 * STAGE_A_B)
#define SM_BH (SM_AL + 4 * STAGE_A_B)
#define SM_BL (SM_BH + 4 * STAGE_B_B)
#define SMEM_G (SM_BL + 4 * STAGE_B_B)

__global__ __launch_bounds__(256, 2) void mma_gemm_kernel(
    const __nv_bfloat16* __restrict__ Ahi, const __nv_bfloat16* __restrict__ Alo,
    const __nv_bfloat16* __restrict__ Whi, const __nv_bfloat16* __restrict__ Wlo,
    const float* __restrict__ bias, float* __restrict__ out,
    __nv_bfloat16* __restrict__ ohi, __nv_bfloat16* __restrict__ olo,
    int M, int ldout, int segstride, int nwrite, const int* __restrict__ Mptr) {
  if (Mptr) {
    M = *Mptr;
    if ((int)(blockIdx.y * BM) >= M) return;
  }
  extern __shared__ __align__(128) char smraw[];
  const uint32_t sm = (uint32_t)__cvta_generic_to_shared(smraw);
  const int tid = threadIdx.x;
  const int warp = tid >> 5, lane = tid & 31;
  const int m0 = blockIdx.y * BM;
  const int n0 = blockIdx.x * BN;
  const int wm0 = (warp >> 1) * 32;
  const int wn0 = (warp & 1) * 48;

  float acc[2][6][4];
#pragma unroll
  for (int i = 0; i < 2; i++)
#pragma unroll
    for (int j = 0; j < 6; j++)
#pragma unroll
      for (int k = 0; k < 4; k++) acc[i][j][k] = 0.f;

  const int lr = tid >> 1, lch = tid & 1;
  const size_t srcA = (size_t)(m0 + lr) * KP + lch * 8;
  const size_t srcB = (size_t)(n0 + lr) * KP + lch * 8;
  const uint32_t dstAoff = (uint32_t)((lr * ST + lch * 8) * 2);
  const uint32_t dstBoff = dstAoff;

#define LOAD_STAGE(buf, ki)                                                   \
  do {                                                                        \
    cpa16(sm + SM_AH + (buf) * STAGE_A_B + dstAoff, Ahi + srcA + (ki) * 16);  \
    cpa16(sm + SM_AL + (buf) * STAGE_A_B + dstAoff, Alo + srcA + (ki) * 16);  \
    if (tid < 2 * BN) {                                                       \
      cpa16(sm + SM_BH + (buf) * STAGE_B_B + dstBoff, Whi + srcB + (ki) * 16);\
      cpa16(sm + SM_BL + (buf) * STAGE_B_B + dstBoff, Wlo + srcB + (ki) * 16);\
    }                                                                         \
  } while (0)

  LOAD_STAGE(0, 0); cpa_commit();
  LOAD_STAGE(1, 1); cpa_commit();
  LOAD_STAGE(2, 2); cpa_commit();

  const int aRow = (lane & 7) + ((lane >> 3) & 1) * 8;
  const int aCol = ((lane >> 4) & 1) * 8;
  const int bRow = (lane & 7) + ((lane >> 4) & 1) * 8;
  const int bCol = ((lane >> 3) & 1) * 8;

  for (int ki = 0; ki < KSTEPS; ki++) {
    const int buf = ki & 3;
    cpa_wait<2>();
    __syncthreads();
    if (ki + 3 < KSTEPS) LOAD_STAGE((ki + 3) & 3, ki + 3);
    cpa_commit();

    const uint32_t aB = sm + SM_AH + buf * STAGE_A_B;
    const uint32_t alB = sm + SM_AL + buf * STAGE_A_B;
    const uint32_t bB = sm + SM_BH + buf * STAGE_B_B;
    const uint32_t blB = sm + SM_BL + buf * STAGE_B_B;

    uint32_t ah[2][4], al[2][4], bh[6][2], bl[6][2];
#pragma unroll
    for (int ti = 0; ti < 2; ti++) {
      uint32_t off = (uint32_t)(((wm0 + ti * 16 + aRow) * ST + aCol) * 2);
      ldsm4(ah[ti], aB + off);
      ldsm4(al[ti], alB + off);
    }
#pragma unroll
    for (int p = 0; p < 3; p++) {
      uint32_t off = (uint32_t)(((wn0 + p * 16 + bRow) * ST + bCol) * 2);
      uint32_t t[4];
      ldsm4(t, bB + off);
      bh[2 * p][0] = t[0]; bh[2 * p][1] = t[1];
      bh[2 * p + 1][0] = t[2]; bh[2 * p + 1][1] = t[3];
      ldsm4(t, blB + off);
      bl[2 * p][0] = t[0]; bl[2 * p][1] = t[1];
      bl[2 * p + 1][0] = t[2]; bl[2 * p + 1][1] = t[3];
    }
#pragma unroll
    for (int ti = 0; ti < 2; ti++)
#pragma unroll
      for (int nj = 0; nj < 6; nj++) {
        mma_bf16(acc[ti][nj], ah[ti], bh[nj]);
        mma_bf16(acc[ti][nj], ah[ti], bl[nj]);
        mma_bf16(acc[ti][nj], al[ti], bh[nj]);
      }
  }
#undef LOAD_STAGE

  const int g = lane >> 2, tq = lane & 3;
#pragma unroll
  for (int ti = 0; ti < 2; ti++) {
    int m = m0 + wm0 + ti * 16 + g;
#pragma unroll
    for (int nj = 0; nj < 6; nj++) {
      int n = n0 + wn0 + nj * 8 + tq * 2;
      int seg = n / NSEG, nr = n - seg * NSEG;
      if (nr >= nwrite) continue;
      int col = seg * segstride + nr;
      float b0 = bias[n], b1 = bias[n + 1];
#pragma unroll
      for (int half = 0; half < 2; half++) {
        int mm = m + half * 8;
        if (mm >= M) continue;
        float v0 = acc[ti][nj][2 * half] + b0;
        float v1 = acc[ti][nj][2 * half + 1] + b1;
        if (out) {
          *(float2*)(out + (size_t)mm * ldout + col) = make_float2(v0, v1);
        } else {
          __nv_bfloat16 h0, l0, h1, l1;
          bf16split(v0, h0, l0);
          bf16split(v1, h1, l1);
          *(__nv_bfloat162*)(ohi + (size_t)mm * KP + col) = __nv_bfloat162(h0, h1);
          *(__nv_bfloat162*)(olo + (size_t)mm * KP + col) = __nv_bfloat162(l0, l1);
        }
      }
    }
  }
}

// ---------------- attention (per sample), writes bf16 split to R_O ----------------
// LAYER 0: q from g_qh; updated-neighbor kv not applicable.
// LAYER 1: q gathered from g_l1out[owner[nodes[b]]][0:172]; updated-neighbor
//          kv rows are g_l1out[ow] + 192 (k at +0, v at +NSEG as usual).
template <int LAYER>
__global__ __launch_bounds__(256) void attn_kernel(const int* __restrict__ neighbors,
                                                   const int* __restrict__ nodes, int B) {
  __shared__ float q[E_];
  __shared__ __align__(16) float kk[KNB][E_];
  __shared__ float sc[HH][KNB];
  __shared__ float at[HH][KNB];
  __shared__ const float* akp[KNB];
  __shared__ const float* bkp[KNB];
  __shared__ int pad[KNB];

  const int b = blockIdx.x;
  const int tid = threadIdx.x;
  const float* trow = g_tqkv + (size_t)b * 576;

  if (tid < KNB) {
    int nb = neighbors[b * KNB + tid];
    pad[tid] = (nb == 0) ? 1 : 0;
    const float* ap = g_node_kv + (size_t)nb * 384;
    if (LAYER == 1) {
      int ow = g_owner[nb];
      if (ow >= 0) ap = g_l1out + (size_t)ow * 576 + 192;
    }
    akp[tid] = ap;
    bkp[tid] = g_edge_kv + (size_t)g_map[b * KNB + tid] * 384;
  }
  if (tid < E_) {
    float qh;
    if (LAYER == 0) {
      qh = g_qh[(size_t)b * KP + tid];
    } else {
      int ow = g_owner[nodes[b]];
      qh = g_l1out[(size_t)ow * 576 + tid];
    }
    q[tid] = qh + trow[tid];
  }
  __syncthreads();

  const float* tk = trow + NSEG;
  for (int idx = tid; idx < KNB * 43; idx += 256) {
    int j = idx / 43, c4 = idx - j * 43;
    float4 a = *(const float4*)(akp[j] + c4 * 4);
    float4 e = *(const float4*)(bkp[j] + c4 * 4);
    float4 t = *(const float4*)(tk + c4 * 4);
    *(float4*)(&kk[j][c4 * 4]) =
        make_float4(a.x + e.x + t.x, a.y + e.y + t.y, a.z + e.z + t.z, a.w + e.w + t.w);
  }
  if (tid == 0) {
    int all = 1;
#pragma unroll
    for (int j = 0; j < KNB; j++) all &= pad[j];
    if (all) pad[0] = 0;
  }
  __syncthreads();

  if (tid < HH * KNB) {
    int h = tid / KNB, j = tid - h * KNB;
    const float* qp = q + h * HD_;
    const float* kp = &kk[j][h * HD_];
    float sum = 0.f;
#pragma unroll
    for (int d = 0; d < HD_; d++) sum += qp[d] * kp[d];
    sum *= 0.10783277320343841f;
    if (pad[j]) sum = -1e9f;
    sc[h][j] = sum;
  }
  __syncthreads();

  if (tid < HH) {
    float m = -INFINITY;
#pragma unroll
    for (int j = 0; j < KNB; j++) m = fmaxf(m, sc[tid][j]);
    float ex[KNB], ssum = 0.f;
#pragma unroll
    for (int j = 0; j < KNB; j++) { ex[j] = expf(sc[tid][j] - m); ssum += ex[j]; }
    float inv = 1.f / ssum;
#pragma unroll
    for (int j = 0; j < KNB; j++) at[tid][j] = ex[j] * inv;
  }
  __syncthreads();

  if (tid < E_) {
    int h = tid / HD_;
    float o = trow[2 * NSEG + tid];
#pragma unroll
    for (int j = 0; j < KNB; j++)
      o += at[h][j] * (akp[j][NSEG + tid] + bkp[j][NSEG + tid]);
    __nv_bfloat16 hh, ll;
    bf16split(o, hh, ll);
    g_Ahi[(size_t)(R_O + b) * KP + tid] = hh;
    g_Alo[(size_t)(R_O + b) * KP + tid] = ll;
  }
}

// ---------------- launch ----------------
static inline int cdiv(int a, int b) { return (a + b - 1) / b; }

extern "C" void kernel_launch(void* const* d_in, const int* in_sizes, int n_in,
                              void* d_out, int out_size) {
  const int* nodes     = (const int*)d_in[0];
  const float* ts      = (const float*)d_in[1];
  const int* neighbors = (const int*)d_in[2];
  const int* eidx      = (const int*)d_in[3];
  const float* nf      = (const float*)d_in[4];
  const float* ef      = (const float*)d_in[5];
  const float* time_w  = (const float*)d_in[6];
  const float* time_b  = (const float*)d_in[7];
  const float* q_w     = (const float*)d_in[8];
  const float* k_w     = (const float*)d_in[9];
  const float* v_w     = (const float*)d_in[10];
  const float* bq      = (const float*)d_in[11];
  const float* bk      = (const float*)d_in[12];
  const float* bv      = (const float*)d_in[13];
  const float* out_w   = (const float*)d_in[14];
  const float* out_b   = (const float*)d_in[15];
  float* out = (float*)d_out;
  const int B = in_sizes[0];

  __nv_bfloat16 *pWhi, *pWlo, *pAhi, *pAlo, *pH1hi, *pH1lo;
  float *pWb, *pzb, *ptqkv, *pnodekv, *pedgekv, *pl1out, *pqh;
  int *pht, *pcnt;
  cudaGetSymbolAddress((void**)&pWhi, g_Whi);
  cudaGetSymbolAddress((void**)&pWlo, g_Wlo);
  cudaGetSymbolAddress((void**)&pWb, g_Wb);
  cudaGetSymbolAddress((void**)&pzb, g_zbias);
  cudaGetSymbolAddress((void**)&pAhi, g_Ahi);
  cudaGetSymbolAddress((void**)&pAlo, g_Alo);
  cudaGetSymbolAddress((void**)&pH1hi, g_H1hi);
  cudaGetSymbolAddress((void**)&pH1lo, g_H1lo);
  cudaGetSymbolAddress((void**)&ptqkv, g_tqkv);
  cudaGetSymbolAddress((void**)&pnodekv, g_node_kv);
  cudaGetSymbolAddress((void**)&pedgekv, g_edge_kv);
  cudaGetSymbolAddress((void**)&pl1out, g_l1out);
  cudaGetSymbolAddress((void**)&pqh, g_qh);
  cudaGetSymbolAddress((void**)&pht, g_ht);
  cudaGetSymbolAddress((void**)&pcnt, g_cnt);

  cudaFuncSetAttribute(mma_gemm_kernel, cudaFuncAttributeMaxDynamicSharedMemorySize, SMEM_G);

  static cudaStream_t s1 = nullptr;
  static cudaEvent_t evF = nullptr, evA, evB, evC, evD;
  if (!s1) {
    cudaStreamCreateWithFlags(&s1, cudaStreamNonBlocking);
    cudaEventCreateWithFlags(&evF, cudaEventDisableTiming);
    cudaEventCreateWithFlags(&evA, cudaEventDisableTiming);
    cudaEventCreateWithFlags(&evB, cudaEventDisableTiming);
    cudaEventCreateWithFlags(&evC, cudaEventDisableTiming);
    cudaEventCreateWithFlags(&evD, cudaEventDisableTiming);
  }
  cudaStream_t s0 = 0;

  PArgs p;

#define GEMMF(Mpad, Npad, poff, Aoff, outp, M, ldo, segs, nw, Mptr)           \
  mma_gemm_kernel<<<dim3((Npad) / BN, (Mpad) / BM), 256, SMEM_G, s0>>>(       \
      pAhi + (size_t)(Aoff) * KP, pAlo + (size_t)(Aoff) * KP,                 \
      pWhi + (size_t)(poff) * KP, pWlo + (size_t)(poff) * KP,                 \
      pWb + (poff), outp, nullptr, nullptr, M, ldo, segs, nw, Mptr)

  // fork s1 from the capture stream
  cudaEventRecord(evF, s0);
  cudaStreamWaitEvent(s1, evF, 0);

  // ---- s1: prep, ordered by when s0 consumes it ----
  // group A: tqkv weights + time convert (cheapest -> first GEMM)
  p.w[0] = q_w; p.ld[0] = E_;     p.coff[0] = 0; p.bias[0] = bq;
  p.w[1] = k_w; p.ld[1] = 2 * E_; p.coff[1] = 0; p.bias[1] = bk;
  p.w[2] = v_w; p.ld[2] = 2 * E_; p.coff[2] = 0; p.bias[2] = bv;
  pack_w_kernel<<<cdiv(3 * NSEG * KP, 256), 256, 0, s1>>>(p, 3, pWhi + (size_t)P1_OFF * KP, pWlo + (size_t)P1_OFF * KP, pWb + P1_OFF);
  timeconv_kernel<<<cdiv(BPAD * C4, 256), 256, 0, s1>>>(ts, time_w, time_b, B, BPAD);
  cudaEventRecord(evA, s1);
  // group B: node weights + node convert
  p.w[0] = k_w; p.ld[0] = 2 * E_; p.coff[0] = 0; p.bias[0] = nullptr;
  p.w[1] = v_w; p.ld[1] = 2 * E_; p.coff[1] = 0; p.bias[1] = nullptr;
  p.w[2] = nullptr; p.ld[2] = 0; p.coff[2] = 0; p.bias[2] = nullptr;
  pack_w_kernel<<<cdiv(2 * NSEG * KP, 256), 256, 0, s1>>>(p, 2, pWhi + (size_t)P2_OFF * KP, pWlo + (size_t)P2_OFF * KP, pWb + P2_OFF);
  convert_kernel<<<cdiv(NPADN * C4, 256), 256, 0, s1>>>(nf, E_, nullptr, 0, NNODES, NPADN, R_NODE);
  cudaEventRecord(evB, s1);
  // group C: edge dedup + edge weights + edge convert
  cudaMemsetAsync(pht, 0xFF, (size_t)HTSZ * sizeof(int), s1);
  cudaMemsetAsync(pcnt, 0, sizeof(int), s1);
  dedup1_kernel<<<cdiv(B * KNB, 256), 256, 0, s1>>>(eidx, B * KNB);
  dedup2_kernel<<<cdiv(HTSZ, 256), 256, 0, s1>>>();
  p.w[0] = k_w; p.ld[0] = 2 * E_; p.coff[0] = E_; p.bias[0] = nullptr;
  p.w[1] = v_w; p.ld[1] = 2 * E_; p.coff[1] = E_; p.bias[1] = nullptr;
  p.w[2] = nullptr;
  pack_w_kernel<<<cdiv(2 * NSEG * KP, 256), 256, 0, s1>>>(p, 2, pWhi + (size_t)P3_OFF * KP, pWlo + (size_t)P3_OFF * KP, pWb + P3_OFF);
  convert_uedges_kernel<<<cdiv(NSLOT * C4, 256), 256, 0, s1>>>(ef);
  cudaEventRecord(evC, s1);
  // group D: dedup map, owner init, q/out weight packs, L0 q convert
  dedup3_kernel<<<cdiv(B * KNB, 256), 256, 0, s1>>>(eidx, B * KNB);
  init_owner_kernel<<<cdiv(NNODES, 256), 256, 0, s1>>>();
  p.w[0] = q_w; p.ld[0] = E_; p.coff[0] = 0; p.bias[0] = nullptr;
  p.w[1] = nullptr; p.w[2] = nullptr;
  pack_w_kernel<<<cdiv(NSEG * KP, 256), 256, 0, s1>>>(p, 1, pWhi + (size_t)P4_OFF * KP, pWlo + (size_t)P4_OFF * KP, pWb + P4_OFF);
  p.w[0] = out_w; p.bias[0] = out_b;
  pack_w_kernel<<<cdiv(NSEG * KP, 256), 256, 0, s1>>>(p, 1, pWhi + (size_t)P5_OFF * KP, pWlo + (size_t)P5_OFF * KP, pWb + P5_OFF);
  convert_kernel<<<cdiv(BPAD * C4, 256), 256, 0, s1>>>(nf, E_, nodes, 1, B, BPAD, R_Q0);
  cudaEventRecord(evD, s1);

  // ---- s0: GEMM chain + attention ----
  cudaStreamWaitEvent(s0, evA, 0);
  GEMMF(BPAD, 576, P1_OFF, R_TIME, ptqkv, B, 576, NSEG, NSEG, nullptr);
  cudaStreamWaitEvent(s0, evB, 0);
  GEMMF(NPADN, 384, P2_OFF, R_NODE, pnodekv, NNODES, 384, NSEG, NSEG, nullptr);
  cudaStreamWaitEvent(s0, evC, 0);
  GEMMF(NSLOT, 384, P3_OFF, R_EDGE, pedgekv, B * KNB, 384, NSEG, NSEG, pcnt);
  cudaStreamWaitEvent(s0, evD, 0);

  // layer 0
  GEMMF(BPAD, NSEG, P4_OFF, R_Q0, pqh, B, KP, 0, KP, nullptr);
  attn_kernel<0><<<B, 256, 0, s0>>>(neighbors, nodes, B);
  // out-proj -> H1 (bf16 split)
  mma_gemm_kernel<<<dim3(NSEG / BN, BPAD / BM), 256, SMEM_G, s0>>>(
      pAhi + (size_t)R_O * KP, pAlo + (size_t)R_O * KP,
      pWhi + (size_t)P5_OFF * KP, pWlo + (size_t)P5_OFF * KP,
      pWb + P5_OFF, nullptr, pH1hi, pH1lo, B, KP, 0, KP, nullptr);
  build_owner_kernel<<<cdiv(B, 256), 256, 0, s0>>>(nodes, B);

  // layer 1: merged H1 @ [q|kE|vE]  (zero bias; biases live on the t-side)
  mma_gemm_kernel<<<dim3(576 / BN, BPAD / BM), 256, SMEM_G, s0>>>(
      pH1hi, pH1lo, pWhi + (size_t)P1_OFF * KP, pWlo + (size_t)P1_OFF * KP,
      pzb, pl1out, nullptr, nullptr, B, 576, NSEG, NSEG, nullptr);
  attn_kernel<1><<<B, 256, 0, s0>>>(neighbors, nodes, B);
  GEMMF(BPAD, NSEG, P5_OFF, R_O, out, B, E_, 0, E_, nullptr);
#undef GEMMF
}

// round 12
// speedup vs baseline: 2.2326x; 1.1948x over previous
#include <cuda_runtime.h>
#include <cuda_fp16.h>
#include <math.h>
#include <stdint.h>

#define E_ 172
#define KP 176            // padded K (11 k16 steps)
#define KSTEPS 11
#define C4 (KP / 4)       // 44 float4 chunks per row (chunk 43 = zeros)
#define NSEG 192
#define KNB 20
#define HH 2
#define HD_ 86
#define NNODES 100000
#define BMAX 12000
#define BPAD 12032
#define NPADN 100096
#define NSLOT 240000
#define HTSZ (1 << 19)

// disjoint A-buffer row regions (for cross-stream overlap)
#define R_EDGE 0
#define R_TIME 240000
#define R_NODE 252032                 // R_TIME + BPAD
#define R_Q0   352128                 // R_NODE + NPADN
#define R_O    364160                 // R_Q0 + BPAD
#define AROWS  376192                 // R_O + BPAD

#define P1_OFF 0
#define P2_OFF 576
#define P3_OFF 960
#define P4_OFF 1344
#define P5_OFF 1536
#define PTOT 1728

// ---------------- scratch ----------------
__device__ __half g_A[(size_t)AROWS * KP];         // single-limb fp16 activations
__device__ __half g_Whi[(size_t)PTOT * KP];        // weight hi limb
__device__ __half g_Wlo[(size_t)PTOT * KP];        // weight lo limb
__device__ float g_Wb[PTOT];
__device__ float g_zbias[576];                     // statically zero

__device__ float g_tqkv[BMAX * 576];
__device__ float g_node_kv[(size_t)NNODES * 384];
__device__ float g_edge_kv[(size_t)NSLOT * 384];
__device__ float g_l1out[BMAX * 576];              // layer-1 merged [q|k|v] of H1
__device__ float g_qh[BMAX * KP];
__device__ __half g_H1[BPAD * KP];                 // layer-0 output h1 (fp16)
__device__ int g_owner[NNODES];

__device__ int g_ht[HTSZ];
__device__ int g_uidtab[HTSZ];
__device__ int g_uelist[NSLOT];
__device__ int g_map[NSLOT];
__device__ int g_cnt;

// ---------------- helpers ----------------
__device__ __forceinline__ void cpa16(uint32_t dst, const void* src) {
  asm volatile("cp.async.cg.shared.global [%0], [%1], 16;" :: "r"(dst), "l"(src));
}
__device__ __forceinline__ void cpa_commit() { asm volatile("cp.async.commit_group;" ::: "memory"); }
template <int N>
__device__ __forceinline__ void cpa_wait() { asm volatile("cp.async.wait_group %0;" :: "n"(N) : "memory"); }

__device__ __forceinline__ void ldsm4(uint32_t* r, uint32_t addr) {
  asm volatile("ldmatrix.sync.aligned.m8n8.x4.shared.b16 {%0,%1,%2,%3}, [%4];"
               : "=r"(r[0]), "=r"(r[1]), "=r"(r[2]), "=r"(r[3]) : "r"(addr));
}
__device__ __forceinline__ void mma_f16(float* d, const uint32_t* a, const uint32_t* b) {
  asm volatile(
      "mma.sync.aligned.m16n8k16.row.col.f32.f16.f16.f32 "
      "{%0,%1,%2,%3},{%4,%5,%6,%7},{%8,%9},{%0,%1,%2,%3};"
      : "+f"(d[0]), "+f"(d[1]), "+f"(d[2]), "+f"(d[3])
      : "r"(a[0]), "r"(a[1]), "r"(a[2]), "r"(a[3]), "r"(b[0]), "r"(b[1]));
}

__device__ __forceinline__ void fp16split(float v, __half& h, __half& l) {
  h = __float2half_rn(v);
  l = __float2half_rn(v - __half2float(h));
}

// convert float4 -> 4 fp16 and store 8 bytes
__device__ __forceinline__ void store4h(float4 v, __half* dst, size_t off) {
  __half2 a = __floats2half2_rn(v.x, v.y);
  __half2 b = __floats2half2_rn(v.z, v.w);
  ((__half2*)(dst + off))[0] = a;
  ((__half2*)(dst + off))[1] = b;
}

__device__ __forceinline__ uint32_t ehash(int e) {
  return (((uint32_t)e * 2654435761u) >> 13) & (HTSZ - 1);
}

// ---------------- small kernels ----------------
__global__ void init_owner_kernel() {
  int i = blockIdx.x * blockDim.x + threadIdx.x;
  if (i < NNODES) g_owner[i] = -1;
}
__global__ void build_owner_kernel(const int* __restrict__ nodes, int B) {
  int i = blockIdx.x * blockDim.x + threadIdx.x;
  if (i < B) atomicMax(&g_owner[nodes[i]], i);
}

// ---------------- edge dedup ----------------
__global__ void dedup1_kernel(const int* __restrict__ eidx, int n) {
  int i = blockIdx.x * blockDim.x + threadIdx.x;
  if (i >= n) return;
  int e = eidx[i];
  uint32_t h = ehash(e);
  while (true) {
    int prev = atomicCAS(&g_ht[h], -1, e);
    if (prev == -1 || prev == e) break;
    h = (h + 1) & (HTSZ - 1);
  }
}
__global__ void dedup2_kernel() {
  int i = blockIdx.x * blockDim.x + threadIdx.x;
  if (i >= HTSZ) return;
  int e = g_ht[i];
  if (e != -1) {
    int uid = atomicAdd(&g_cnt, 1);
    g_uidtab[i] = uid;
    g_uelist[uid] = e;
  }
}
__global__ void dedup3_kernel(const int* __restrict__ eidx, int n) {
  int i = blockIdx.x * blockDim.x + threadIdx.x;
  if (i >= n) return;
  int e = eidx[i];
  uint32_t h = ehash(e);
  while (g_ht[h] != e) h = (h + 1) & (HTSZ - 1);
  g_map[i] = g_uidtab[h];
}

// ---------------- weight packing (fp16 two-limb) ----------------
struct PArgs {
  const float* w[3];
  int ld[3];
  int coff[3];
  const float* bias[3];
};
__global__ void pack_w_kernel(PArgs a, int nseg, __half* whi,
                              __half* wlo, float* pbias) {
  int i = blockIdx.x * blockDim.x + threadIdx.x;
  int tot = nseg * NSEG * KP;
  if (i >= tot) return;
  int n = i / KP, c = i - n * KP;
  int seg = n / NSEG, nr = n - seg * NSEG;
  float v = 0.f;
  if (nr < E_ && c < E_) v = a.w[seg][(size_t)nr * a.ld[seg] + a.coff[seg] + c];
  __half h, l;
  fp16split(v, h, l);
  whi[i] = h; wlo[i] = l;
  if (c == 0) pbias[n] = (nr < E_ && a.bias[seg]) ? a.bias[seg][nr] : 0.f;
}

// ---------------- vectorized converts (1 float4 per thread) ----------------
__global__ void convert_kernel(const float* __restrict__ X, int ldx,
                               const int* __restrict__ g1, int gmode,
                               int M, int Mpad, int rowoff) {
  int i = blockIdx.x * blockDim.x + threadIdx.x;
  if (i >= Mpad * C4) return;
  int r = i / C4, c4 = i - r * C4;
  float4 v = make_float4(0.f, 0.f, 0.f, 0.f);
  if (r < M && c4 < 43) {
    int src = (gmode >= 1) ? g1[r] : r;
    v = *(const float4*)(X + (size_t)src * ldx + c4 * 4);
  }
  store4h(v, g_A, (size_t)(rowoff + r) * KP + c4 * 4);
}

__global__ void convert_uedges_kernel(const float* __restrict__ ef) {
  int i = blockIdx.x * blockDim.x + threadIdx.x;
  if (i >= NSLOT * C4) return;
  int r = i / C4, c4 = i - r * C4;
  if (r >= g_cnt) return;
  float4 v = make_float4(0.f, 0.f, 0.f, 0.f);
  if (c4 < 43) v = *(const float4*)(ef + (size_t)g_uelist[r] * E_ + c4 * 4);
  store4h(v, g_A, (size_t)(R_EDGE + r) * KP + c4 * 4);
}

__global__ void timeconv_kernel(const float* __restrict__ ts,
                                const float* __restrict__ tw,
                                const float* __restrict__ tb, int B, int Mpad) {
  int i = blockIdx.x * blockDim.x + threadIdx.x;
  if (i >= Mpad * C4) return;
  int r = i / C4, c4 = i - r * C4;
  float4 v = make_float4(0.f, 0.f, 0.f, 0.f);
  if (r < B && c4 < 43) {
    float tval = ts[r];
    float4 w = *(const float4*)(tw + c4 * 4);
    float4 b = *(const float4*)(tb + c4 * 4);
    v.x = (float)cos((double)__fadd_rn(__fmul_rn(tval, w.x), b.x));
    v.y = (float)cos((double)__fadd_rn(__fmul_rn(tval, w.y), b.y));
    v.z = (float)cos((double)__fadd_rn(__fmul_rn(tval, w.z), b.z));
    v.w = (float)cos((double)__fadd_rn(__fmul_rn(tval, w.w), b.w));
  }
  store4h(v, g_A, (size_t)(R_TIME + r) * KP + c4 * 4);
}

// ---------------- pipelined fp16 HMMA GEMM (A 1-limb, W 2-limb) ----------------
#define BM 128
#define BN 96
#define ST 24
#define STAGE_A_B (BM * ST * 2)   // 6144
#define STAGE_B_B (BN * ST * 2)   // 4608
#define SM_A  0
#define SM_BH (SM_A + 4 * STAGE_A_B)
#define SM_BL (SM_BH + 4 * STAGE_B_B)
#define SMEM_G (SM_BL + 4 * STAGE_B_B)  // 61440

__global__ __launch_bounds__(256, 2) void mma_gemm_kernel(
    const __half* __restrict__ A,
    const __half* __restrict__ Whi, const __half* __restrict__ Wlo,
    const float* __restrict__ bias, float* __restrict__ out,
    __half* __restrict__ oh,
    int M, int ldout, int segstride, int nwrite, const int* __restrict__ Mptr) {
  if (Mptr) {
    M = *Mptr;
    if ((int)(blockIdx.y * BM) >= M) return;
  }
  extern __shared__ __align__(128) char smraw[];
  const uint32_t sm = (uint32_t)__cvta_generic_to_shared(smraw);
  const int tid = threadIdx.x;
  const int warp = tid >> 5, lane = tid & 31;
  const int m0 = blockIdx.y * BM;
  const int n0 = blockIdx.x * BN;
  const int wm0 = (warp >> 1) * 32;
  const int wn0 = (warp & 1) * 48;

  float acc[2][6][4];
#pragma unroll
  for (int i = 0; i < 2; i++)
#pragma unroll
    for (int j = 0; j < 6; j++)
#pragma unroll
      for (int k = 0; k < 4; k++) acc[i][j][k] = 0.f;

  const int lr = tid >> 1, lch = tid & 1;
  const size_t srcA = (size_t)(m0 + lr) * KP + lch * 8;
  const size_t srcB = (size_t)(n0 + lr) * KP + lch * 8;
  const uint32_t dstAoff = (uint32_t)((lr * ST + lch * 8) * 2);
  const uint32_t dstBoff = dstAoff;

#define LOAD_STAGE(buf, ki)                                                   \
  do {                                                                        \
    cpa16(sm + SM_A + (buf) * STAGE_A_B + dstAoff, A + srcA + (ki) * 16);     \
    if (tid < 2 * BN) {                                                       \
      cpa16(sm + SM_BH + (buf) * STAGE_B_B + dstBoff, Whi + srcB + (ki) * 16);\
      cpa16(sm + SM_BL + (buf) * STAGE_B_B + dstBoff, Wlo + srcB + (ki) * 16);\
    }                                                                         \
  } while (0)

  LOAD_STAGE(0, 0); cpa_commit();
  LOAD_STAGE(1, 1); cpa_commit();
  LOAD_STAGE(2, 2); cpa_commit();

  const int aRow = (lane & 7) + ((lane >> 3) & 1) * 8;
  const int aCol = ((lane >> 4) & 1) * 8;
  const int bRow = (lane & 7) + ((lane >> 4) & 1) * 8;
  const int bCol = ((lane >> 3) & 1) * 8;

  for (int ki = 0; ki < KSTEPS; ki++) {
    const int buf = ki & 3;
    cpa_wait<2>();
    __syncthreads();
    if (ki + 3 < KSTEPS) LOAD_STAGE((ki + 3) & 3, ki + 3);
    cpa_commit();

    const uint32_t aB = sm + SM_A + buf * STAGE_A_B;
    const uint32_t bB = sm + SM_BH + buf * STAGE_B_B;
    const uint32_t blB = sm + SM_BL + buf * STAGE_B_B;

    uint32_t af[2][4], bh[6][2], bl[6][2];
#pragma unroll
    for (int ti = 0; ti < 2; ti++) {
      uint32_t off = (uint32_t)(((wm0 + ti * 16 + aRow) * ST + aCol) * 2);
      ldsm4(af[ti], aB + off);
    }
#pragma unroll
    for (int p = 0; p < 3; p++) {
      uint32_t off = (uint32_t)(((wn0 + p * 16 + bRow) * ST + bCol) * 2);
      uint32_t t[4];
      ldsm4(t, bB + off);
      bh[2 * p][0] = t[0]; bh[2 * p][1] = t[1];
      bh[2 * p + 1][0] = t[2]; bh[2 * p + 1][1] = t[3];
      ldsm4(t, blB + off);
      bl[2 * p][0] = t[0]; bl[2 * p][1] = t[1];
      bl[2 * p + 1][0] = t[2]; bl[2 * p + 1][1] = t[3];
    }
#pragma unroll
    for (int ti = 0; ti < 2; ti++)
#pragma unroll
      for (int nj = 0; nj < 6; nj++) {
        mma_f16(acc[ti][nj], af[ti], bh[nj]);
        mma_f16(acc[ti][nj], af[ti], bl[nj]);
      }
  }
#undef LOAD_STAGE

  const int g = lane >> 2, tq = lane & 3;
#pragma unroll
  for (int ti = 0; ti < 2; ti++) {
    int m = m0 + wm0 + ti * 16 + g;
#pragma unroll
    for (int nj = 0; nj < 6; nj++) {
      int n = n0 + wn0 + nj * 8 + tq * 2;
      int seg = n / NSEG, nr = n - seg * NSEG;
      if (nr >= nwrite) continue;
      int col = seg * segstride + nr;
      float b0 = bias[n], b1 = bias[n + 1];
#pragma unroll
      for (int half = 0; half < 2; half++) {
        int mm = m + half * 8;
        if (mm >= M) continue;
        float v0 = acc[ti][nj][2 * half] + b0;
        float v1 = acc[ti][nj][2 * half + 1] + b1;
        if (out) {
          *(float2*)(out + (size_t)mm * ldout + col) = make_float2(v0, v1);
        } else {
          *(__half2*)(oh + (size_t)mm * KP + col) = __floats2half2_rn(v0, v1);
        }
      }
    }
  }
}

// ---------------- attention (per sample), writes fp16 to R_O ----------------
template <int LAYER>
__global__ __launch_bounds__(256) void attn_kernel(const int* __restrict__ neighbors,
                                                   const int* __restrict__ nodes, int B) {
  __shared__ float q[E_];
  __shared__ __align__(16) float kk[KNB][E_];
  __shared__ float sc[HH][KNB];
  __shared__ float at[HH][KNB];
  __shared__ const float* akp[KNB];
  __shared__ const float* bkp[KNB];
  __shared__ int pad[KNB];

  const int b = blockIdx.x;
  const int tid = threadIdx.x;
  const float* trow = g_tqkv + (size_t)b * 576;

  if (tid < KNB) {
    int nb = neighbors[b * KNB + tid];
    pad[tid] = (nb == 0) ? 1 : 0;
    const float* ap = g_node_kv + (size_t)nb * 384;
    if (LAYER == 1) {
      int ow = g_owner[nb];
      if (ow >= 0) ap = g_l1out + (size_t)ow * 576 + 192;
    }
    akp[tid] = ap;
    bkp[tid] = g_edge_kv + (size_t)g_map[b * KNB + tid] * 384;
  }
  if (tid < E_) {
    float qh;
    if (LAYER == 0) {
      qh = g_qh[(size_t)b * KP + tid];
    } else {
      int ow = g_owner[nodes[b]];
      qh = g_l1out[(size_t)ow * 576 + tid];
    }
    q[tid] = qh + trow[tid];
  }
  __syncthreads();

  const float* tk = trow + NSEG;
  for (int idx = tid; idx < KNB * 43; idx += 256) {
    int j = idx / 43, c4 = idx - j * 43;
    float4 a = *(const float4*)(akp[j] + c4 * 4);
    float4 e = *(const float4*)(bkp[j] + c4 * 4);
    float4 t = *(const float4*)(tk + c4 * 4);
    *(float4*)(&kk[j][c4 * 4]) =
        make_float4(a.x + e.x + t.x, a.y + e.y + t.y, a.z + e.z + t.z, a.w + e.w + t.w);
  }
  if (tid == 0) {
    int all = 1;
#pragma unroll
    for (int j = 0; j < KNB; j++) all &= pad[j];
    if (all) pad[0] = 0;
  }
  __syncthreads();

  if (tid < HH * KNB) {
    int h = tid / KNB, j = tid - h * KNB;
    const float* qp = q + h * HD_;
    const float* kp = &kk[j][h * HD_];
    float sum = 0.f;
#pragma unroll
    for (int d = 0; d < HD_; d++) sum += qp[d] * kp[d];
    sum *= 0.10783277320343841f;
    if (pad[j]) sum = -1e9f;
    sc[h][j] = sum;
  }
  __syncthreads();

  if (tid < HH) {
    float m = -INFINITY;
#pragma unroll
    for (int j = 0; j < KNB; j++) m = fmaxf(m, sc[tid][j]);
    float ex[KNB], ssum = 0.f;
#pragma unroll
    for (int j = 0; j < KNB; j++) { ex[j] = expf(sc[tid][j] - m); ssum += ex[j]; }
    float inv = 1.f / ssum;
#pragma unroll
    for (int j = 0; j < KNB; j++) at[tid][j] = ex[j] * inv;
  }
  __syncthreads();

  if (tid < E_) {
    int h = tid / HD_;
    float o = trow[2 * NSEG + tid];
#pragma unroll
    for (int j = 0; j < KNB; j++)
      o += at[h][j] * (akp[j][NSEG + tid] + bkp[j][NSEG + tid]);
    g_A[(size_t)(R_O + b) * KP + tid] = __float2half_rn(o);
  }
}

// ---------------- launch ----------------
static inline int cdiv(int a, int b) { return (a + b - 1) / b; }

extern "C" void kernel_launch(void* const* d_in, const int* in_sizes, int n_in,
                              void* d_out, int out_size) {
  const int* nodes     = (const int*)d_in[0];
  const float* ts      = (const float*)d_in[1];
  const int* neighbors = (const int*)d_in[2];
  const int* eidx      = (const int*)d_in[3];
  const float* nf      = (const float*)d_in[4];
  const float* ef      = (const float*)d_in[5];
  const float* time_w  = (const float*)d_in[6];
  const float* time_b  = (const float*)d_in[7];
  const float* q_w     = (const float*)d_in[8];
  const float* k_w     = (const float*)d_in[9];
  const float* v_w     = (const float*)d_in[10];
  const float* bq      = (const float*)d_in[11];
  const float* bk      = (const float*)d_in[12];
  const float* bv      = (const float*)d_in[13];
  const float* out_w   = (const float*)d_in[14];
  const float* out_b   = (const float*)d_in[15];
  float* out = (float*)d_out;
  const int B = in_sizes[0];

  __half *pWhi, *pWlo, *pA, *pH1;
  float *pWb, *pzb, *ptqkv, *pnodekv, *pedgekv, *pl1out, *pqh;
  int *pht, *pcnt;
  cudaGetSymbolAddress((void**)&pWhi, g_Whi);
  cudaGetSymbolAddress((void**)&pWlo, g_Wlo);
  cudaGetSymbolAddress((void**)&pWb, g_Wb);
  cudaGetSymbolAddress((void**)&pzb, g_zbias);
  cudaGetSymbolAddress((void**)&pA, g_A);
  cudaGetSymbolAddress((void**)&pH1, g_H1);
  cudaGetSymbolAddress((void**)&ptqkv, g_tqkv);
  cudaGetSymbolAddress((void**)&pnodekv, g_node_kv);
  cudaGetSymbolAddress((void**)&pedgekv, g_edge_kv);
  cudaGetSymbolAddress((void**)&pl1out, g_l1out);
  cudaGetSymbolAddress((void**)&pqh, g_qh);
  cudaGetSymbolAddress((void**)&pht, g_ht);
  cudaGetSymbolAddress((void**)&pcnt, g_cnt);

  cudaFuncSetAttribute(mma_gemm_kernel, cudaFuncAttributeMaxDynamicSharedMemorySize, SMEM_G);

  static cudaStream_t s1 = nullptr;
  static cudaEvent_t evF = nullptr, evA, evB, evC, evD;
  if (!s1) {
    cudaStreamCreateWithFlags(&s1, cudaStreamNonBlocking);
    cudaEventCreateWithFlags(&evF, cudaEventDisableTiming);
    cudaEventCreateWithFlags(&evA, cudaEventDisableTiming);
    cudaEventCreateWithFlags(&evB, cudaEventDisableTiming);
    cudaEventCreateWithFlags(&evC, cudaEventDisableTiming);
    cudaEventCreateWithFlags(&evD, cudaEventDisableTiming);
  }
  cudaStream_t s0 = 0;

  PArgs p;

#define GEMMF(Mpad, Npad, poff, Aoff, outp, M, ldo, segs, nw, Mptr)           \
  mma_gemm_kernel<<<dim3((Npad) / BN, (Mpad) / BM), 256, SMEM_G, s0>>>(       \
      pA + (size_t)(Aoff) * KP,                                               \
      pWhi + (size_t)(poff) * KP, pWlo + (size_t)(poff) * KP,                 \
      pWb + (poff), outp, nullptr, M, ldo, segs, nw, Mptr)

  // fork s1 from the capture stream
  cudaEventRecord(evF, s0);
  cudaStreamWaitEvent(s1, evF, 0);

  // ---- s1: prep, ordered by when s0 consumes it ----
  // group A: tqkv weights + time convert
  p.w[0] = q_w; p.ld[0] = E_;     p.coff[0] = 0; p.bias[0] = bq;
  p.w[1] = k_w; p.ld[1] = 2 * E_; p.coff[1] = 0; p.bias[1] = bk;
  p.w[2] = v_w; p.ld[2] = 2 * E_; p.coff[2] = 0; p.bias[2] = bv;
  pack_w_kernel<<<cdiv(3 * NSEG * KP, 256), 256, 0, s1>>>(p, 3, pWhi + (size_t)P1_OFF * KP, pWlo + (size_t)P1_OFF * KP, pWb + P1_OFF);
  timeconv_kernel<<<cdiv(BPAD * C4, 256), 256, 0, s1>>>(ts, time_w, time_b, B, BPAD);
  cudaEventRecord(evA, s1);
  // group B: node weights + node convert
  p.w[0] = k_w; p.ld[0] = 2 * E_; p.coff[0] = 0; p.bias[0] = nullptr;
  p.w[1] = v_w; p.ld[1] = 2 * E_; p.coff[1] = 0; p.bias[1] = nullptr;
  p.w[2] = nullptr; p.ld[2] = 0; p.coff[2] = 0; p.bias[2] = nullptr;
  pack_w_kernel<<<cdiv(2 * NSEG * KP, 256), 256, 0, s1>>>(p, 2, pWhi + (size_t)P2_OFF * KP, pWlo + (size_t)P2_OFF * KP, pWb + P2_OFF);
  convert_kernel<<<cdiv(NPADN * C4, 256), 256, 0, s1>>>(nf, E_, nullptr, 0, NNODES, NPADN, R_NODE);
  cudaEventRecord(evB, s1);
  // group C: edge dedup + edge weights + edge convert
  cudaMemsetAsync(pht, 0xFF, (size_t)HTSZ * sizeof(int), s1);
  cudaMemsetAsync(pcnt, 0, sizeof(int), s1);
  dedup1_kernel<<<cdiv(B * KNB, 256), 256, 0, s1>>>(eidx, B * KNB);
  dedup2_kernel<<<cdiv(HTSZ, 256), 256, 0, s1>>>();
  p.w[0] = k_w; p.ld[0] = 2 * E_; p.coff[0] = E_; p.bias[0] = nullptr;
  p.w[1] = v_w; p.ld[1] = 2 * E_; p.coff[1] = E_; p.bias[1] = nullptr;
  p.w[2] = nullptr;
  pack_w_kernel<<<cdiv(2 * NSEG * KP, 256), 256, 0, s1>>>(p, 2, pWhi + (size_t)P3_OFF * KP, pWlo + (size_t)P3_OFF * KP, pWb + P3_OFF);
  convert_uedges_kernel<<<cdiv(NSLOT * C4, 256), 256, 0, s1>>>(ef);
  cudaEventRecord(evC, s1);
  // group D: dedup map, owner init, q/out weight packs, L0 q convert
  dedup3_kernel<<<cdiv(B * KNB, 256), 256, 0, s1>>>(eidx, B * KNB);
  init_owner_kernel<<<cdiv(NNODES, 256), 256, 0, s1>>>();
  p.w[0] = q_w; p.ld[0] = E_; p.coff[0] = 0; p.bias[0] = nullptr;
  p.w[1] = nullptr; p.w[2] = nullptr;
  pack_w_kernel<<<cdiv(NSEG * KP, 256), 256, 0, s1>>>(p, 1, pWhi + (size_t)P4_OFF * KP, pWlo + (size_t)P4_OFF * KP, pWb + P4_OFF);
  p.w[0] = out_w; p.bias[0] = out_b;
  pack_w_kernel<<<cdiv(NSEG * KP, 256), 256, 0, s1>>>(p, 1, pWhi + (size_t)P5_OFF * KP, pWlo + (size_t)P5_OFF * KP, pWb + P5_OFF);
  convert_kernel<<<cdiv(BPAD * C4, 256), 256, 0, s1>>>(nf, E_, nodes, 1, B, BPAD, R_Q0);
  cudaEventRecord(evD, s1);

  // ---- s0: GEMM chain + attention ----
  cudaStreamWaitEvent(s0, evA, 0);
  GEMMF(BPAD, 576, P1_OFF, R_TIME, ptqkv, B, 576, NSEG, NSEG, nullptr);
  cudaStreamWaitEvent(s0, evB, 0);
  GEMMF(NPADN, 384, P2_OFF, R_NODE, pnodekv, NNODES, 384, NSEG, NSEG, nullptr);
  cudaStreamWaitEvent(s0, evC, 0);
  GEMMF(NSLOT, 384, P3_OFF, R_EDGE, pedgekv, B * KNB, 384, NSEG, NSEG, pcnt);
  cudaStreamWaitEvent(s0, evD, 0);

  // layer 0
  GEMMF(BPAD, NSEG, P4_OFF, R_Q0, pqh, B, KP, 0, KP, nullptr);
  attn_kernel<0><<<B, 256, 0, s0>>>(neighbors, nodes, B);
  // out-proj -> H1 (fp16)
  mma_gemm_kernel<<<dim3(NSEG / BN, BPAD / BM), 256, SMEM_G, s0>>>(
      pA + (size_t)R_O * KP,
      pWhi + (size_t)P5_OFF * KP, pWlo + (size_t)P5_OFF * KP,
      pWb + P5_OFF, nullptr, pH1, B, KP, 0, KP, nullptr);
  build_owner_kernel<<<cdiv(B, 256), 256, 0, s0>>>(nodes, B);

  // layer 1: merged H1 @ [q|kE|vE]  (zero bias; biases live on the t-side)
  mma_gemm_kernel<<<dim3(576 / BN, BPAD / BM), 256, SMEM_G, s0>>>(
      pH1,
      pWhi + (size_t)P1_OFF * KP, pWlo + (size_t)P1_OFF * KP,
      pzb, pl1out, nullptr, B, 576, NSEG, NSEG, nullptr);
  attn_kernel<1><<<B, 256, 0, s0>>>(neighbors, nodes, B);
  GEMMF(BPAD, NSEG, P5_OFF, R_O, out, B, E_, 0, E_, nullptr);
#undef GEMMF
}

// round 13
// speedup vs baseline: 2.5282x; 1.1324x over previous
#include <cuda_runtime.h>
#include <cuda_fp16.h>
#include <math.h>
#include <stdint.h>

#define E_ 172
#define KP 176            // padded K (11 k16 steps)
#define KSTEPS 11
#define C4 (KP / 4)       // 44 float4 chunks per row (chunk 43 = zeros)
#define NSEG 192
#define KNB 20
#define HH 2
#define HD_ 86
#define NNODES 100000
#define BMAX 12000
#define BPAD 12032
#define NPADN 100096
#define NSLOT 240000
#define HTSZ (1 << 19)

// disjoint A-buffer row regions (for cross-stream overlap)
#define R_EDGE 0
#define R_TIME 240000
#define R_NODE 252032                 // R_TIME + BPAD
#define R_Q0   352128                 // R_NODE + NPADN
#define R_O    364160                 // R_Q0 + BPAD
#define AROWS  376192                 // R_O + BPAD

#define P1_OFF 0
#define P2_OFF 576
#define P3_OFF 960
#define P4_OFF 1344
#define P5_OFF 1536
#define PTOT 1728

// ---------------- scratch ----------------
__device__ __half g_A[(size_t)AROWS * KP];         // fp16 activations
__device__ __half g_W[(size_t)PTOT * KP];          // fp16 weights (single limb)
__device__ float g_Wb[PTOT];
__device__ float g_zbias[576];                     // statically zero

__device__ float g_tqkv[BMAX * 576];
__device__ float g_node_kv[(size_t)NNODES * 384];
__device__ float g_edge_kv[(size_t)NSLOT * 384];
__device__ float g_l1out[BMAX * 576];              // layer-1 merged [q|k|v] of H1
__device__ float g_qh[BMAX * KP];
__device__ __half g_H1[BPAD * KP];                 // layer-0 output h1 (fp16)
__device__ int g_owner[NNODES];

__device__ int g_ht[HTSZ];
__device__ int g_uidtab[HTSZ];
__device__ int g_uelist[NSLOT];
__device__ int g_map[NSLOT];
__device__ int g_cnt;

// ---------------- helpers ----------------
__device__ __forceinline__ void cpa16(uint32_t dst, const void* src) {
  asm volatile("cp.async.cg.shared.global [%0], [%1], 16;" :: "r"(dst), "l"(src));
}
__device__ __forceinline__ void cpa_commit() { asm volatile("cp.async.commit_group;" ::: "memory"); }
template <int N>
__device__ __forceinline__ void cpa_wait() { asm volatile("cp.async.wait_group %0;" :: "n"(N) : "memory"); }

__device__ __forceinline__ void ldsm4(uint32_t* r, uint32_t addr) {
  asm volatile("ldmatrix.sync.aligned.m8n8.x4.shared.b16 {%0,%1,%2,%3}, [%4];"
               : "=r"(r[0]), "=r"(r[1]), "=r"(r[2]), "=r"(r[3]) : "r"(addr));
}
__device__ __forceinline__ void mma_f16(float* d, const uint32_t* a, const uint32_t* b) {
  asm volatile(
      "mma.sync.aligned.m16n8k16.row.col.f32.f16.f16.f32 "
      "{%0,%1,%2,%3},{%4,%5,%6,%7},{%8,%9},{%0,%1,%2,%3};"
      : "+f"(d[0]), "+f"(d[1]), "+f"(d[2]), "+f"(d[3])
      : "r"(a[0]), "r"(a[1]), "r"(a[2]), "r"(a[3]), "r"(b[0]), "r"(b[1]));
}

// convert float4 -> 4 fp16 and store 8 bytes
__device__ __forceinline__ void store4h(float4 v, __half* dst, size_t off) {
  __half2 a = __floats2half2_rn(v.x, v.y);
  __half2 b = __floats2half2_rn(v.z, v.w);
  ((__half2*)(dst + off))[0] = a;
  ((__half2*)(dst + off))[1] = b;
}

__device__ __forceinline__ uint32_t ehash(int e) {
  return (((uint32_t)e * 2654435761u) >> 13) & (HTSZ - 1);
}

// ---------------- small kernels ----------------
__global__ void init_owner_kernel() {
  int i = blockIdx.x * blockDim.x + threadIdx.x;
  if (i < NNODES) g_owner[i] = -1;
}
__global__ void build_owner_kernel(const int* __restrict__ nodes, int B) {
  int i = blockIdx.x * blockDim.x + threadIdx.x;
  if (i < B) atomicMax(&g_owner[nodes[i]], i);
}

// ---------------- edge dedup ----------------
__global__ void dedup1_kernel(const int* __restrict__ eidx, int n) {
  int i = blockIdx.x * blockDim.x + threadIdx.x;
  if (i >= n) return;
  int e = eidx[i];
  uint32_t h = ehash(e);
  while (true) {
    int prev = atomicCAS(&g_ht[h], -1, e);
    if (prev == -1 || prev == e) break;
    h = (h + 1) & (HTSZ - 1);
  }
}
__global__ void dedup2_kernel() {
  int i = blockIdx.x * blockDim.x + threadIdx.x;
  if (i >= HTSZ) return;
  int e = g_ht[i];
  if (e != -1) {
    int uid = atomicAdd(&g_cnt, 1);
    g_uidtab[i] = uid;
    g_uelist[uid] = e;
  }
}
__global__ void dedup3_kernel(const int* __restrict__ eidx, int n) {
  int i = blockIdx.x * blockDim.x + threadIdx.x;
  if (i >= n) return;
  int e = eidx[i];
  uint32_t h = ehash(e);
  while (g_ht[h] != e) h = (h + 1) & (HTSZ - 1);
  g_map[i] = g_uidtab[h];
}

// ---------------- weight packing (fp16 single-limb) ----------------
struct PArgs {
  const float* w[3];
  int ld[3];
  int coff[3];
  const float* bias[3];
};
__global__ void pack_w_kernel(PArgs a, int nseg, __half* wq, float* pbias) {
  int i = blockIdx.x * blockDim.x + threadIdx.x;
  int tot = nseg * NSEG * KP;
  if (i >= tot) return;
  int n = i / KP, c = i - n * KP;
  int seg = n / NSEG, nr = n - seg * NSEG;
  float v = 0.f;
  if (nr < E_ && c < E_) v = a.w[seg][(size_t)nr * a.ld[seg] + a.coff[seg] + c];
  wq[i] = __float2half_rn(v);
  if (c == 0) pbias[n] = (nr < E_ && a.bias[seg]) ? a.bias[seg][nr] : 0.f;
}

// ---------------- vectorized converts (1 float4 per thread) ----------------
__global__ void convert_kernel(const float* __restrict__ X, int ldx,
                               const int* __restrict__ g1, int gmode,
                               int M, int Mpad, int rowoff) {
  int i = blockIdx.x * blockDim.x + threadIdx.x;
  if (i >= Mpad * C4) return;
  int r = i / C4, c4 = i - r * C4;
  float4 v = make_float4(0.f, 0.f, 0.f, 0.f);
  if (r < M && c4 < 43) {
    int src = (gmode >= 1) ? g1[r] : r;
    v = *(const float4*)(X + (size_t)src * ldx + c4 * 4);
  }
  store4h(v, g_A, (size_t)(rowoff + r) * KP + c4 * 4);
}

__global__ void convert_uedges_kernel(const float* __restrict__ ef) {
  int i = blockIdx.x * blockDim.x + threadIdx.x;
  if (i >= NSLOT * C4) return;
  int r = i / C4, c4 = i - r * C4;
  if (r >= g_cnt) return;
  float4 v = make_float4(0.f, 0.f, 0.f, 0.f);
  if (c4 < 43) v = *(const float4*)(ef + (size_t)g_uelist[r] * E_ + c4 * 4);
  store4h(v, g_A, (size_t)(R_EDGE + r) * KP + c4 * 4);
}

__global__ void timeconv_kernel(const float* __restrict__ ts,
                                const float* __restrict__ tw,
                                const float* __restrict__ tb, int B, int Mpad) {
  int i = blockIdx.x * blockDim.x + threadIdx.x;
  if (i >= Mpad * C4) return;
  int r = i / C4, c4 = i - r * C4;
  float4 v = make_float4(0.f, 0.f, 0.f, 0.f);
  if (r < B && c4 < 43) {
    float tval = ts[r];
    float4 w = *(const float4*)(tw + c4 * 4);
    float4 b = *(const float4*)(tb + c4 * 4);
    v.x = (float)cos((double)__fadd_rn(__fmul_rn(tval, w.x), b.x));
    v.y = (float)cos((double)__fadd_rn(__fmul_rn(tval, w.y), b.y));
    v.z = (float)cos((double)__fadd_rn(__fmul_rn(tval, w.z), b.z));
    v.w = (float)cos((double)__fadd_rn(__fmul_rn(tval, w.w), b.w));
  }
  store4h(v, g_A, (size_t)(R_TIME + r) * KP + c4 * 4);
}

// ---------------- pipelined fp16 HMMA GEMM (single pass) ----------------
#define BM 128
#define BN 96
#define ST 24
#define STAGE_A_B (BM * ST * 2)   // 6144
#define STAGE_B_B (BN * ST * 2)   // 4608
#define SM_A  0
#define SM_B  (SM_A + 4 * STAGE_A_B)
#define SMEM_G (SM_B + 4 * STAGE_B_B)  // 43008

__global__ __launch_bounds__(256, 2) void mma_gemm_kernel(
    const __half* __restrict__ A, const __half* __restrict__ W,
    const float* __restrict__ bias, float* __restrict__ out,
    __half* __restrict__ oh,
    int M, int ldout, int segstride, int nwrite, const int* __restrict__ Mptr) {
  if (Mptr) {
    M = *Mptr;
    if ((int)(blockIdx.y * BM) >= M) return;
  }
  extern __shared__ __align__(128) char smraw[];
  const uint32_t sm = (uint32_t)__cvta_generic_to_shared(smraw);
  const int tid = threadIdx.x;
  const int warp = tid >> 5, lane = tid & 31;
  const int m0 = blockIdx.y * BM;
  const int n0 = blockIdx.x * BN;
  const int wm0 = (warp >> 1) * 32;
  const int wn0 = (warp & 1) * 48;

  float acc[2][6][4];
#pragma unroll
  for (int i = 0; i < 2; i++)
#pragma unroll
    for (int j = 0; j < 6; j++)
#pragma unroll
      for (int k = 0; k < 4; k++) acc[i][j][k] = 0.f;

  const int lr = tid >> 1, lch = tid & 1;
  const size_t srcA = (size_t)(m0 + lr) * KP + lch * 8;
  const size_t srcB = (size_t)(n0 + lr) * KP + lch * 8;
  const uint32_t dstAoff = (uint32_t)((lr * ST + lch * 8) * 2);
  const uint32_t dstBoff = dstAoff;

#define LOAD_STAGE(buf, ki)                                                 \
  do {                                                                      \
    cpa16(sm + SM_A + (buf) * STAGE_A_B + dstAoff, A + srcA + (ki) * 16);   \
    if (tid < 2 * BN)                                                       \
      cpa16(sm + SM_B + (buf) * STAGE_B_B + dstBoff, W + srcB + (ki) * 16); \
  } while (0)

  LOAD_STAGE(0, 0); cpa_commit();
  LOAD_STAGE(1, 1); cpa_commit();
  LOAD_STAGE(2, 2); cpa_commit();

  const int aRow = (lane & 7) + ((lane >> 3) & 1) * 8;
  const int aCol = ((lane >> 4) & 1) * 8;
  const int bRow = (lane & 7) + ((lane >> 4) & 1) * 8;
  const int bCol = ((lane >> 3) & 1) * 8;

  for (int ki = 0; ki < KSTEPS; ki++) {
    const int buf = ki & 3;
    cpa_wait<2>();
    __syncthreads();
    if (ki + 3 < KSTEPS) LOAD_STAGE((ki + 3) & 3, ki + 3);
    cpa_commit();

    const uint32_t aB = sm + SM_A + buf * STAGE_A_B;
    const uint32_t bB = sm + SM_B + buf * STAGE_B_B;

    uint32_t af[2][4], bf[6][2];
#pragma unroll
    for (int ti = 0; ti < 2; ti++) {
      uint32_t off = (uint32_t)(((wm0 + ti * 16 + aRow) * ST + aCol) * 2);
      ldsm4(af[ti], aB + off);
    }
#pragma unroll
    for (int p = 0; p < 3; p++) {
      uint32_t off = (uint32_t)(((wn0 + p * 16 + bRow) * ST + bCol) * 2);
      uint32_t t[4];
      ldsm4(t, bB + off);
      bf[2 * p][0] = t[0]; bf[2 * p][1] = t[1];
      bf[2 * p + 1][0] = t[2]; bf[2 * p + 1][1] = t[3];
    }
#pragma unroll
    for (int ti = 0; ti < 2; ti++)
#pragma unroll
      for (int nj = 0; nj < 6; nj++)
        mma_f16(acc[ti][nj], af[ti], bf[nj]);
  }
#undef LOAD_STAGE

  const int g = lane >> 2, tq = lane & 3;
#pragma unroll
  for (int ti = 0; ti < 2; ti++) {
    int m = m0 + wm0 + ti * 16 + g;
#pragma unroll
    for (int nj = 0; nj < 6; nj++) {
      int n = n0 + wn0 + nj * 8 + tq * 2;
      int seg = n / NSEG, nr = n - seg * NSEG;
      if (nr >= nwrite) continue;
      int col = seg * segstride + nr;
      float b0 = bias[n], b1 = bias[n + 1];
#pragma unroll
      for (int half = 0; half < 2; half++) {
        int mm = m + half * 8;
        if (mm >= M) continue;
        float v0 = acc[ti][nj][2 * half] + b0;
        float v1 = acc[ti][nj][2 * half + 1] + b1;
        if (out) {
          *(float2*)(out + (size_t)mm * ldout + col) = make_float2(v0, v1);
        } else {
          *(__half2*)(oh + (size_t)mm * KP + col) = __floats2half2_rn(v0, v1);
        }
      }
    }
  }
}

// ---------------- attention (per sample), writes fp16 to R_O ----------------
template <int LAYER>
__global__ __launch_bounds__(256) void attn_kernel(const int* __restrict__ neighbors,
                                                   const int* __restrict__ nodes, int B) {
  __shared__ float q[E_];
  __shared__ __align__(16) float kk[KNB][E_];
  __shared__ float sc[HH][KNB];
  __shared__ float at[HH][KNB];
  __shared__ const float* akp[KNB];
  __shared__ const float* bkp[KNB];
  __shared__ int pad[KNB];

  const int b = blockIdx.x;
  const int tid = threadIdx.x;
  const float* trow = g_tqkv + (size_t)b * 576;

  if (tid < KNB) {
    int nb = neighbors[b * KNB + tid];
    pad[tid] = (nb == 0) ? 1 : 0;
    const float* ap = g_node_kv + (size_t)nb * 384;
    if (LAYER == 1) {
      int ow = g_owner[nb];
      if (ow >= 0) ap = g_l1out + (size_t)ow * 576 + 192;
    }
    akp[tid] = ap;
    bkp[tid] = g_edge_kv + (size_t)g_map[b * KNB + tid] * 384;
  }
  if (tid < E_) {
    float qh;
    if (LAYER == 0) {
      qh = g_qh[(size_t)b * KP + tid];
    } else {
      int ow = g_owner[nodes[b]];
      qh = g_l1out[(size_t)ow * 576 + tid];
    }
    q[tid] = qh + trow[tid];
  }
  __syncthreads();

  const float* tk = trow + NSEG;
  for (int idx = tid; idx < KNB * 43; idx += 256) {
    int j = idx / 43, c4 = idx - j * 43;
    float4 a = *(const float4*)(akp[j] + c4 * 4);
    float4 e = *(const float4*)(bkp[j] + c4 * 4);
    float4 t = *(const float4*)(tk + c4 * 4);
    *(float4*)(&kk[j][c4 * 4]) =
        make_float4(a.x + e.x + t.x, a.y + e.y + t.y, a.z + e.z + t.z, a.w + e.w + t.w);
  }
  if (tid == 0) {
    int all = 1;
#pragma unroll
    for (int j = 0; j < KNB; j++) all &= pad[j];
    if (all) pad[0] = 0;
  }
  __syncthreads();

  if (tid < HH * KNB) {
    int h = tid / KNB, j = tid - h * KNB;
    const float* qp = q + h * HD_;
    const float* kp = &kk[j][h * HD_];
    float sum = 0.f;
#pragma unroll
    for (int d = 0; d < HD_; d++) sum += qp[d] * kp[d];
    sum *= 0.10783277320343841f;
    if (pad[j]) sum = -1e9f;
    sc[h][j] = sum;
  }
  __syncthreads();

  if (tid < HH) {
    float m = -INFINITY;
#pragma unroll
    for (int j = 0; j < KNB; j++) m = fmaxf(m, sc[tid][j]);
    float ex[KNB], ssum = 0.f;
#pragma unroll
    for (int j = 0; j < KNB; j++) { ex[j] = expf(sc[tid][j] - m); ssum += ex[j]; }
    float inv = 1.f / ssum;
#pragma unroll
    for (int j = 0; j < KNB; j++) at[tid][j] = ex[j] * inv;
  }
  __syncthreads();

  if (tid < E_) {
    int h = tid / HD_;
    float o = trow[2 * NSEG + tid];
#pragma unroll
    for (int j = 0; j < KNB; j++)
      o += at[h][j] * (akp[j][NSEG + tid] + bkp[j][NSEG + tid]);
    g_A[(size_t)(R_O + b) * KP + tid] = __float2half_rn(o);
  }
}

// ---------------- launch ----------------
static inline int cdiv(int a, int b) { return (a + b - 1) / b; }

extern "C" void kernel_launch(void* const* d_in, const int* in_sizes, int n_in,
                              void* d_out, int out_size) {
  const int* nodes     = (const int*)d_in[0];
  const float* ts      = (const float*)d_in[1];
  const int* neighbors = (const int*)d_in[2];
  const int* eidx      = (const int*)d_in[3];
  const float* nf      = (const float*)d_in[4];
  const float* ef      = (const float*)d_in[5];
  const float* time_w  = (const float*)d_in[6];
  const float* time_b  = (const float*)d_in[7];
  const float* q_w     = (const float*)d_in[8];
  const float* k_w     = (const float*)d_in[9];
  const float* v_w     = (const float*)d_in[10];
  const float* bq      = (const float*)d_in[11];
  const float* bk      = (const float*)d_in[12];
  const float* bv      = (const float*)d_in[13];
  const float* out_w   = (const float*)d_in[14];
  const float* out_b   = (const float*)d_in[15];
  float* out = (float*)d_out;
  const int B = in_sizes[0];

  __half *pW, *pA, *pH1;
  float *pWb, *pzb, *ptqkv, *pnodekv, *pedgekv, *pl1out, *pqh;
  int *pht, *pcnt;
  cudaGetSymbolAddress((void**)&pW, g_W);
  cudaGetSymbolAddress((void**)&pWb, g_Wb);
  cudaGetSymbolAddress((void**)&pzb, g_zbias);
  cudaGetSymbolAddress((void**)&pA, g_A);
  cudaGetSymbolAddress((void**)&pH1, g_H1);
  cudaGetSymbolAddress((void**)&ptqkv, g_tqkv);
  cudaGetSymbolAddress((void**)&pnodekv, g_node_kv);
  cudaGetSymbolAddress((void**)&pedgekv, g_edge_kv);
  cudaGetSymbolAddress((void**)&pl1out, g_l1out);
  cudaGetSymbolAddress((void**)&pqh, g_qh);
  cudaGetSymbolAddress((void**)&pht, g_ht);
  cudaGetSymbolAddress((void**)&pcnt, g_cnt);

  cudaFuncSetAttribute(mma_gemm_kernel, cudaFuncAttributeMaxDynamicSharedMemorySize, SMEM_G);

  static cudaStream_t s1 = nullptr;
  static cudaEvent_t evF = nullptr, evA, evB, evC, evD;
  if (!s1) {
    cudaStreamCreateWithFlags(&s1, cudaStreamNonBlocking);
    cudaEventCreateWithFlags(&evF, cudaEventDisableTiming);
    cudaEventCreateWithFlags(&evA, cudaEventDisableTiming);
    cudaEventCreateWithFlags(&evB, cudaEventDisableTiming);
    cudaEventCreateWithFlags(&evC, cudaEventDisableTiming);
    cudaEventCreateWithFlags(&evD, cudaEventDisableTiming);
  }
  cudaStream_t s0 = 0;

  PArgs p;

#define GEMMF(Mpad, Npad, poff, Aoff, outp, M, ldo, segs, nw, Mptr)           \
  mma_gemm_kernel<<<dim3((Npad) / BN, (Mpad) / BM), 256, SMEM_G, s0>>>(       \
      pA + (size_t)(Aoff) * KP, pW + (size_t)(poff) * KP,                     \
      pWb + (poff), outp, nullptr, M, ldo, segs, nw, Mptr)

  // fork s1 from the capture stream
  cudaEventRecord(evF, s0);
  cudaStreamWaitEvent(s1, evF, 0);

  // ---- s1: prep, ordered by when s0 consumes it ----
  // group A: tqkv weights + time convert
  p.w[0] = q_w; p.ld[0] = E_;     p.coff[0] = 0; p.bias[0] = bq;
  p.w[1] = k_w; p.ld[1] = 2 * E_; p.coff[1] = 0; p.bias[1] = bk;
  p.w[2] = v_w; p.ld[2] = 2 * E_; p.coff[2] = 0; p.bias[2] = bv;
  pack_w_kernel<<<cdiv(3 * NSEG * KP, 256), 256, 0, s1>>>(p, 3, pW + (size_t)P1_OFF * KP, pWb + P1_OFF);
  timeconv_kernel<<<cdiv(BPAD * C4, 256), 256, 0, s1>>>(ts, time_w, time_b, B, BPAD);
  cudaEventRecord(evA, s1);
  // group B: node weights + node convert
  p.w[0] = k_w; p.ld[0] = 2 * E_; p.coff[0] = 0; p.bias[0] = nullptr;
  p.w[1] = v_w; p.ld[1] = 2 * E_; p.coff[1] = 0; p.bias[1] = nullptr;
  p.w[2] = nullptr; p.ld[2] = 0; p.coff[2] = 0; p.bias[2] = nullptr;
  pack_w_kernel<<<cdiv(2 * NSEG * KP, 256), 256, 0, s1>>>(p, 2, pW + (size_t)P2_OFF * KP, pWb + P2_OFF);
  convert_kernel<<<cdiv(NPADN * C4, 256), 256, 0, s1>>>(nf, E_, nullptr, 0, NNODES, NPADN, R_NODE);
  cudaEventRecord(evB, s1);
  // group C: edge dedup + edge weights + edge convert
  cudaMemsetAsync(pht, 0xFF, (size_t)HTSZ * sizeof(int), s1);
  cudaMemsetAsync(pcnt, 0, sizeof(int), s1);
  dedup1_kernel<<<cdiv(B * KNB, 256), 256, 0, s1>>>(eidx, B * KNB);
  dedup2_kernel<<<cdiv(HTSZ, 256), 256, 0, s1>>>();
  p.w[0] = k_w; p.ld[0] = 2 * E_; p.coff[0] = E_; p.bias[0] = nullptr;
  p.w[1] = v_w; p.ld[1] = 2 * E_; p.coff[1] = E_; p.bias[1] = nullptr;
  p.w[2] = nullptr;
  pack_w_kernel<<<cdiv(2 * NSEG * KP, 256), 256, 0, s1>>>(p, 2, pW + (size_t)P3_OFF * KP, pWb + P3_OFF);
  convert_uedges_kernel<<<cdiv(NSLOT * C4, 256), 256, 0, s1>>>(ef);
  cudaEventRecord(evC, s1);
  // group D: dedup map, owner init, q/out weight packs, L0 q convert
  dedup3_kernel<<<cdiv(B * KNB, 256), 256, 0, s1>>>(eidx, B * KNB);
  init_owner_kernel<<<cdiv(NNODES, 256), 256, 0, s1>>>();
  p.w[0] = q_w; p.ld[0] = E_; p.coff[0] = 0; p.bias[0] = nullptr;
  p.w[1] = nullptr; p.w[2] = nullptr;
  pack_w_kernel<<<cdiv(NSEG * KP, 256), 256, 0, s1>>>(p, 1, pW + (size_t)P4_OFF * KP, pWb + P4_OFF);
  p.w[0] = out_w; p.bias[0] = out_b;
  pack_w_kernel<<<cdiv(NSEG * KP, 256), 256, 0, s1>>>(p, 1, pW + (size_t)P5_OFF * KP, pWb + P5_OFF);
  convert_kernel<<<cdiv(BPAD * C4, 256), 256, 0, s1>>>(nf, E_, nodes, 1, B, BPAD, R_Q0);
  cudaEventRecord(evD, s1);

  // ---- s0: GEMM chain + attention ----
  cudaStreamWaitEvent(s0, evA, 0);
  GEMMF(BPAD, 576, P1_OFF, R_TIME, ptqkv, B, 576, NSEG, NSEG, nullptr);
  cudaStreamWaitEvent(s0, evB, 0);
  GEMMF(NPADN, 384, P2_OFF, R_NODE, pnodekv, NNODES, 384, NSEG, NSEG, nullptr);
  cudaStreamWaitEvent(s0, evC, 0);
  GEMMF(NSLOT, 384, P3_OFF, R_EDGE, pedgekv, B * KNB, 384, NSEG, NSEG, pcnt);
  cudaStreamWaitEvent(s0, evD, 0);

  // layer 0
  GEMMF(BPAD, NSEG, P4_OFF, R_Q0, pqh, B, KP, 0, KP, nullptr);
  attn_kernel<0><<<B, 256, 0, s0>>>(neighbors, nodes, B);
  // out-proj -> H1 (fp16)
  mma_gemm_kernel<<<dim3(NSEG / BN, BPAD / BM), 256, SMEM_G, s0>>>(
      pA + (size_t)R_O * KP, pW + (size_t)P5_OFF * KP,
      pWb + P5_OFF, nullptr, pH1, B, KP, 0, KP, nullptr);
  build_owner_kernel<<<cdiv(B, 256), 256, 0, s0>>>(nodes, B);

  // layer 1: merged H1 @ [q|kE|vE]  (zero bias; biases live on the t-side)
  mma_gemm_kernel<<<dim3(576 / BN, BPAD / BM), 256, SMEM_G, s0>>>(
      pH1, pW + (size_t)P1_OFF * KP,
      pzb, pl1out, nullptr, B, 576, NSEG, NSEG, nullptr);
  attn_kernel<1><<<B, 256, 0, s0>>>(neighbors, nodes, B);
  GEMMF(BPAD, NSEG, P5_OFF, R_O, out, B, E_, 0, E_, nullptr);
#undef GEMMF
}

// round 14
// speedup vs baseline: 2.6936x; 1.0654x over previous
#include <cuda_runtime.h>
#include <cuda_fp16.h>
#include <math.h>
#include <stdint.h>

#define E_ 172
#define KP 176            // padded K (11 k16 steps)
#define KSTEPS 11
#define C4 (KP / 4)       // 44 float4 chunks per row (chunk 43 = zeros)
#define NSEG 192
#define KNB 20
#define HH 2
#define HD_ 86
#define NNODES 100000
#define BMAX 12000
#define BPAD 12032
#define NPADN 100096
#define NSLOT 240000
#define HTSZ (1 << 19)

// disjoint A-buffer row regions (for cross-stream overlap)
#define R_EDGE 0
#define R_TIME 240000
#define R_NODE 252032                 // R_TIME + BPAD
#define R_Q0   352128                 // R_NODE + NPADN
#define R_O    364160                 // R_Q0 + BPAD
#define AROWS  376192                 // R_O + BPAD

#define P1_OFF 0
#define P2_OFF 576
#define P3_OFF 960
#define P4_OFF 1344
#define P5_OFF 1536
#define PTOT 1728

// ---------------- scratch ----------------
__device__ __half g_A[(size_t)AROWS * KP];         // fp16 activations
__device__ __half g_W[(size_t)PTOT * KP];          // fp16 weights
__device__ float g_Wb[PTOT];
__device__ float g_zbias[576];                     // statically zero

__device__ float g_tqkv[BMAX * 576];               // fp32 (small, holds biases)
__device__ __half g_node_kv[(size_t)NNODES * 384]; // fp16 kv intermediates
__device__ __half g_edge_kv[(size_t)NSLOT * 384];
__device__ __half g_l1out[BMAX * 576];             // layer-1 merged [q|k|v] of H1
__device__ float g_qh[BMAX * KP];
__device__ __half g_H1[BPAD * KP];                 // layer-0 output h1 (fp16)
__device__ int g_owner[NNODES];

__device__ int g_ht[HTSZ];
__device__ int g_uidtab[HTSZ];
__device__ int g_uelist[NSLOT];
__device__ int g_map[NSLOT];
__device__ int g_cnt;

// ---------------- helpers ----------------
__device__ __forceinline__ void cpa16(uint32_t dst, const void* src) {
  asm volatile("cp.async.cg.shared.global [%0], [%1], 16;" :: "r"(dst), "l"(src));
}
__device__ __forceinline__ void cpa_commit() { asm volatile("cp.async.commit_group;" ::: "memory"); }
template <int N>
__device__ __forceinline__ void cpa_wait() { asm volatile("cp.async.wait_group %0;" :: "n"(N) : "memory"); }

__device__ __forceinline__ void ldsm4(uint32_t* r, uint32_t addr) {
  asm volatile("ldmatrix.sync.aligned.m8n8.x4.shared.b16 {%0,%1,%2,%3}, [%4];"
               : "=r"(r[0]), "=r"(r[1]), "=r"(r[2]), "=r"(r[3]) : "r"(addr));
}
__device__ __forceinline__ void mma_f16(float* d, const uint32_t* a, const uint32_t* b) {
  asm volatile(
      "mma.sync.aligned.m16n8k16.row.col.f32.f16.f16.f32 "
      "{%0,%1,%2,%3},{%4,%5,%6,%7},{%8,%9},{%0,%1,%2,%3};"
      : "+f"(d[0]), "+f"(d[1]), "+f"(d[2]), "+f"(d[3])
      : "r"(a[0]), "r"(a[1]), "r"(a[2]), "r"(a[3]), "r"(b[0]), "r"(b[1]));
}

__device__ __forceinline__ void store4h(float4 v, __half* dst, size_t off) {
  __half2 a = __floats2half2_rn(v.x, v.y);
  __half2 b = __floats2half2_rn(v.z, v.w);
  ((__half2*)(dst + off))[0] = a;
  ((__half2*)(dst + off))[1] = b;
}

__device__ __forceinline__ uint32_t ehash(int e) {
  return (((uint32_t)e * 2654435761u) >> 13) & (HTSZ - 1);
}

// ---------------- small kernels ----------------
__global__ void init_owner_kernel() {
  int i = blockIdx.x * blockDim.x + threadIdx.x;
  if (i < NNODES) g_owner[i] = -1;
}
__global__ void build_owner_kernel(const int* __restrict__ nodes, int B) {
  int i = blockIdx.x * blockDim.x + threadIdx.x;
  if (i < B) atomicMax(&g_owner[nodes[i]], i);
}

// ---------------- edge dedup ----------------
__global__ void dedup1_kernel(const int* __restrict__ eidx, int n) {
  int i = blockIdx.x * blockDim.x + threadIdx.x;
  if (i >= n) return;
  int e = eidx[i];
  uint32_t h = ehash(e);
  while (true) {
    int prev = atomicCAS(&g_ht[h], -1, e);
    if (prev == -1 || prev == e) break;
    h = (h + 1) & (HTSZ - 1);
  }
}
__global__ void dedup2_kernel() {
  int i = blockIdx.x * blockDim.x + threadIdx.x;
  if (i >= HTSZ) return;
  int e = g_ht[i];
  if (e != -1) {
    int uid = atomicAdd(&g_cnt, 1);
    g_uidtab[i] = uid;
    g_uelist[uid] = e;
  }
}
__global__ void dedup3_kernel(const int* __restrict__ eidx, int n) {
  int i = blockIdx.x * blockDim.x + threadIdx.x;
  if (i >= n) return;
  int e = eidx[i];
  uint32_t h = ehash(e);
  while (g_ht[h] != e) h = (h + 1) & (HTSZ - 1);
  g_map[i] = g_uidtab[h];
}

// ---------------- weight packing ----------------
struct PArgs {
  const float* w[3];
  int ld[3];
  int coff[3];
  const float* bias[3];
};
__global__ void pack_w_kernel(PArgs a, int nseg, __half* wq, float* pbias) {
  int i = blockIdx.x * blockDim.x + threadIdx.x;
  int tot = nseg * NSEG * KP;
  if (i >= tot) return;
  int n = i / KP, c = i - n * KP;
  int seg = n / NSEG, nr = n - seg * NSEG;
  float v = 0.f;
  if (nr < E_ && c < E_) v = a.w[seg][(size_t)nr * a.ld[seg] + a.coff[seg] + c];
  wq[i] = __float2half_rn(v);
  if (c == 0) pbias[n] = (nr < E_ && a.bias[seg]) ? a.bias[seg][nr] : 0.f;
}

// ---------------- vectorized converts ----------------
__global__ void convert_kernel(const float* __restrict__ X, int ldx,
                               const int* __restrict__ g1, int gmode,
                               int M, int Mpad, int rowoff) {
  int i = blockIdx.x * blockDim.x + threadIdx.x;
  if (i >= Mpad * C4) return;
  int r = i / C4, c4 = i - r * C4;
  float4 v = make_float4(0.f, 0.f, 0.f, 0.f);
  if (r < M && c4 < 43) {
    int src = (gmode >= 1) ? g1[r] : r;
    v = *(const float4*)(X + (size_t)src * ldx + c4 * 4);
  }
  store4h(v, g_A, (size_t)(rowoff + r) * KP + c4 * 4);
}

__global__ void convert_uedges_kernel(const float* __restrict__ ef) {
  int i = blockIdx.x * blockDim.x + threadIdx.x;
  if (i >= NSLOT * C4) return;
  int r = i / C4, c4 = i - r * C4;
  if (r >= g_cnt) return;
  float4 v = make_float4(0.f, 0.f, 0.f, 0.f);
  if (c4 < 43) v = *(const float4*)(ef + (size_t)g_uelist[r] * E_ + c4 * 4);
  store4h(v, g_A, (size_t)(R_EDGE + r) * KP + c4 * 4);
}

__global__ void timeconv_kernel(const float* __restrict__ ts,
                                const float* __restrict__ tw,
                                const float* __restrict__ tb, int B, int Mpad) {
  int i = blockIdx.x * blockDim.x + threadIdx.x;
  if (i >= Mpad * C4) return;
  int r = i / C4, c4 = i - r * C4;
  float4 v = make_float4(0.f, 0.f, 0.f, 0.f);
  if (r < B && c4 < 43) {
    float tval = ts[r];
    float4 w = *(const float4*)(tw + c4 * 4);
    float4 b = *(const float4*)(tb + c4 * 4);
    v.x = (float)cos((double)__fadd_rn(__fmul_rn(tval, w.x), b.x));
    v.y = (float)cos((double)__fadd_rn(__fmul_rn(tval, w.y), b.y));
    v.z = (float)cos((double)__fadd_rn(__fmul_rn(tval, w.z), b.z));
    v.w = (float)cos((double)__fadd_rn(__fmul_rn(tval, w.w), b.w));
  }
  store4h(v, g_A, (size_t)(R_TIME + r) * KP + c4 * 4);
}

// ---------------- pipelined fp16 HMMA GEMM (single pass) ----------------
#define BM 128
#define BN 96
#define ST 24
#define STAGE_A_B (BM * ST * 2)
#define STAGE_B_B (BN * ST * 2)
#define SM_A  0
#define SM_B  (SM_A + 4 * STAGE_A_B)
#define SMEM_G (SM_B + 4 * STAGE_B_B)  // 43008

__global__ __launch_bounds__(256, 2) void mma_gemm_kernel(
    const __half* __restrict__ A, const __half* __restrict__ W,
    const float* __restrict__ bias, float* __restrict__ outf,
    __half* __restrict__ outh,
    int M, int ldout, int segstride, int nwrite, const int* __restrict__ Mptr) {
  if (Mptr) {
    M = *Mptr;
    if ((int)(blockIdx.y * BM) >= M) return;
  }
  extern __shared__ __align__(128) char smraw[];
  const uint32_t sm = (uint32_t)__cvta_generic_to_shared(smraw);
  const int tid = threadIdx.x;
  const int warp = tid >> 5, lane = tid & 31;
  const int m0 = blockIdx.y * BM;
  const int n0 = blockIdx.x * BN;
  const int wm0 = (warp >> 1) * 32;
  const int wn0 = (warp & 1) * 48;

  float acc[2][6][4];
#pragma unroll
  for (int i = 0; i < 2; i++)
#pragma unroll
    for (int j = 0; j < 6; j++)
#pragma unroll
      for (int k = 0; k < 4; k++) acc[i][j][k] = 0.f;

  const int lr = tid >> 1, lch = tid & 1;
  const size_t srcA = (size_t)(m0 + lr) * KP + lch * 8;
  const size_t srcB = (size_t)(n0 + lr) * KP + lch * 8;
  const uint32_t dstAoff = (uint32_t)((lr * ST + lch * 8) * 2);
  const uint32_t dstBoff = dstAoff;

#define LOAD_STAGE(buf, ki)                                                 \
  do {                                                                      \
    cpa16(sm + SM_A + (buf) * STAGE_A_B + dstAoff, A + srcA + (ki) * 16);   \
    if (tid < 2 * BN)                                                       \
      cpa16(sm + SM_B + (buf) * STAGE_B_B + dstBoff, W + srcB + (ki) * 16); \
  } while (0)

  LOAD_STAGE(0, 0); cpa_commit();
  LOAD_STAGE(1, 1); cpa_commit();
  LOAD_STAGE(2, 2); cpa_commit();

  const int aRow = (lane & 7) + ((lane >> 3) & 1) * 8;
  const int aCol = ((lane >> 4) & 1) * 8;
  const int bRow = (lane & 7) + ((lane >> 4) & 1) * 8;
  const int bCol = ((lane >> 3) & 1) * 8;

  for (int ki = 0; ki < KSTEPS; ki++) {
    const int buf = ki & 3;
    cpa_wait<2>();
    __syncthreads();
    if (ki + 3 < KSTEPS) LOAD_STAGE((ki + 3) & 3, ki + 3);
    cpa_commit();

    const uint32_t aB = sm + SM_A + buf * STAGE_A_B;
    const uint32_t bB = sm + SM_B + buf * STAGE_B_B;

    uint32_t af[2][4], bf[6][2];
#pragma unroll
    for (int ti = 0; ti < 2; ti++) {
      uint32_t off = (uint32_t)(((wm0 + ti * 16 + aRow) * ST + aCol) * 2);
      ldsm4(af[ti], aB + off);
    }
#pragma unroll
    for (int p = 0; p < 3; p++) {
      uint32_t off = (uint32_t)(((wn0 + p * 16 + bRow) * ST + bCol) * 2);
      uint32_t t[4];
      ldsm4(t, bB + off);
      bf[2 * p][0] = t[0]; bf[2 * p][1] = t[1];
      bf[2 * p + 1][0] = t[2]; bf[2 * p + 1][1] = t[3];
    }
#pragma unroll
    for (int ti = 0; ti < 2; ti++)
#pragma unroll
      for (int nj = 0; nj < 6; nj++)
        mma_f16(acc[ti][nj], af[ti], bf[nj]);
  }
#undef LOAD_STAGE

  const int g = lane >> 2, tq = lane & 3;
#pragma unroll
  for (int ti = 0; ti < 2; ti++) {
    int m = m0 + wm0 + ti * 16 + g;
#pragma unroll
    for (int nj = 0; nj < 6; nj++) {
      int n = n0 + wn0 + nj * 8 + tq * 2;
      int seg = n / NSEG, nr = n - seg * NSEG;
      if (nr >= nwrite) continue;
      int col = seg * segstride + nr;
      float b0 = bias[n], b1 = bias[n + 1];
#pragma unroll
      for (int half = 0; half < 2; half++) {
        int mm = m + half * 8;
        if (mm >= M) continue;
        float v0 = acc[ti][nj][2 * half] + b0;
        float v1 = acc[ti][nj][2 * half + 1] + b1;
        if (outf) {
          *(float2*)(outf + (size_t)mm * ldout + col) = make_float2(v0, v1);
        } else {
          *(__half2*)(outh + (size_t)mm * ldout + col) = __floats2half2_rn(v0, v1);
        }
      }
    }
  }
}

// ---------------- attention (per sample), writes fp16 to R_O ----------------
// kv sources are fp16: node_kv / edge_kv / l1out(+192). t terms fp32.
template <int LAYER>
__global__ __launch_bounds__(256) void attn_kernel(const int* __restrict__ neighbors,
                                                   const int* __restrict__ nodes, int B) {
  __shared__ float q[E_];
  __shared__ __align__(16) float kk[KNB][E_];
  __shared__ float sc[HH][KNB];
  __shared__ float at[HH][KNB];
  __shared__ const __half* akp[KNB];
  __shared__ const __half* bkp[KNB];
  __shared__ int pad[KNB];

  const int b = blockIdx.x;
  const int tid = threadIdx.x;
  const float* trow = g_tqkv + (size_t)b * 576;

  if (tid < KNB) {
    int nb = neighbors[b * KNB + tid];
    pad[tid] = (nb == 0) ? 1 : 0;
    const __half* ap = g_node_kv + (size_t)nb * 384;
    if (LAYER == 1) {
      int ow = g_owner[nb];
      if (ow >= 0) ap = g_l1out + (size_t)ow * 576 + 192;
    }
    akp[tid] = ap;
    bkp[tid] = g_edge_kv + (size_t)g_map[b * KNB + tid] * 384;
  }
  if (tid < E_) {
    float qh;
    if (LAYER == 0) {
      qh = g_qh[(size_t)b * KP + tid];
    } else {
      int ow = g_owner[nodes[b]];
      qh = __half2float(g_l1out[(size_t)ow * 576 + tid]);
    }
    q[tid] = qh + trow[tid];
  }
  __syncthreads();

  const float* tk = trow + NSEG;
  for (int idx = tid; idx < KNB * 43; idx += 256) {
    int j = idx / 43, c4 = idx - j * 43;
    const __half2* a2 = (const __half2*)(akp[j] + c4 * 4);
    const __half2* e2 = (const __half2*)(bkp[j] + c4 * 4);
    float2 a0 = __half22float2(a2[0]), a1 = __half22float2(a2[1]);
    float2 e0 = __half22float2(e2[0]), e1 = __half22float2(e2[1]);
    float4 t = *(const float4*)(tk + c4 * 4);
    float* dst = &kk[j][c4 * 4];
    dst[0] = a0.x + e0.x + t.x;
    dst[1] = a0.y + e0.y + t.y;
    dst[2] = a1.x + e1.x + t.z;
    dst[3] = a1.y + e1.y + t.w;
  }
  if (tid == 0) {
    int all = 1;
#pragma unroll
    for (int j = 0; j < KNB; j++) all &= pad[j];
    if (all) pad[0] = 0;
  }
  __syncthreads();

  if (tid < HH * KNB) {
    int h = tid / KNB, j = tid - h * KNB;
    const float* qp = q + h * HD_;
    const float* kp = &kk[j][h * HD_];
    float sum = 0.f;
#pragma unroll
    for (int d = 0; d < HD_; d++) sum += qp[d] * kp[d];
    sum *= 0.10783277320343841f;
    if (pad[j]) sum = -1e9f;
    sc[h][j] = sum;
  }
  __syncthreads();

  if (tid < HH) {
    float m = -INFINITY;
#pragma unroll
    for (int j = 0; j < KNB; j++) m = fmaxf(m, sc[tid][j]);
    float ex[KNB], ssum = 0.f;
#pragma unroll
    for (int j = 0; j < KNB; j++) { ex[j] = expf(sc[tid][j] - m); ssum += ex[j]; }
    float inv = 1.f / ssum;
#pragma unroll
    for (int j = 0; j < KNB; j++) at[tid][j] = ex[j] * inv;
  }
  __syncthreads();

  if (tid < E_) {
    int h = tid / HD_;
    float o = trow[2 * NSEG + tid];
#pragma unroll
    for (int j = 0; j < KNB; j++)
      o += at[h][j] * (__half2float(akp[j][NSEG + tid]) + __half2float(bkp[j][NSEG + tid]));
    g_A[(size_t)(R_O + b) * KP + tid] = __float2half_rn(o);
  }
}

// ---------------- launch ----------------
static inline int cdiv(int a, int b) { return (a + b - 1) / b; }

extern "C" void kernel_launch(void* const* d_in, const int* in_sizes, int n_in,
                              void* d_out, int out_size) {
  const int* nodes     = (const int*)d_in[0];
  const float* ts      = (const float*)d_in[1];
  const int* neighbors = (const int*)d_in[2];
  const int* eidx      = (const int*)d_in[3];
  const float* nf      = (const float*)d_in[4];
  const float* ef      = (const float*)d_in[5];
  const float* time_w  = (const float*)d_in[6];
  const float* time_b  = (const float*)d_in[7];
  const float* q_w     = (const float*)d_in[8];
  const float* k_w     = (const float*)d_in[9];
  const float* v_w     = (const float*)d_in[10];
  const float* bq      = (const float*)d_in[11];
  const float* bk      = (const float*)d_in[12];
  const float* bv      = (const float*)d_in[13];
  const float* out_w   = (const float*)d_in[14];
  const float* out_b   = (const float*)d_in[15];
  float* out = (float*)d_out;
  const int B = in_sizes[0];

  __half *pW, *pA, *pH1, *pnodekv, *pedgekv, *pl1out;
  float *pWb, *pzb, *ptqkv, *pqh;
  int *pht, *pcnt;
  cudaGetSymbolAddress((void**)&pW, g_W);
  cudaGetSymbolAddress((void**)&pWb, g_Wb);
  cudaGetSymbolAddress((void**)&pzb, g_zbias);
  cudaGetSymbolAddress((void**)&pA, g_A);
  cudaGetSymbolAddress((void**)&pH1, g_H1);
  cudaGetSymbolAddress((void**)&ptqkv, g_tqkv);
  cudaGetSymbolAddress((void**)&pnodekv, g_node_kv);
  cudaGetSymbolAddress((void**)&pedgekv, g_edge_kv);
  cudaGetSymbolAddress((void**)&pl1out, g_l1out);
  cudaGetSymbolAddress((void**)&pqh, g_qh);
  cudaGetSymbolAddress((void**)&pht, g_ht);
  cudaGetSymbolAddress((void**)&pcnt, g_cnt);

  cudaFuncSetAttribute(mma_gemm_kernel, cudaFuncAttributeMaxDynamicSharedMemorySize, SMEM_G);

  static cudaStream_t s1 = nullptr;
  static cudaEvent_t evF = nullptr, evA, evB, evC, evD;
  if (!s1) {
    cudaStreamCreateWithFlags(&s1, cudaStreamNonBlocking);
    cudaEventCreateWithFlags(&evF, cudaEventDisableTiming);
    cudaEventCreateWithFlags(&evA, cudaEventDisableTiming);
    cudaEventCreateWithFlags(&evB, cudaEventDisableTiming);
    cudaEventCreateWithFlags(&evC, cudaEventDisableTiming);
    cudaEventCreateWithFlags(&evD, cudaEventDisableTiming);
  }
  cudaStream_t s0 = 0;

  PArgs p;

#define GEMM_F(Mpad, Npad, poff, Aoff, outp, M, ldo, segs, nw, Mptr)          \
  mma_gemm_kernel<<<dim3((Npad) / BN, (Mpad) / BM), 256, SMEM_G, s0>>>(       \
      pA + (size_t)(Aoff) * KP, pW + (size_t)(poff) * KP,                     \
      pWb + (poff), outp, nullptr, M, ldo, segs, nw, Mptr)
#define GEMM_H(Mpad, Npad, poff, Aoff, outp, M, ldo, segs, nw, Mptr)          \
  mma_gemm_kernel<<<dim3((Npad) / BN, (Mpad) / BM), 256, SMEM_G, s0>>>(       \
      pA + (size_t)(Aoff) * KP, pW + (size_t)(poff) * KP,                     \
      pWb + (poff), nullptr, outp, M, ldo, segs, nw, Mptr)

  // fork s1 from the capture stream
  cudaEventRecord(evF, s0);
  cudaStreamWaitEvent(s1, evF, 0);

  // ---- s1: prep, ordered by when s0 consumes it ----
  // group A: tqkv weights + time convert
  p.w[0] = q_w; p.ld[0] = E_;     p.coff[0] = 0; p.bias[0] = bq;
  p.w[1] = k_w; p.ld[1] = 2 * E_; p.coff[1] = 0; p.bias[1] = bk;
  p.w[2] = v_w; p.ld[2] = 2 * E_; p.coff[2] = 0; p.bias[2] = bv;
  pack_w_kernel<<<cdiv(3 * NSEG * KP, 256), 256, 0, s1>>>(p, 3, pW + (size_t)P1_OFF * KP, pWb + P1_OFF);
  timeconv_kernel<<<cdiv(BPAD * C4, 256), 256, 0, s1>>>(ts, time_w, time_b, B, BPAD);
  cudaEventRecord(evA, s1);
  // group B: node weights + node convert
  p.w[0] = k_w; p.ld[0] = 2 * E_; p.coff[0] = 0; p.bias[0] = nullptr;
  p.w[1] = v_w; p.ld[1] = 2 * E_; p.coff[1] = 0; p.bias[1] = nullptr;
  p.w[2] = nullptr; p.ld[2] = 0; p.coff[2] = 0; p.bias[2] = nullptr;
  pack_w_kernel<<<cdiv(2 * NSEG * KP, 256), 256, 0, s1>>>(p, 2, pW + (size_t)P2_OFF * KP, pWb + P2_OFF);
  convert_kernel<<<cdiv(NPADN * C4, 256), 256, 0, s1>>>(nf, E_, nullptr, 0, NNODES, NPADN, R_NODE);
  cudaEventRecord(evB, s1);
  // group C: edge dedup + edge weights + edge convert
  cudaMemsetAsync(pht, 0xFF, (size_t)HTSZ * sizeof(int), s1);
  cudaMemsetAsync(pcnt, 0, sizeof(int), s1);
  dedup1_kernel<<<cdiv(B * KNB, 256), 256, 0, s1>>>(eidx, B * KNB);
  dedup2_kernel<<<cdiv(HTSZ, 256), 256, 0, s1>>>();
  p.w[0] = k_w; p.ld[0] = 2 * E_; p.coff[0] = E_; p.bias[0] = nullptr;
  p.w[1] = v_w; p.ld[1] = 2 * E_; p.coff[1] = E_; p.bias[1] = nullptr;
  p.w[2] = nullptr;
  pack_w_kernel<<<cdiv(2 * NSEG * KP, 256), 256, 0, s1>>>(p, 2, pW + (size_t)P3_OFF * KP, pWb + P3_OFF);
  convert_uedges_kernel<<<cdiv(NSLOT * C4, 256), 256, 0, s1>>>(ef);
  cudaEventRecord(evC, s1);
  // group D: dedup map, owner init, q/out weight packs, L0 q convert
  dedup3_kernel<<<cdiv(B * KNB, 256), 256, 0, s1>>>(eidx, B * KNB);
  init_owner_kernel<<<cdiv(NNODES, 256), 256, 0, s1>>>();
  p.w[0] = q_w; p.ld[0] = E_; p.coff[0] = 0; p.bias[0] = nullptr;
  p.w[1] = nullptr; p.w[2] = nullptr;
  pack_w_kernel<<<cdiv(NSEG * KP, 256), 256, 0, s1>>>(p, 1, pW + (size_t)P4_OFF * KP, pWb + P4_OFF);
  p.w[0] = out_w; p.bias[0] = out_b;
  pack_w_kernel<<<cdiv(NSEG * KP, 256), 256, 0, s1>>>(p, 1, pW + (size_t)P5_OFF * KP, pWb + P5_OFF);
  convert_kernel<<<cdiv(BPAD * C4, 256), 256, 0, s1>>>(nf, E_, nodes, 1, B, BPAD, R_Q0);
  cudaEventRecord(evD, s1);

  // ---- s0: GEMM chain + attention ----
  cudaStreamWaitEvent(s0, evA, 0);
  GEMM_F(BPAD, 576, P1_OFF, R_TIME, ptqkv, B, 576, NSEG, NSEG, nullptr);
  cudaStreamWaitEvent(s0, evB, 0);
  GEMM_H(NPADN, 384, P2_OFF, R_NODE, pnodekv, NNODES, 384, NSEG, NSEG, nullptr);
  cudaStreamWaitEvent(s0, evC, 0);
  GEMM_H(NSLOT, 384, P3_OFF, R_EDGE, pedgekv, B * KNB, 384, NSEG, NSEG, pcnt);
  cudaStreamWaitEvent(s0, evD, 0);

  // layer 0
  GEMM_F(BPAD, NSEG, P4_OFF, R_Q0, pqh, B, KP, 0, KP, nullptr);
  attn_kernel<0><<<B, 256, 0, s0>>>(neighbors, nodes, B);
  GEMM_H(BPAD, NSEG, P5_OFF, R_O, pH1, B, KP, 0, KP, nullptr);  // out-proj -> H1 fp16
  build_owner_kernel<<<cdiv(B, 256), 256, 0, s0>>>(nodes, B);

  // layer 1: merged H1 @ [q|kE|vE] -> fp16 l1out (zero bias; biases on t-side)
  mma_gemm_kernel<<<dim3(576 / BN, BPAD / BM), 256, SMEM_G, s0>>>(
      pH1, pW + (size_t)P1_OFF * KP,
      pzb, nullptr, pl1out, B, 576, NSEG, NSEG, nullptr);
  attn_kernel<1><<<B, 256, 0, s0>>>(neighbors, nodes, B);
  GEMM_F(BPAD, NSEG, P5_OFF, R_O, out, B, E_, 0, E_, nullptr);
#undef GEMM_F
#undef GEMM_H
}

// round 15
// speedup vs baseline: 2.7240x; 1.0113x over previous
#include <cuda_runtime.h>
#include <cuda_fp16.h>
#include <math.h>
#include <stdint.h>

#define E_ 172
#define KP 176            // padded K (11 k16 steps)
#define KSTEPS 11
#define C4 (KP / 4)       // 44 float4 chunks per row (chunk 43 = zeros)
#define NSEG 192
#define KNB 20
#define HH 2
#define HD_ 86
#define NNODES 100000
#define BMAX 12000
#define BPAD 12032
#define NPADN 100096
#define NSLOT 240000
#define HTSZ (1 << 19)

// disjoint A-buffer row regions (for cross-stream overlap)
#define R_EDGE 0
#define R_TIME 240000
#define R_NODE 252032                 // R_TIME + BPAD
#define R_Q0   352128                 // R_NODE + NPADN
#define R_O    364160                 // R_Q0 + BPAD
#define AROWS  376192                 // R_O + BPAD

#define P1_OFF 0
#define P2_OFF 576
#define P3_OFF 960
#define P4_OFF 1344
#define P5_OFF 1536
#define PTOT 1728

// ---------------- scratch ----------------
__device__ __half g_A[(size_t)AROWS * KP];         // fp16 activations
__device__ __half g_W[(size_t)PTOT * KP];          // fp16 weights
__device__ float g_Wb[PTOT];
__device__ float g_zbias[576];                     // statically zero

__device__ __half g_tqkv[BMAX * 576];              // fp16 t-side [q|k|v] (+biases)
__device__ __half g_node_kv[(size_t)NNODES * 384];
__device__ __half g_edge_kv[(size_t)NSLOT * 384];
__device__ __half g_l1out[BMAX * 576];             // layer-1 merged [q|k|v] of H1
__device__ __half g_qh[BMAX * KP];                 // L0 q-proj (fp16)
__device__ __half g_H1[BPAD * KP];                 // layer-0 output h1 (fp16)
__device__ int g_owner[NNODES];

__device__ int g_ht[HTSZ];
__device__ int g_uidtab[HTSZ];
__device__ int g_uelist[NSLOT];
__device__ int g_map[NSLOT];
__device__ int g_cnt;

// ---------------- helpers ----------------
__device__ __forceinline__ void cpa16(uint32_t dst, const void* src) {
  asm volatile("cp.async.cg.shared.global [%0], [%1], 16;" :: "r"(dst), "l"(src));
}
__device__ __forceinline__ void cpa_commit() { asm volatile("cp.async.commit_group;" ::: "memory"); }
template <int N>
__device__ __forceinline__ void cpa_wait() { asm volatile("cp.async.wait_group %0;" :: "n"(N) : "memory"); }

__device__ __forceinline__ void ldsm4(uint32_t* r, uint32_t addr) {
  asm volatile("ldmatrix.sync.aligned.m8n8.x4.shared.b16 {%0,%1,%2,%3}, [%4];"
               : "=r"(r[0]), "=r"(r[1]), "=r"(r[2]), "=r"(r[3]) : "r"(addr));
}
__device__ __forceinline__ void mma_f16(float* d, const uint32_t* a, const uint32_t* b) {
  asm volatile(
      "mma.sync.aligned.m16n8k16.row.col.f32.f16.f16.f32 "
      "{%0,%1,%2,%3},{%4,%5,%6,%7},{%8,%9},{%0,%1,%2,%3};"
      : "+f"(d[0]), "+f"(d[1]), "+f"(d[2]), "+f"(d[3])
      : "r"(a[0]), "r"(a[1]), "r"(a[2]), "r"(a[3]), "r"(b[0]), "r"(b[1]));
}

__device__ __forceinline__ void store4h(float4 v, __half* dst, size_t off) {
  __half2 a = __floats2half2_rn(v.x, v.y);
  __half2 b = __floats2half2_rn(v.z, v.w);
  ((__half2*)(dst + off))[0] = a;
  ((__half2*)(dst + off))[1] = b;
}

__device__ __forceinline__ uint32_t ehash(int e) {
  return (((uint32_t)e * 2654435761u) >> 13) & (HTSZ - 1);
}

// ---------------- small kernels ----------------
__global__ void init_owner_kernel() {
  int i = blockIdx.x * blockDim.x + threadIdx.x;
  if (i < NNODES) g_owner[i] = -1;
}
__global__ void build_owner_kernel(const int* __restrict__ nodes, int B) {
  int i = blockIdx.x * blockDim.x + threadIdx.x;
  if (i < B) atomicMax(&g_owner[nodes[i]], i);
}

// ---------------- edge dedup ----------------
__global__ void dedup1_kernel(const int* __restrict__ eidx, int n) {
  int i = blockIdx.x * blockDim.x + threadIdx.x;
  if (i >= n) return;
  int e = eidx[i];
  uint32_t h = ehash(e);
  while (true) {
    int prev = atomicCAS(&g_ht[h], -1, e);
    if (prev == -1 || prev == e) break;
    h = (h + 1) & (HTSZ - 1);
  }
}
__global__ void dedup2_kernel() {
  int i = blockIdx.x * blockDim.x + threadIdx.x;
  if (i >= HTSZ) return;
  int e = g_ht[i];
  if (e != -1) {
    int uid = atomicAdd(&g_cnt, 1);
    g_uidtab[i] = uid;
    g_uelist[uid] = e;
  }
}
__global__ void dedup3_kernel(const int* __restrict__ eidx, int n) {
  int i = blockIdx.x * blockDim.x + threadIdx.x;
  if (i >= n) return;
  int e = eidx[i];
  uint32_t h = ehash(e);
  while (g_ht[h] != e) h = (h + 1) & (HTSZ - 1);
  g_map[i] = g_uidtab[h];
}

// ---------------- weight packing ----------------
struct PArgs {
  const float* w[3];
  int ld[3];
  int coff[3];
  const float* bias[3];
};
__global__ void pack_w_kernel(PArgs a, int nseg, __half* wq, float* pbias) {
  int i = blockIdx.x * blockDim.x + threadIdx.x;
  int tot = nseg * NSEG * KP;
  if (i >= tot) return;
  int n = i / KP, c = i - n * KP;
  int seg = n / NSEG, nr = n - seg * NSEG;
  float v = 0.f;
  if (nr < E_ && c < E_) v = a.w[seg][(size_t)nr * a.ld[seg] + a.coff[seg] + c];
  wq[i] = __float2half_rn(v);
  if (c == 0) pbias[n] = (nr < E_ && a.bias[seg]) ? a.bias[seg][nr] : 0.f;
}

// ---------------- vectorized converts ----------------
__global__ void convert_kernel(const float* __restrict__ X, int ldx,
                               const int* __restrict__ g1, int gmode,
                               int M, int Mpad, int rowoff) {
  int i = blockIdx.x * blockDim.x + threadIdx.x;
  if (i >= Mpad * C4) return;
  int r = i / C4, c4 = i - r * C4;
  float4 v = make_float4(0.f, 0.f, 0.f, 0.f);
  if (r < M && c4 < 43) {
    int src = (gmode >= 1) ? g1[r] : r;
    v = *(const float4*)(X + (size_t)src * ldx + c4 * 4);
  }
  store4h(v, g_A, (size_t)(rowoff + r) * KP + c4 * 4);
}

__global__ void convert_uedges_kernel(const float* __restrict__ ef) {
  int i = blockIdx.x * blockDim.x + threadIdx.x;
  if (i >= NSLOT * C4) return;
  int r = i / C4, c4 = i - r * C4;
  if (r >= g_cnt) return;
  float4 v = make_float4(0.f, 0.f, 0.f, 0.f);
  if (c4 < 43) v = *(const float4*)(ef + (size_t)g_uelist[r] * E_ + c4 * 4);
  store4h(v, g_A, (size_t)(R_EDGE + r) * KP + c4 * 4);
}

__global__ void timeconv_kernel(const float* __restrict__ ts,
                                const float* __restrict__ tw,
                                const float* __restrict__ tb, int B, int Mpad) {
  int i = blockIdx.x * blockDim.x + threadIdx.x;
  if (i >= Mpad * C4) return;
  int r = i / C4, c4 = i - r * C4;
  float4 v = make_float4(0.f, 0.f, 0.f, 0.f);
  if (r < B && c4 < 43) {
    float tval = ts[r];
    float4 w = *(const float4*)(tw + c4 * 4);
    float4 b = *(const float4*)(tb + c4 * 4);
    v.x = (float)cos((double)__fadd_rn(__fmul_rn(tval, w.x), b.x));
    v.y = (float)cos((double)__fadd_rn(__fmul_rn(tval, w.y), b.y));
    v.z = (float)cos((double)__fadd_rn(__fmul_rn(tval, w.z), b.z));
    v.w = (float)cos((double)__fadd_rn(__fmul_rn(tval, w.w), b.w));
  }
  store4h(v, g_A, (size_t)(R_TIME + r) * KP + c4 * 4);
}

// ---------------- pipelined fp16 HMMA GEMM (single pass) ----------------
#define BM 128
#define BN 96
#define ST 24
#define STAGE_A_B (BM * ST * 2)
#define STAGE_B_B (BN * ST * 2)
#define SM_A  0
#define SM_B  (SM_A + 4 * STAGE_A_B)
#define SMEM_G (SM_B + 4 * STAGE_B_B)  // 43008

__global__ __launch_bounds__(256, 2) void mma_gemm_kernel(
    const __half* __restrict__ A, const __half* __restrict__ W,
    const float* __restrict__ bias, float* __restrict__ outf,
    __half* __restrict__ outh,
    int M, int ldout, int segstride, int nwrite, const int* __restrict__ Mptr) {
  if (Mptr) {
    M = *Mptr;
    if ((int)(blockIdx.y * BM) >= M) return;
  }
  extern __shared__ __align__(128) char smraw[];
  const uint32_t sm = (uint32_t)__cvta_generic_to_shared(smraw);
  const int tid = threadIdx.x;
  const int warp = tid >> 5, lane = tid & 31;
  const int m0 = blockIdx.y * BM;
  const int n0 = blockIdx.x * BN;
  const int wm0 = (warp >> 1) * 32;
  const int wn0 = (warp & 1) * 48;

  float acc[2][6][4];
#pragma unroll
  for (int i = 0; i < 2; i++)
#pragma unroll
    for (int j = 0; j < 6; j++)
#pragma unroll
      for (int k = 0; k < 4; k++) acc[i][j][k] = 0.f;

  const int lr = tid >> 1, lch = tid & 1;
  const size_t srcA = (size_t)(m0 + lr) * KP + lch * 8;
  const size_t srcB = (size_t)(n0 + lr) * KP + lch * 8;
  const uint32_t dstAoff = (uint32_t)((lr * ST + lch * 8) * 2);
  const uint32_t dstBoff = dstAoff;

#define LOAD_STAGE(buf, ki)                                                 \
  do {                                                                      \
    cpa16(sm + SM_A + (buf) * STAGE_A_B + dstAoff, A + srcA + (ki) * 16);   \
    if (tid < 2 * BN)                                                       \
      cpa16(sm + SM_B + (buf) * STAGE_B_B + dstBoff, W + srcB + (ki) * 16); \
  } while (0)

  LOAD_STAGE(0, 0); cpa_commit();
  LOAD_STAGE(1, 1); cpa_commit();
  LOAD_STAGE(2, 2); cpa_commit();

  const int aRow = (lane & 7) + ((lane >> 3) & 1) * 8;
  const int aCol = ((lane >> 4) & 1) * 8;
  const int bRow = (lane & 7) + ((lane >> 4) & 1) * 8;
  const int bCol = ((lane >> 3) & 1) * 8;

  for (int ki = 0; ki < KSTEPS; ki++) {
    const int buf = ki & 3;
    cpa_wait<2>();
    __syncthreads();
    if (ki + 3 < KSTEPS) LOAD_STAGE((ki + 3) & 3, ki + 3);
    cpa_commit();

    const uint32_t aB = sm + SM_A + buf * STAGE_A_B;
    const uint32_t bB = sm + SM_B + buf * STAGE_B_B;

    uint32_t af[2][4], bf[6][2];
#pragma unroll
    for (int ti = 0; ti < 2; ti++) {
      uint32_t off = (uint32_t)(((wm0 + ti * 16 + aRow) * ST + aCol) * 2);
      ldsm4(af[ti], aB + off);
    }
#pragma unroll
    for (int p = 0; p < 3; p++) {
      uint32_t off = (uint32_t)(((wn0 + p * 16 + bRow) * ST + bCol) * 2);
      uint32_t t[4];
      ldsm4(t, bB + off);
      bf[2 * p][0] = t[0]; bf[2 * p][1] = t[1];
      bf[2 * p + 1][0] = t[2]; bf[2 * p + 1][1] = t[3];
    }
#pragma unroll
    for (int ti = 0; ti < 2; ti++)
#pragma unroll
      for (int nj = 0; nj < 6; nj++)
        mma_f16(acc[ti][nj], af[ti], bf[nj]);
  }
#undef LOAD_STAGE

  const int g = lane >> 2, tq = lane & 3;
#pragma unroll
  for (int ti = 0; ti < 2; ti++) {
    int m = m0 + wm0 + ti * 16 + g;
#pragma unroll
    for (int nj = 0; nj < 6; nj++) {
      int n = n0 + wn0 + nj * 8 + tq * 2;
      int seg = n / NSEG, nr = n - seg * NSEG;
      if (nr >= nwrite) continue;
      int col = seg * segstride + nr;
      float b0 = bias[n], b1 = bias[n + 1];
#pragma unroll
      for (int half = 0; half < 2; half++) {
        int mm = m + half * 8;
        if (mm >= M) continue;
        float v0 = acc[ti][nj][2 * half] + b0;
        float v1 = acc[ti][nj][2 * half + 1] + b1;
        if (outf) {
          *(float2*)(outf + (size_t)mm * ldout + col) = make_float2(v0, v1);
        } else {
          *(__half2*)(outh + (size_t)mm * ldout + col) = __floats2half2_rn(v0, v1);
        }
      }
    }
  }
}

// ---------------- attention (per sample), writes fp16 to R_O ----------------
template <int LAYER>
__global__ __launch_bounds__(256) void attn_kernel(const int* __restrict__ neighbors,
                                                   const int* __restrict__ nodes, int B) {
  __shared__ float q[E_];
  __shared__ __align__(16) float kk[KNB][E_];
  __shared__ float sc[HH][KNB];
  __shared__ float at[HH][KNB];
  __shared__ const __half* akp[KNB];
  __shared__ const __half* bkp[KNB];
  __shared__ int pad[KNB];

  const int b = blockIdx.x;
  const int tid = threadIdx.x;
  const __half* trow = g_tqkv + (size_t)b * 576;

  if (tid < KNB) {
    int nb = neighbors[b * KNB + tid];
    pad[tid] = (nb == 0) ? 1 : 0;
    const __half* ap = g_node_kv + (size_t)nb * 384;
    if (LAYER == 1) {
      int ow = g_owner[nb];
      if (ow >= 0) ap = g_l1out + (size_t)ow * 576 + 192;
    }
    akp[tid] = ap;
    bkp[tid] = g_edge_kv + (size_t)g_map[b * KNB + tid] * 384;
  }
  if (tid < E_) {
    float qh;
    if (LAYER == 0) {
      qh = __half2float(g_qh[(size_t)b * KP + tid]);
    } else {
      int ow = g_owner[nodes[b]];
      qh = __half2float(g_l1out[(size_t)ow * 576 + tid]);
    }
    q[tid] = qh + __half2float(trow[tid]);
  }
  __syncthreads();

  const __half* tk = trow + NSEG;
  for (int idx = tid; idx < KNB * 43; idx += 256) {
    int j = idx / 43, c4 = idx - j * 43;
    const __half2* a2 = (const __half2*)(akp[j] + c4 * 4);
    const __half2* e2 = (const __half2*)(bkp[j] + c4 * 4);
    const __half2* t2 = (const __half2*)(tk + c4 * 4);
    float2 a0 = __half22float2(a2[0]), a1 = __half22float2(a2[1]);
    float2 e0 = __half22float2(e2[0]), e1 = __half22float2(e2[1]);
    float2 t0 = __half22float2(t2[0]), t1 = __half22float2(t2[1]);
    float* dst = &kk[j][c4 * 4];
    dst[0] = a0.x + e0.x + t0.x;
    dst[1] = a0.y + e0.y + t0.y;
    dst[2] = a1.x + e1.x + t1.x;
    dst[3] = a1.y + e1.y + t1.y;
  }
  if (tid == 0) {
    int all = 1;
#pragma unroll
    for (int j = 0; j < KNB; j++) all &= pad[j];
    if (all) pad[0] = 0;
  }
  __syncthreads();

  if (tid < HH * KNB) {
    int h = tid / KNB, j = tid - h * KNB;
    const float* qp = q + h * HD_;
    const float* kp = &kk[j][h * HD_];
    float sum = 0.f;
#pragma unroll
    for (int d = 0; d < HD_; d++) sum += qp[d] * kp[d];
    sum *= 0.10783277320343841f;
    if (pad[j]) sum = -1e9f;
    sc[h][j] = sum;
  }
  __syncthreads();

  if (tid < HH) {
    float m = -INFINITY;
#pragma unroll
    for (int j = 0; j < KNB; j++) m = fmaxf(m, sc[tid][j]);
    float ex[KNB], ssum = 0.f;
#pragma unroll
    for (int j = 0; j < KNB; j++) { ex[j] = expf(sc[tid][j] - m); ssum += ex[j]; }
    float inv = 1.f / ssum;
#pragma unroll
    for (int j = 0; j < KNB; j++) at[tid][j] = ex[j] * inv;
  }
  __syncthreads();

  if (tid < E_) {
    int h = tid / HD_;
    float o = __half2float(trow[2 * NSEG + tid]);
#pragma unroll
    for (int j = 0; j < KNB; j++)
      o += at[h][j] * (__half2float(akp[j][NSEG + tid]) + __half2float(bkp[j][NSEG + tid]));
    g_A[(size_t)(R_O + b) * KP + tid] = __float2half_rn(o);
  }
}

// ---------------- launch ----------------
static inline int cdiv(int a, int b) { return (a + b - 1) / b; }

extern "C" void kernel_launch(void* const* d_in, const int* in_sizes, int n_in,
                              void* d_out, int out_size) {
  const int* nodes     = (const int*)d_in[0];
  const float* ts      = (const float*)d_in[1];
  const int* neighbors = (const int*)d_in[2];
  const int* eidx      = (const int*)d_in[3];
  const float* nf      = (const float*)d_in[4];
  const float* ef      = (const float*)d_in[5];
  const float* time_w  = (const float*)d_in[6];
  const float* time_b  = (const float*)d_in[7];
  const float* q_w     = (const float*)d_in[8];
  const float* k_w     = (const float*)d_in[9];
  const float* v_w     = (const float*)d_in[10];
  const float* bq      = (const float*)d_in[11];
  const float* bk      = (const float*)d_in[12];
  const float* bv      = (const float*)d_in[13];
  const float* out_w   = (const float*)d_in[14];
  const float* out_b   = (const float*)d_in[15];
  float* out = (float*)d_out;
  const int B = in_sizes[0];

  __half *pW, *pA, *pH1, *pnodekv, *pedgekv, *pl1out, *ptqkv, *pqh;
  float *pWb, *pzb;
  int *pht, *pcnt;
  cudaGetSymbolAddress((void**)&pW, g_W);
  cudaGetSymbolAddress((void**)&pWb, g_Wb);
  cudaGetSymbolAddress((void**)&pzb, g_zbias);
  cudaGetSymbolAddress((void**)&pA, g_A);
  cudaGetSymbolAddress((void**)&pH1, g_H1);
  cudaGetSymbolAddress((void**)&ptqkv, g_tqkv);
  cudaGetSymbolAddress((void**)&pnodekv, g_node_kv);
  cudaGetSymbolAddress((void**)&pedgekv, g_edge_kv);
  cudaGetSymbolAddress((void**)&pl1out, g_l1out);
  cudaGetSymbolAddress((void**)&pqh, g_qh);
  cudaGetSymbolAddress((void**)&pht, g_ht);
  cudaGetSymbolAddress((void**)&pcnt, g_cnt);

  cudaFuncSetAttribute(mma_gemm_kernel, cudaFuncAttributeMaxDynamicSharedMemorySize, SMEM_G);

  static cudaStream_t s1 = nullptr;
  static cudaEvent_t evF = nullptr, evA, evB, evC, evQ;
  if (!s1) {
    cudaStreamCreateWithFlags(&s1, cudaStreamNonBlocking);
    cudaEventCreateWithFlags(&evF, cudaEventDisableTiming);
    cudaEventCreateWithFlags(&evA, cudaEventDisableTiming);
    cudaEventCreateWithFlags(&evB, cudaEventDisableTiming);
    cudaEventCreateWithFlags(&evC, cudaEventDisableTiming);
    cudaEventCreateWithFlags(&evQ, cudaEventDisableTiming);
  }
  cudaStream_t s0 = 0;

  PArgs p;

#define GEMM_F(strm, Mpad, Npad, poff, Aoff, outp, M, ldo, segs, nw, Mptr)    \
  mma_gemm_kernel<<<dim3((Npad) / BN, (Mpad) / BM), 256, SMEM_G, strm>>>(     \
      pA + (size_t)(Aoff) * KP, pW + (size_t)(poff) * KP,                     \
      pWb + (poff), outp, nullptr, M, ldo, segs, nw, Mptr)
#define GEMM_H(strm, Mpad, Npad, poff, Aoff, outp, M, ldo, segs, nw, Mptr)    \
  mma_gemm_kernel<<<dim3((Npad) / BN, (Mpad) / BM), 256, SMEM_G, strm>>>(     \
      pA + (size_t)(Aoff) * KP, pW + (size_t)(poff) * KP,                     \
      pWb + (poff), nullptr, outp, M, ldo, segs, nw, Mptr)

  // fork s1 from the capture stream
  cudaEventRecord(evF, s0);
  cudaStreamWaitEvent(s1, evF, 0);

  // ---- s1: prep, ordered by when s0 consumes it ----
  // group A: tqkv weights + time convert
  p.w[0] = q_w; p.ld[0] = E_;     p.coff[0] = 0; p.bias[0] = bq;
  p.w[1] = k_w; p.ld[1] = 2 * E_; p.coff[1] = 0; p.bias[1] = bk;
  p.w[2] = v_w; p.ld[2] = 2 * E_; p.coff[2] = 0; p.bias[2] = bv;
  pack_w_kernel<<<cdiv(3 * NSEG * KP, 256), 256, 0, s1>>>(p, 3, pW + (size_t)P1_OFF * KP, pWb + P1_OFF);
  timeconv_kernel<<<cdiv(BPAD * C4, 256), 256, 0, s1>>>(ts, time_w, time_b, B, BPAD);
  cudaEventRecord(evA, s1);
  // group B: node weights + node convert
  p.w[0] = k_w; p.ld[0] = 2 * E_; p.coff[0] = 0; p.bias[0] = nullptr;
  p.w[1] = v_w; p.ld[1] = 2 * E_; p.coff[1] = 0; p.bias[1] = nullptr;
  p.w[2] = nullptr; p.ld[2] = 0; p.coff[2] = 0; p.bias[2] = nullptr;
  pack_w_kernel<<<cdiv(2 * NSEG * KP, 256), 256, 0, s1>>>(p, 2, pW + (size_t)P2_OFF * KP, pWb + P2_OFF);
  convert_kernel<<<cdiv(NPADN * C4, 256), 256, 0, s1>>>(nf, E_, nullptr, 0, NNODES, NPADN, R_NODE);
  cudaEventRecord(evB, s1);
  // group C: edge dedup + edge weights + edge convert
  cudaMemsetAsync(pht, 0xFF, (size_t)HTSZ * sizeof(int), s1);
  cudaMemsetAsync(pcnt, 0, sizeof(int), s1);
  dedup1_kernel<<<cdiv(B * KNB, 256), 256, 0, s1>>>(eidx, B * KNB);
  dedup2_kernel<<<cdiv(HTSZ, 256), 256, 0, s1>>>();
  p.w[0] = k_w; p.ld[0] = 2 * E_; p.coff[0] = E_; p.bias[0] = nullptr;
  p.w[1] = v_w; p.ld[1] = 2 * E_; p.coff[1] = E_; p.bias[1] = nullptr;
  p.w[2] = nullptr;
  pack_w_kernel<<<cdiv(2 * NSEG * KP, 256), 256, 0, s1>>>(p, 2, pW + (size_t)P3_OFF * KP, pWb + P3_OFF);
  convert_uedges_kernel<<<cdiv(NSLOT * C4, 256), 256, 0, s1>>>(ef);
  cudaEventRecord(evC, s1);
  // group D (s1): dedup map, owner init, q/out weight packs, L0 q convert + L0 q GEMM
  dedup3_kernel<<<cdiv(B * KNB, 256), 256, 0, s1>>>(eidx, B * KNB);
  init_owner_kernel<<<cdiv(NNODES, 256), 256, 0, s1>>>();
  p.w[0] = q_w; p.ld[0] = E_; p.coff[0] = 0; p.bias[0] = nullptr;
  p.w[1] = nullptr; p.w[2] = nullptr;
  pack_w_kernel<<<cdiv(NSEG * KP, 256), 256, 0, s1>>>(p, 1, pW + (size_t)P4_OFF * KP, pWb + P4_OFF);
  p.w[0] = out_w; p.bias[0] = out_b;
  pack_w_kernel<<<cdiv(NSEG * KP, 256), 256, 0, s1>>>(p, 1, pW + (size_t)P5_OFF * KP, pWb + P5_OFF);
  convert_kernel<<<cdiv(BPAD * C4, 256), 256, 0, s1>>>(nf, E_, nodes, 1, B, BPAD, R_Q0);
  GEMM_H(s1, BPAD, NSEG, P4_OFF, R_Q0, pqh, B, KP, 0, KP, nullptr);  // L0 q-proj on s1
  cudaEventRecord(evQ, s1);

  // ---- s0: GEMM chain + attention ----
  cudaStreamWaitEvent(s0, evA, 0);
  GEMM_H(s0, BPAD, 576, P1_OFF, R_TIME, ptqkv, B, 576, NSEG, NSEG, nullptr);
  cudaStreamWaitEvent(s0, evB, 0);
  GEMM_H(s0, NPADN, 384, P2_OFF, R_NODE, pnodekv, NNODES, 384, NSEG, NSEG, nullptr);
  cudaStreamWaitEvent(s0, evC, 0);
  GEMM_H(s0, NSLOT, 384, P3_OFF, R_EDGE, pedgekv, B * KNB, 384, NSEG, NSEG, pcnt);
  cudaStreamWaitEvent(s0, evQ, 0);

  // layer 0
  attn_kernel<0><<<B, 256, 0, s0>>>(neighbors, nodes, B);
  GEMM_H(s0, BPAD, NSEG, P5_OFF, R_O, pH1, B, KP, 0, KP, nullptr);  // out-proj -> H1 fp16
  build_owner_kernel<<<cdiv(B, 256), 256, 0, s0>>>(nodes, B);

  // layer 1: merged H1 @ [q|kE|vE] -> fp16 l1out (zero bias; biases on t-side)
  mma_gemm_kernel<<<dim3(576 / BN, BPAD / BM), 256, SMEM_G, s0>>>(
      pH1, pW + (size_t)P1_OFF * KP,
      pzb, nullptr, pl1out, B, 576, NSEG, NSEG, nullptr);
  attn_kernel<1><<<B, 256, 0, s0>>>(neighbors, nodes, B);
  GEMM_F(s0, BPAD, NSEG, P5_OFF, R_O, out, B, E_, 0, E_, nullptr);
#undef GEMM_F
#undef GEMM_H
}